// round 9
// baseline (speedup 1.0000x reference)
#include <cuda_runtime.h>
#include <math.h>

typedef unsigned long long ull;
typedef unsigned int u32;

#define B_  2
#define L_  2048
#define S_  2048
#define D_  256
#define H_  8
#define SPLITS 2
#define SHALF (S_ / SPLITS)      // 1024
#define LT 32                    // l-rows per block
#define ST 16
#define NT (SHALF / ST)          // 64

// ---------------- f32x2 packed math ----------------
#define PACK2(d, x, y) asm("mov.b64 %0, {%1, %2};" : "=l"(d) : "r"(__float_as_uint(x)), "r"(__float_as_uint(y)))
#define UNPACK2(x, y, d) do { u32 _lo, _hi; \
    asm("mov.b64 {%0, %1}, %2;" : "=r"(_lo), "=r"(_hi) : "l"(d)); \
    (x) = __uint_as_float(_lo); (y) = __uint_as_float(_hi); } while (0)
#define FMA2(d, a, b, c) asm("fma.rn.f32x2 %0, %1, %2, %3;" : "=l"(d) : "l"(a), "l"(b), "l"(c))
#define MUL2(d, a, b)    asm("mul.rn.f32x2 %0, %1, %2;"     : "=l"(d) : "l"(a), "l"(b))
#define ADD2(d, a, b)    asm("add.rn.f32x2 %0, %1, %2;"     : "=l"(d) : "l"(a), "l"(b))

__device__ __forceinline__ float ex2f(float x) {
    float r;
    asm("ex2.approx.ftz.f32 %0, %1;" : "=f"(r) : "f"(x));
    return r;
}

// ---------------- scratch ----------------
__device__ float g_Q[(size_t)B_ * L_ * D_];
__device__ float g_K[(size_t)B_ * S_ * D_];
__device__ float g_V[(size_t)B_ * S_ * D_];
__device__ float g_OP[(size_t)SPLITS * B_ * L_ * D_];
__device__ float g_SS[(size_t)SPLITS * B_ * H_ * L_];
__device__ float g_M[(size_t)B_ * L_ * D_];
__device__ float g_HB[(size_t)B_ * L_ * 2 * D_];
__device__ float g_T[(size_t)B_ * L_ * D_];

// ---------------- GEMM core ----------------
// Tile 64x64, 256 threads, microtile 2(m)x8(n), f32x2 pairs along n.
// MODE: 0 plain, 1 SPLIT (X = [X|X2] along K, each 256 wide),
//       2 COMBINE (X = (OP0+OP1)*inv(SS0+SS1), attention partial merge).
template <bool RELU, int MODE>
__device__ __forceinline__ void gemm_body(
    const float* __restrict__ X, const float* __restrict__ X2,
    const float* __restrict__ SSp,
    const float* __restrict__ W, float* __restrict__ Y,
    int N, int K, int bm, int bn) {
    __shared__ float XsT[16][68];   // [k][m]
    __shared__ float BsT[16][72];   // [k][n]
    const int t = threadIdx.x, tx = t & 7, ty = t >> 3;
    const int NTk = K >> 4;
    const int lr = t >> 2, lc = (t & 3) * 4;   // load coords: row 0..63, col*4

    float4 xr, wr;
    // ---- X/W tile loader (kc = absolute k index) ----
    #define LOAD_XW(kc_) do { \
        int kc = (kc_); \
        if (MODE == 1) { \
            xr = (kc < 256) ? *(const float4*)(X + (size_t)(bm + lr) * 256 + kc) \
                            : *(const float4*)(X2 + (size_t)(bm + lr) * 256 + (kc - 256)); \
        } else if (MODE == 2) { \
            size_t row = bm + lr; \
            size_t e = row * 256 + kc; \
            float4 a = *(const float4*)(X + e); \
            float4 c2 = *(const float4*)(X2 + e); \
            size_t bb = row >> 11, l = row & 2047; \
            int h = kc >> 5; \
            float s = SSp[(bb * H_ + h) * L_ + l] \
                    + SSp[(size_t)B_ * H_ * L_ + (bb * H_ + h) * L_ + l]; \
            float inv = 1.0f / s; \
            xr.x = (a.x + c2.x) * inv; xr.y = (a.y + c2.y) * inv; \
            xr.z = (a.z + c2.z) * inv; xr.w = (a.w + c2.w) * inv; \
        } else { \
            xr = *(const float4*)(X + (size_t)(bm + lr) * K + kc); \
        } \
        wr = *(const float4*)(W + (size_t)(bn + lr) * K + kc); \
    } while (0)

    LOAD_XW(lc);

    ull acc[2][4]; ull zero; PACK2(zero, 0.0f, 0.0f);
    #pragma unroll
    for (int m = 0; m < 2; m++)
        #pragma unroll
        for (int n = 0; n < 4; n++) acc[m][n] = zero;

    for (int kt = 0; kt < NTk; kt++) {
        __syncthreads();
        XsT[lc + 0][lr] = xr.x; XsT[lc + 1][lr] = xr.y;
        XsT[lc + 2][lr] = xr.z; XsT[lc + 3][lr] = xr.w;
        BsT[lc + 0][lr] = wr.x; BsT[lc + 1][lr] = wr.y;
        BsT[lc + 2][lr] = wr.z; BsT[lc + 3][lr] = wr.w;
        if (kt + 1 < NTk) LOAD_XW((kt + 1) * 16 + lc);
        __syncthreads();
        #pragma unroll
        for (int kk = 0; kk < 16; kk++) {
            float2 a2 = *(const float2*)&XsT[kk][ty * 2];
            ulonglong2 b01 = *(const ulonglong2*)&BsT[kk][tx * 8];
            ulonglong2 b23 = *(const ulonglong2*)&BsT[kk][tx * 8 + 4];
            ull am;
            PACK2(am, a2.x, a2.x);
            FMA2(acc[0][0], am, b01.x, acc[0][0]); FMA2(acc[0][1], am, b01.y, acc[0][1]);
            FMA2(acc[0][2], am, b23.x, acc[0][2]); FMA2(acc[0][3], am, b23.y, acc[0][3]);
            PACK2(am, a2.y, a2.y);
            FMA2(acc[1][0], am, b01.x, acc[1][0]); FMA2(acc[1][1], am, b01.y, acc[1][1]);
            FMA2(acc[1][2], am, b23.x, acc[1][2]); FMA2(acc[1][3], am, b23.y, acc[1][3]);
        }
    }
    #undef LOAD_XW

    float o[2][8];
    #pragma unroll
    for (int m = 0; m < 2; m++)
        #pragma unroll
        for (int np = 0; np < 4; np++)
            UNPACK2(o[m][2 * np], o[m][2 * np + 1], acc[m][np]);
    #pragma unroll
    for (int r = 0; r < 2; r++) {
        if (RELU)
            #pragma unroll
            for (int n = 0; n < 8; n++) o[r][n] = fmaxf(o[r][n], 0.0f);
        float4 w0, w1;
        w0.x = o[r][0]; w0.y = o[r][1]; w0.z = o[r][2]; w0.w = o[r][3];
        w1.x = o[r][4]; w1.y = o[r][5]; w1.z = o[r][6]; w1.w = o[r][7];
        float* yp = Y + (size_t)(bm + ty * 2 + r) * N + bn + tx * 8;
        *(float4*)yp = w0;
        *(float4*)(yp + 4) = w1;
    }
}

template <bool RELU, int MODE>
__global__ void __launch_bounds__(256) gemm64(
    const float* __restrict__ X, const float* __restrict__ X2,
    const float* __restrict__ SSp,
    const float* __restrict__ W, float* __restrict__ Y,
    int N, int K) {
    gemm_body<RELU, MODE>(X, X2, SSp, W, Y, N, K, blockIdx.y * 64, blockIdx.x * 64);
}

// fused QKV projections: blockIdx.z selects (x,Wq)->Q / (src,Wk)->K / (src,Wv)->V
__global__ void __launch_bounds__(256) gemm_qkv(
    const float* __restrict__ x, const float* __restrict__ src,
    const float* __restrict__ Wq, const float* __restrict__ Wk,
    const float* __restrict__ Wv,
    float* __restrict__ Q, float* __restrict__ K, float* __restrict__ V) {
    const int z = blockIdx.z;
    const float* X = (z == 0) ? x : src;
    const float* W = (z == 0) ? Wq : (z == 1) ? Wk : Wv;
    float* Y = (z == 0) ? Q : (z == 1) ? K : V;
    gemm_body<false, 0>(X, nullptr, nullptr, W, Y, 256, 256, blockIdx.y * 64, blockIdx.x * 64);
}

// ---------------- fused attention: 2 rows/thread, shared K/V loads ----------------
// Block: 256 threads = 8 warps (warp = head), covers 32 l-rows.
// lane&15 = row pair (rows lr, lr+16); lane>>4 = dim-half (16 dims).
// Every K/V smem load serves TWO rows. Score halves combined via shfl_xor(16).
// Grid: (L/32, SPLITS, B) = 256 blocks, 2 blocks/SM.
// smem: Ks[2][16][256] | Vs[2][16][256] | Afs[2][32][17] = 70016 bytes.
#define ATTN_SMEM 70016

#define ISSUE_KV(t_, buf_) do { \
    const float* ksrc_ = Kb + (size_t)(sbase + (t_) * ST) * D_; \
    const float* vsrc_ = Vb + (size_t)(sbase + (t_) * ST) * D_; \
    u32 kd_ = kbase + (u32)(buf_) * 16384; \
    u32 vd_ = vbase + (u32)(buf_) * 16384; \
    _Pragma("unroll") \
    for (int i_ = 0; i_ < 4; i_++) { \
        int idx_ = tid + 256 * i_; int s_ = idx_ >> 6; int c_ = (idx_ & 63) * 4; \
        asm volatile("cp.async.cg.shared.global [%0], [%1], 16;" :: \
            "r"(kd_ + (u32)(s_ * 256 + c_) * 4), "l"(ksrc_ + s_ * 256 + c_)); \
        asm volatile("cp.async.cg.shared.global [%0], [%1], 16;" :: \
            "r"(vd_ + (u32)(s_ * 256 + c_) * 4), "l"(vsrc_ + s_ * 256 + c_)); \
    } \
    asm volatile("cp.async.commit_group;"); \
} while (0)

#define LOAD_AF(t_) do { \
    afr0 = afb[(size_t)(tid >> 4) * S_ + (t_) * ST + (tid & 15)]; \
    afr1 = afb[(size_t)((tid >> 4) + 16) * S_ + (t_) * ST + (tid & 15)]; \
} while (0)

#define STORE_AF(buf_) do { \
    Afs[(buf_) * 544 + (tid >> 4) * 17 + (tid & 15)] = afr0; \
    Afs[(buf_) * 544 + ((tid >> 4) + 16) * 17 + (tid & 15)] = afr1; \
} while (0)

__global__ void __launch_bounds__(256, 2) attn4(
    const float* __restrict__ Qg, const float* __restrict__ Kg,
    const float* __restrict__ Vg, const float* __restrict__ af,
    float* __restrict__ Op, float* __restrict__ SSp) {
    extern __shared__ float sm[];
    float* Ksm = sm;                 // 2*16*256 = 8192 floats
    float* Vsm = sm + 8192;          // 8192
    float* Afs = sm + 16384;         // 2*32*17 = 1088

    const int b = blockIdx.z, sp = blockIdx.y;
    const int l0 = blockIdx.x * LT;
    const int tid = threadIdx.x;
    const int w = tid >> 5, lane = tid & 31;
    const int lr = lane & 15, half = lane >> 4;
    const int dimoff = w * 32 + half * 16;
    const int sbase = sp * SHALF;
    const float* Kb  = Kg + (size_t)b * S_ * D_;
    const float* Vb  = Vg + (size_t)b * S_ * D_;
    const float* afb = af + ((size_t)b * L_ + l0) * S_ + sbase;
    const u32 smb = (u32)__cvta_generic_to_shared(sm);
    const u32 kbase = smb;
    const u32 vbase = smb + 8192 * 4;

    // q regs for both rows (16 dims each), pre-scaled by log2(e)/sqrt(32)
    ull q0[8], q1[8];
    {
        const float QS = 0.25503486f;  // 1.4426950408889634 / sqrt(32)
        const float* qr0 = Qg + ((size_t)b * L_ + l0 + lr) * D_ + dimoff;
        const float* qr1 = qr0 + 16 * D_;
        #pragma unroll
        for (int i = 0; i < 4; i++) {
            float4 f = *(const float4*)(qr0 + i * 4);
            f.x *= QS; f.y *= QS; f.z *= QS; f.w *= QS;
            PACK2(q0[2 * i], f.x, f.y);
            PACK2(q0[2 * i + 1], f.z, f.w);
            float4 g = *(const float4*)(qr1 + i * 4);
            g.x *= QS; g.y *= QS; g.z *= QS; g.w *= QS;
            PACK2(q1[2 * i], g.x, g.y);
            PACK2(q1[2 * i + 1], g.z, g.w);
        }
    }
    ull zero; PACK2(zero, 0.0f, 0.0f);
    ull o0[8], o1[8];
    #pragma unroll
    for (int i = 0; i < 8; i++) { o0[i] = zero; o1[i] = zero; }
    float ssum0 = 0.0f, ssum1 = 0.0f;
    float afr0, afr1;

    // prologue
    ISSUE_KV(0, 0);
    LOAD_AF(0);
    ISSUE_KV(1, 1);
    STORE_AF(0);
    LOAD_AF(1);

    for (int t = 0; t < NT; t++) {
        const int buf = t & 1;
        if (t + 1 < NT) asm volatile("cp.async.wait_group 1;");
        else            asm volatile("cp.async.wait_group 0;");
        __syncthreads();
        if (t + 1 < NT) STORE_AF(buf ^ 1);
        if (t + 2 < NT) LOAD_AF(t + 2);

        const float* ks   = Ksm + buf * 4096 + dimoff;
        const float* vs   = Vsm + buf * 4096 + dimoff;
        const float* afl0 = Afs + buf * 544 + lr * 17;
        const float* afl1 = afl0 + 16 * 17;

        #pragma unroll 4
        for (int s = 0; s < ST; s++) {
            const ulonglong2* kp = (const ulonglong2*)(ks + s * 256);
            ull a0, a1, c0, c1;
            {
                ulonglong2 kv = kp[0];
                MUL2(a0, q0[0], kv.x); MUL2(a1, q0[1], kv.y);
                MUL2(c0, q1[0], kv.x); MUL2(c1, q1[1], kv.y);
            }
            { ulonglong2 kv = kp[1];
              FMA2(a0, q0[2], kv.x, a0); FMA2(a1, q0[3], kv.y, a1);
              FMA2(c0, q1[2], kv.x, c0); FMA2(c1, q1[3], kv.y, c1); }
            { ulonglong2 kv = kp[2];
              FMA2(a0, q0[4], kv.x, a0); FMA2(a1, q0[5], kv.y, a1);
              FMA2(c0, q1[4], kv.x, c0); FMA2(c1, q1[5], kv.y, c1); }
            { ulonglong2 kv = kp[3];
              FMA2(a0, q0[6], kv.x, a0); FMA2(a1, q0[7], kv.y, a1);
              FMA2(c0, q1[6], kv.x, c0); FMA2(c1, q1[7], kv.y, c1); }
            ADD2(a0, a0, a1); ADD2(c0, c0, c1);
            float xa0, xa1, xc0, xc1;
            UNPACK2(xa0, xa1, a0);
            UNPACK2(xc0, xc1, c0);
            float xa = xa0 + xa1;
            float xc = xc0 + xc1;
            xa += __shfl_xor_sync(0xffffffffu, xa, 16);  // combine dim halves
            xc += __shfl_xor_sync(0xffffffffu, xc, 16);
            float p0 = ex2f(xa * afl0[s]);
            float p1 = ex2f(xc * afl1[s]);
            ssum0 += p0; ssum1 += p1;
            ull pp0, pp1; PACK2(pp0, p0, p0); PACK2(pp1, p1, p1);
            const ulonglong2* vp = (const ulonglong2*)(vs + s * 256);
            #pragma unroll
            for (int j = 0; j < 4; j++) {
                ulonglong2 vv = vp[j];
                FMA2(o0[2 * j],     pp0, vv.x, o0[2 * j]);
                FMA2(o0[2 * j + 1], pp0, vv.y, o0[2 * j + 1]);
                FMA2(o1[2 * j],     pp1, vv.x, o1[2 * j]);
                FMA2(o1[2 * j + 1], pp1, vv.y, o1[2 * j + 1]);
            }
        }
        __syncthreads();
        if (t + 2 < NT) ISSUE_KV(t + 2, buf);
    }

    // write raw partials (division happens fused into the Wm GEMM)
    float* op0 = Op + (((size_t)sp * B_ + b) * L_ + l0 + lr) * D_ + dimoff;
    float* op1 = op0 + 16 * D_;
    #pragma unroll
    for (int j = 0; j < 2; j++) {
        float v0, v1, v2, v3;
        UNPACK2(v0, v1, o0[2 * j * 2]);     UNPACK2(v2, v3, o0[2 * j * 2 + 1]);
        float4 f; f.x = v0; f.y = v1; f.z = v2; f.w = v3;
        *(float4*)(op0 + j * 8) = f;
        UNPACK2(v0, v1, o0[2 * j * 2 + 2]); UNPACK2(v2, v3, o0[2 * j * 2 + 3]);
        float4 g; g.x = v0; g.y = v1; g.z = v2; g.w = v3;
        *(float4*)(op0 + j * 8 + 4) = g;
        UNPACK2(v0, v1, o1[2 * j * 2]);     UNPACK2(v2, v3, o1[2 * j * 2 + 1]);
        float4 h; h.x = v0; h.y = v1; h.z = v2; h.w = v3;
        *(float4*)(op1 + j * 8) = h;
        UNPACK2(v0, v1, o1[2 * j * 2 + 2]); UNPACK2(v2, v3, o1[2 * j * 2 + 3]);
        float4 e; e.x = v0; e.y = v1; e.z = v2; e.w = v3;
        *(float4*)(op1 + j * 8 + 4) = e;
    }
    if (half == 0) {
        size_t ssb = (((size_t)sp * B_ + b) * H_ + w) * L_ + l0;
        SSp[ssb + lr] = ssum0;
        SSp[ssb + 16 + lr] = ssum1;
    }
}

// ---------------- LayerNorm over D=256 ----------------
template <bool RESID>
__global__ void ln_kernel(const float* __restrict__ in, const float* __restrict__ g,
                          const float* __restrict__ bt, const float* __restrict__ resid,
                          float* __restrict__ out) {
    const size_t row = blockIdx.x;
    const int tid = threadIdx.x;
    float x = in[row * D_ + tid];
    __shared__ float red[256];
    red[tid] = x; __syncthreads();
    #pragma unroll
    for (int off = 128; off > 0; off >>= 1) {
        if (tid < off) red[tid] += red[tid + off];
        __syncthreads();
    }
    const float mean = red[0] * (1.0f / D_);
    __syncthreads();
    const float d = x - mean;
    red[tid] = d * d; __syncthreads();
    #pragma unroll
    for (int off = 128; off > 0; off >>= 1) {
        if (tid < off) red[tid] += red[tid + off];
        __syncthreads();
    }
    const float var = red[0] * (1.0f / D_);
    float y = d * rsqrtf(var + 1e-5f) * g[tid] + bt[tid];
    if (RESID) y += resid[row * D_ + tid];
    out[row * D_ + tid] = y;
}

// ---------------- launch ----------------
extern "C" void kernel_launch(void* const* d_in, const int* in_sizes, int n_in,
                              void* d_out, int out_size) {
    const float* x   = (const float*)d_in[0];
    const float* src = (const float*)d_in[1];
    const float* af  = (const float*)d_in[2];
    const float* Wq  = (const float*)d_in[3];
    const float* Wk  = (const float*)d_in[4];
    const float* Wv  = (const float*)d_in[5];
    const float* Wm  = (const float*)d_in[6];
    const float* W1  = (const float*)d_in[7];
    const float* W2  = (const float*)d_in[8];
    const float* g1  = (const float*)d_in[9];
    const float* b1  = (const float*)d_in[10];
    const float* g2  = (const float*)d_in[11];
    const float* b2  = (const float*)d_in[12];
    float* out = (float*)d_out;

    float *Q, *K, *V, *OP, *SS, *M, *HB, *T;
    cudaGetSymbolAddress((void**)&Q,  g_Q);
    cudaGetSymbolAddress((void**)&K,  g_K);
    cudaGetSymbolAddress((void**)&V,  g_V);
    cudaGetSymbolAddress((void**)&OP, g_OP);
    cudaGetSymbolAddress((void**)&SS, g_SS);
    cudaGetSymbolAddress((void**)&M,  g_M);
    cudaGetSymbolAddress((void**)&HB, g_HB);
    cudaGetSymbolAddress((void**)&T,  g_T);

    cudaFuncSetAttribute(attn4, cudaFuncAttributeMaxDynamicSharedMemorySize, ATTN_SMEM);

    const int ML = B_ * L_;  // 4096
    float* OP1 = OP + (size_t)B_ * L_ * D_;  // second split partial

    // projections (one launch, grid.z selects Q/K/V)
    gemm_qkv<<<dim3(4, ML / 64, 3), 256>>>(x, src, Wq, Wk, Wv, Q, K, V);

    // attention (writes raw partials OP + sums SS)
    attn4<<<dim3(L_ / LT, SPLITS, B_), 256, ATTN_SMEM>>>(Q, K, V, af, OP, SS);

    // output proj with fused split-combine + LN1
    gemm64<false, 2><<<dim3(4, ML / 64), 256>>>(OP, OP1, SS, Wm, M, 256, 256);
    ln_kernel<false><<<ML, 256>>>(M, g1, b1, nullptr, M);

    // MLP
    gemm64<true, 1><<<dim3(8, ML / 64), 256>>>(x, M, nullptr, W1, HB, 512, 512);
    gemm64<false, 0><<<dim3(4, ML / 64), 256>>>(HB, nullptr, nullptr, W2, T, 256, 512);

    // LN2 + residual -> out
    ln_kernel<true><<<ML, 256>>>(T, g2, b2, x, out);
}

// round 10
// speedup vs baseline: 1.3153x; 1.3153x over previous
#include <cuda_runtime.h>
#include <math.h>

typedef unsigned long long ull;
typedef unsigned int u32;

#define B_  2
#define L_  2048
#define S_  2048
#define D_  256
#define H_  8
#define SPLITS 2
#define SHALF (S_ / SPLITS)      // 1024
#define LT 32                    // l-rows per block
#define ST 16
#define NT (SHALF / ST)          // 64

// ---------------- f32x2 packed math ----------------
#define PACK2(d, x, y) asm("mov.b64 %0, {%1, %2};" : "=l"(d) : "r"(__float_as_uint(x)), "r"(__float_as_uint(y)))
#define UNPACK2(x, y, d) do { u32 _lo, _hi; \
    asm("mov.b64 {%0, %1}, %2;" : "=r"(_lo), "=r"(_hi) : "l"(d)); \
    (x) = __uint_as_float(_lo); (y) = __uint_as_float(_hi); } while (0)
#define FMA2(d, a, b, c) asm("fma.rn.f32x2 %0, %1, %2, %3;" : "=l"(d) : "l"(a), "l"(b), "l"(c))
#define MUL2(d, a, b)    asm("mul.rn.f32x2 %0, %1, %2;"     : "=l"(d) : "l"(a), "l"(b))
#define ADD2(d, a, b)    asm("add.rn.f32x2 %0, %1, %2;"     : "=l"(d) : "l"(a), "l"(b))

__device__ __forceinline__ float ex2f(float x) {
    float r;
    asm("ex2.approx.ftz.f32 %0, %1;" : "=f"(r) : "f"(x));
    return r;
}

// ---------------- scratch ----------------
__device__ float g_Q[(size_t)B_ * L_ * D_];
__device__ float g_K[(size_t)B_ * S_ * D_];
__device__ float g_V[(size_t)B_ * S_ * D_];
__device__ float g_OP[(size_t)SPLITS * B_ * L_ * D_];
__device__ float g_SS[(size_t)SPLITS * B_ * H_ * L_];
__device__ float g_O[(size_t)B_ * L_ * D_];
__device__ float g_M[(size_t)B_ * L_ * D_];
__device__ float g_HB[(size_t)B_ * L_ * 2 * D_];
__device__ float g_T[(size_t)B_ * L_ * D_];

// ---------------- GEMM core (R7-proven inner loop) ----------------
// Tile 64x64, 128 threads, microtile 4(m)x8(n), f32x2 pairs along n.
// ldx/ldw: leading dims of X and W (SPLIT mode: X/X2 each 256 wide).
template <bool RELU, bool SPLIT>
__device__ __forceinline__ void gemm_body(
    const float* __restrict__ X, const float* __restrict__ X2,
    const float* __restrict__ W, float* __restrict__ Y,
    int N, int K, int ldx, int ldw, int bm, int bn) {
    __shared__ float XsT[16][68];   // [k][m]
    __shared__ float BsT[16][72];   // [k][n]
    const int t = threadIdx.x, tx = t & 7, ty = t >> 3;
    const int NTk = K >> 4;

    float4 xr[2], wr[2];
    #pragma unroll
    for (int i = 0; i < 2; i++) {   // prologue load k-tile 0
        int idx = t + 128 * i; int r = idx >> 2; int c = (idx & 3) * 4;
        if (SPLIT) xr[i] = (c < 256) ? *(const float4*)(X + (size_t)(bm + r) * 256 + c)
                                     : *(const float4*)(X2 + (size_t)(bm + r) * 256 + (c - 256));
        else       xr[i] = *(const float4*)(X + (size_t)(bm + r) * ldx + c);
        wr[i] = *(const float4*)(W + (size_t)(bn + r) * ldw + c);
    }

    ull acc[4][4]; ull zero; PACK2(zero, 0.0f, 0.0f);
    #pragma unroll
    for (int m = 0; m < 4; m++)
        #pragma unroll
        for (int n = 0; n < 4; n++) acc[m][n] = zero;

    for (int kt = 0; kt < NTk; kt++) {
        __syncthreads();
        #pragma unroll
        for (int i = 0; i < 2; i++) {
            int idx = t + 128 * i; int r = idx >> 2; int c = (idx & 3) * 4;
            XsT[c + 0][r] = xr[i].x; XsT[c + 1][r] = xr[i].y;
            XsT[c + 2][r] = xr[i].z; XsT[c + 3][r] = xr[i].w;
            BsT[c + 0][r] = wr[i].x; BsT[c + 1][r] = wr[i].y;
            BsT[c + 2][r] = wr[i].z; BsT[c + 3][r] = wr[i].w;
        }
        if (kt + 1 < NTk) {
            int k0 = (kt + 1) * 16;
            #pragma unroll
            for (int i = 0; i < 2; i++) {
                int idx = t + 128 * i; int r = idx >> 2; int c = (idx & 3) * 4;
                int kc = k0 + c;
                if (SPLIT) xr[i] = (kc < 256) ? *(const float4*)(X + (size_t)(bm + r) * 256 + kc)
                                              : *(const float4*)(X2 + (size_t)(bm + r) * 256 + (kc - 256));
                else       xr[i] = *(const float4*)(X + (size_t)(bm + r) * ldx + kc);
                wr[i] = *(const float4*)(W + (size_t)(bn + r) * ldw + kc);
            }
        }
        __syncthreads();
        #pragma unroll
        for (int kk = 0; kk < 16; kk++) {
            float4 a4 = *(const float4*)&XsT[kk][ty * 4];
            ulonglong2 b01 = *(const ulonglong2*)&BsT[kk][tx * 8];
            ulonglong2 b23 = *(const ulonglong2*)&BsT[kk][tx * 8 + 4];
            ull am;
            PACK2(am, a4.x, a4.x);
            FMA2(acc[0][0], am, b01.x, acc[0][0]); FMA2(acc[0][1], am, b01.y, acc[0][1]);
            FMA2(acc[0][2], am, b23.x, acc[0][2]); FMA2(acc[0][3], am, b23.y, acc[0][3]);
            PACK2(am, a4.y, a4.y);
            FMA2(acc[1][0], am, b01.x, acc[1][0]); FMA2(acc[1][1], am, b01.y, acc[1][1]);
            FMA2(acc[1][2], am, b23.x, acc[1][2]); FMA2(acc[1][3], am, b23.y, acc[1][3]);
            PACK2(am, a4.z, a4.z);
            FMA2(acc[2][0], am, b01.x, acc[2][0]); FMA2(acc[2][1], am, b01.y, acc[2][1]);
            FMA2(acc[2][2], am, b23.x, acc[2][2]); FMA2(acc[2][3], am, b23.y, acc[2][3]);
            PACK2(am, a4.w, a4.w);
            FMA2(acc[3][0], am, b01.x, acc[3][0]); FMA2(acc[3][1], am, b01.y, acc[3][1]);
            FMA2(acc[3][2], am, b23.x, acc[3][2]); FMA2(acc[3][3], am, b23.y, acc[3][3]);
        }
    }

    float o[4][8];
    #pragma unroll
    for (int m = 0; m < 4; m++)
        #pragma unroll
        for (int np = 0; np < 4; np++)
            UNPACK2(o[m][2 * np], o[m][2 * np + 1], acc[m][np]);
    #pragma unroll
    for (int r = 0; r < 4; r++) {
        if (RELU)
            #pragma unroll
            for (int n = 0; n < 8; n++) o[r][n] = fmaxf(o[r][n], 0.0f);
        float4 w0, w1;
        w0.x = o[r][0]; w0.y = o[r][1]; w0.z = o[r][2]; w0.w = o[r][3];
        w1.x = o[r][4]; w1.y = o[r][5]; w1.z = o[r][6]; w1.w = o[r][7];
        float* yp = Y + (size_t)(bm + ty * 4 + r) * N + bn + tx * 8;
        *(float4*)yp = w0;
        *(float4*)(yp + 4) = w1;
    }
}

template <bool RELU, bool SPLIT>
__global__ void __launch_bounds__(128) gemm64(
    const float* __restrict__ X, const float* __restrict__ X2,
    const float* __restrict__ W, float* __restrict__ Y,
    int N, int K, int ldx, int ldw) {
    gemm_body<RELU, SPLIT>(X, X2, W, Y, N, K, ldx, ldw, blockIdx.y * 64, blockIdx.x * 64);
}

// split-K=2: blockIdx.z selects K-half; partials go to Y0 / Y1 (summed in LN).
__global__ void __launch_bounds__(128) gemm_splitk(
    const float* __restrict__ X, const float* __restrict__ W,
    float* __restrict__ Y0, float* __restrict__ Y1,
    int N, int Kh, int ldx, int ldw) {
    const int z = blockIdx.z;
    float* Y = z ? Y1 : Y0;
    gemm_body<false, false>(X + z * Kh, nullptr, W + z * Kh, Y,
                            N, Kh, ldx, ldw, blockIdx.y * 64, blockIdx.x * 64);
}

// fused QKV projections: blockIdx.z selects (x,Wq)->Q / (src,Wk)->K / (src,Wv)->V
__global__ void __launch_bounds__(128) gemm_qkv(
    const float* __restrict__ x, const float* __restrict__ src,
    const float* __restrict__ Wq, const float* __restrict__ Wk,
    const float* __restrict__ Wv,
    float* __restrict__ Q, float* __restrict__ K, float* __restrict__ V) {
    const int z = blockIdx.z;
    const float* X = (z == 0) ? x : src;
    const float* W = (z == 0) ? Wq : (z == 1) ? Wk : Wv;
    float* Y = (z == 0) ? Q : (z == 1) ? K : V;
    gemm_body<false, false>(X, nullptr, W, Y, 256, 256, 256, 256,
                            blockIdx.y * 64, blockIdx.x * 64);
}

// ---------------- fused attention (R7-verbatim): 2 rows/thread ----------------
#define ATTN_SMEM 70016

#define ISSUE_KV(t_, buf_) do { \
    const float* ksrc_ = Kb + (size_t)(sbase + (t_) * ST) * D_; \
    const float* vsrc_ = Vb + (size_t)(sbase + (t_) * ST) * D_; \
    u32 kd_ = kbase + (u32)(buf_) * 16384; \
    u32 vd_ = vbase + (u32)(buf_) * 16384; \
    _Pragma("unroll") \
    for (int i_ = 0; i_ < 4; i_++) { \
        int idx_ = tid + 256 * i_; int s_ = idx_ >> 6; int c_ = (idx_ & 63) * 4; \
        asm volatile("cp.async.cg.shared.global [%0], [%1], 16;" :: \
            "r"(kd_ + (u32)(s_ * 256 + c_) * 4), "l"(ksrc_ + s_ * 256 + c_)); \
        asm volatile("cp.async.cg.shared.global [%0], [%1], 16;" :: \
            "r"(vd_ + (u32)(s_ * 256 + c_) * 4), "l"(vsrc_ + s_ * 256 + c_)); \
    } \
    asm volatile("cp.async.commit_group;"); \
} while (0)

#define LOAD_AF(t_) do { \
    afr0 = afb[(size_t)(tid >> 4) * S_ + (t_) * ST + (tid & 15)]; \
    afr1 = afb[(size_t)((tid >> 4) + 16) * S_ + (t_) * ST + (tid & 15)]; \
} while (0)

#define STORE_AF(buf_) do { \
    Afs[(buf_) * 544 + (tid >> 4) * 17 + (tid & 15)] = afr0; \
    Afs[(buf_) * 544 + ((tid >> 4) + 16) * 17 + (tid & 15)] = afr1; \
} while (0)

__global__ void __launch_bounds__(256, 2) attn4(
    const float* __restrict__ Qg, const float* __restrict__ Kg,
    const float* __restrict__ Vg, const float* __restrict__ af,
    float* __restrict__ Op, float* __restrict__ SSp) {
    extern __shared__ float sm[];
    float* Ksm = sm;                 // 2*16*256 = 8192 floats
    float* Vsm = sm + 8192;          // 8192
    float* Afs = sm + 16384;         // 2*32*17 = 1088

    const int b = blockIdx.z, sp = blockIdx.y;
    const int l0 = blockIdx.x * LT;
    const int tid = threadIdx.x;
    const int w = tid >> 5, lane = tid & 31;
    const int lr = lane & 15, half = lane >> 4;
    const int dimoff = w * 32 + half * 16;
    const int sbase = sp * SHALF;
    const float* Kb  = Kg + (size_t)b * S_ * D_;
    const float* Vb  = Vg + (size_t)b * S_ * D_;
    const float* afb = af + ((size_t)b * L_ + l0) * S_ + sbase;
    const u32 smb = (u32)__cvta_generic_to_shared(sm);
    const u32 kbase = smb;
    const u32 vbase = smb + 8192 * 4;

    ull q0[8], q1[8];
    {
        const float QS = 0.25503486f;  // 1.4426950408889634 / sqrt(32)
        const float* qr0 = Qg + ((size_t)b * L_ + l0 + lr) * D_ + dimoff;
        const float* qr1 = qr0 + 16 * D_;
        #pragma unroll
        for (int i = 0; i < 4; i++) {
            float4 f = *(const float4*)(qr0 + i * 4);
            f.x *= QS; f.y *= QS; f.z *= QS; f.w *= QS;
            PACK2(q0[2 * i], f.x, f.y);
            PACK2(q0[2 * i + 1], f.z, f.w);
            float4 g = *(const float4*)(qr1 + i * 4);
            g.x *= QS; g.y *= QS; g.z *= QS; g.w *= QS;
            PACK2(q1[2 * i], g.x, g.y);
            PACK2(q1[2 * i + 1], g.z, g.w);
        }
    }
    ull zero; PACK2(zero, 0.0f, 0.0f);
    ull o0[8], o1[8];
    #pragma unroll
    for (int i = 0; i < 8; i++) { o0[i] = zero; o1[i] = zero; }
    float ssum0 = 0.0f, ssum1 = 0.0f;
    float afr0, afr1;

    ISSUE_KV(0, 0);
    LOAD_AF(0);
    ISSUE_KV(1, 1);
    STORE_AF(0);
    LOAD_AF(1);

    for (int t = 0; t < NT; t++) {
        const int buf = t & 1;
        if (t + 1 < NT) asm volatile("cp.async.wait_group 1;");
        else            asm volatile("cp.async.wait_group 0;");
        __syncthreads();
        if (t + 1 < NT) STORE_AF(buf ^ 1);
        if (t + 2 < NT) LOAD_AF(t + 2);

        const float* ks   = Ksm + buf * 4096 + dimoff;
        const float* vs   = Vsm + buf * 4096 + dimoff;
        const float* afl0 = Afs + buf * 544 + lr * 17;
        const float* afl1 = afl0 + 16 * 17;

        #pragma unroll 4
        for (int s = 0; s < ST; s++) {
            const ulonglong2* kp = (const ulonglong2*)(ks + s * 256);
            ull a0, a1, c0, c1;
            {
                ulonglong2 kv = kp[0];
                MUL2(a0, q0[0], kv.x); MUL2(a1, q0[1], kv.y);
                MUL2(c0, q1[0], kv.x); MUL2(c1, q1[1], kv.y);
            }
            { ulonglong2 kv = kp[1];
              FMA2(a0, q0[2], kv.x, a0); FMA2(a1, q0[3], kv.y, a1);
              FMA2(c0, q1[2], kv.x, c0); FMA2(c1, q1[3], kv.y, c1); }
            { ulonglong2 kv = kp[2];
              FMA2(a0, q0[4], kv.x, a0); FMA2(a1, q0[5], kv.y, a1);
              FMA2(c0, q1[4], kv.x, c0); FMA2(c1, q1[5], kv.y, c1); }
            { ulonglong2 kv = kp[3];
              FMA2(a0, q0[6], kv.x, a0); FMA2(a1, q0[7], kv.y, a1);
              FMA2(c0, q1[6], kv.x, c0); FMA2(c1, q1[7], kv.y, c1); }
            ADD2(a0, a0, a1); ADD2(c0, c0, c1);
            float xa0, xa1, xc0, xc1;
            UNPACK2(xa0, xa1, a0);
            UNPACK2(xc0, xc1, c0);
            float xa = xa0 + xa1;
            float xc = xc0 + xc1;
            xa += __shfl_xor_sync(0xffffffffu, xa, 16);
            xc += __shfl_xor_sync(0xffffffffu, xc, 16);
            float p0 = ex2f(xa * afl0[s]);
            float p1 = ex2f(xc * afl1[s]);
            ssum0 += p0; ssum1 += p1;
            ull pp0, pp1; PACK2(pp0, p0, p0); PACK2(pp1, p1, p1);
            const ulonglong2* vp = (const ulonglong2*)(vs + s * 256);
            #pragma unroll
            for (int j = 0; j < 4; j++) {
                ulonglong2 vv = vp[j];
                FMA2(o0[2 * j],     pp0, vv.x, o0[2 * j]);
                FMA2(o0[2 * j + 1], pp0, vv.y, o0[2 * j + 1]);
                FMA2(o1[2 * j],     pp1, vv.x, o1[2 * j]);
                FMA2(o1[2 * j + 1], pp1, vv.y, o1[2 * j + 1]);
            }
        }
        __syncthreads();
        if (t + 2 < NT) ISSUE_KV(t + 2, buf);
    }

    float* op0 = Op + (((size_t)sp * B_ + b) * L_ + l0 + lr) * D_ + dimoff;
    float* op1 = op0 + 16 * D_;
    #pragma unroll
    for (int j = 0; j < 2; j++) {
        float v0, v1, v2, v3;
        UNPACK2(v0, v1, o0[2 * j * 2]);     UNPACK2(v2, v3, o0[2 * j * 2 + 1]);
        float4 f; f.x = v0; f.y = v1; f.z = v2; f.w = v3;
        *(float4*)(op0 + j * 8) = f;
        UNPACK2(v0, v1, o0[2 * j * 2 + 2]); UNPACK2(v2, v3, o0[2 * j * 2 + 3]);
        float4 g; g.x = v0; g.y = v1; g.z = v2; g.w = v3;
        *(float4*)(op0 + j * 8 + 4) = g;
        UNPACK2(v0, v1, o1[2 * j * 2]);     UNPACK2(v2, v3, o1[2 * j * 2 + 1]);
        float4 h; h.x = v0; h.y = v1; h.z = v2; h.w = v3;
        *(float4*)(op1 + j * 8) = h;
        UNPACK2(v0, v1, o1[2 * j * 2 + 2]); UNPACK2(v2, v3, o1[2 * j * 2 + 3]);
        float4 e; e.x = v0; e.y = v1; e.z = v2; e.w = v3;
        *(float4*)(op1 + j * 8 + 4) = e;
    }
    if (half == 0) {
        size_t ssb = (((size_t)sp * B_ + b) * H_ + w) * L_ + l0;
        SSp[ssb + lr] = ssum0;
        SSp[ssb + 16 + lr] = ssum1;
    }
}

// ---------------- combine split partials: O = (O0+O1)/(s0+s1) ----------------
__global__ void combine_kernel(const float* __restrict__ Op, const float* __restrict__ SSp,
                               float* __restrict__ O) {
    size_t i = (size_t)blockIdx.x * 256 + threadIdx.x;   // per float4
    size_t e = i * 4;
    int d = (int)(e & 255);
    size_t bl = e >> 8;                 // b*L + l
    int h = d >> 5;
    size_t b = bl >> 11, l = bl & 2047;
    float4 a = *(const float4*)(Op + e);
    float4 c = *(const float4*)(Op + (size_t)B_ * L_ * D_ + e);
    float s = SSp[(b * H_ + h) * L_ + l] + SSp[((size_t)B_ * H_ + b * H_ + h) * L_ + l];
    float inv = 1.0f / s;
    float4 r;
    r.x = (a.x + c.x) * inv; r.y = (a.y + c.y) * inv;
    r.z = (a.z + c.z) * inv; r.w = (a.w + c.w) * inv;
    *(float4*)(O + e) = r;
}

// ---------------- LayerNorm over D=256, two-input sum, shuffle reduce ----------------
template <bool RESID, bool TWOIN>
__global__ void ln_kernel(const float* __restrict__ in0, const float* __restrict__ in1,
                          const float* __restrict__ g, const float* __restrict__ bt,
                          const float* __restrict__ resid, float* __restrict__ out) {
    const size_t row = blockIdx.x;
    const int tid = threadIdx.x;
    const int lane = tid & 31, wid = tid >> 5;
    float x = in0[row * D_ + tid];
    if (TWOIN) x += in1[row * D_ + tid];
    __shared__ float ws[8];

    float v = x;
    #pragma unroll
    for (int off = 16; off > 0; off >>= 1) v += __shfl_xor_sync(0xffffffffu, v, off);
    if (lane == 0) ws[wid] = v;
    __syncthreads();
    float mean = 0.0f;
    #pragma unroll
    for (int i = 0; i < 8; i++) mean += ws[i];
    mean *= (1.0f / D_);
    __syncthreads();

    const float d = x - mean;
    v = d * d;
    #pragma unroll
    for (int off = 16; off > 0; off >>= 1) v += __shfl_xor_sync(0xffffffffu, v, off);
    if (lane == 0) ws[wid] = v;
    __syncthreads();
    float var = 0.0f;
    #pragma unroll
    for (int i = 0; i < 8; i++) var += ws[i];
    var *= (1.0f / D_);

    float y = d * rsqrtf(var + 1e-5f) * g[tid] + bt[tid];
    if (RESID) y += resid[row * D_ + tid];
    out[row * D_ + tid] = y;
}

// ---------------- launch ----------------
extern "C" void kernel_launch(void* const* d_in, const int* in_sizes, int n_in,
                              void* d_out, int out_size) {
    const float* x   = (const float*)d_in[0];
    const float* src = (const float*)d_in[1];
    const float* af  = (const float*)d_in[2];
    const float* Wq  = (const float*)d_in[3];
    const float* Wk  = (const float*)d_in[4];
    const float* Wv  = (const float*)d_in[5];
    const float* Wm  = (const float*)d_in[6];
    const float* W1  = (const float*)d_in[7];
    const float* W2  = (const float*)d_in[8];
    const float* g1  = (const float*)d_in[9];
    const float* b1  = (const float*)d_in[10];
    const float* g2  = (const float*)d_in[11];
    const float* b2  = (const float*)d_in[12];
    float* out = (float*)d_out;

    float *Q, *K, *V, *OP, *SS, *O, *M, *HB, *T;
    cudaGetSymbolAddress((void**)&Q,  g_Q);
    cudaGetSymbolAddress((void**)&K,  g_K);
    cudaGetSymbolAddress((void**)&V,  g_V);
    cudaGetSymbolAddress((void**)&OP, g_OP);
    cudaGetSymbolAddress((void**)&SS, g_SS);
    cudaGetSymbolAddress((void**)&O,  g_O);
    cudaGetSymbolAddress((void**)&M,  g_M);
    cudaGetSymbolAddress((void**)&HB, g_HB);
    cudaGetSymbolAddress((void**)&T,  g_T);

    cudaFuncSetAttribute(attn4, cudaFuncAttributeMaxDynamicSharedMemorySize, ATTN_SMEM);

    const int ML = B_ * L_;  // 4096

    // projections (one launch, grid.z selects Q/K/V)
    gemm_qkv<<<dim3(4, ML / 64, 3), 128>>>(x, src, Wq, Wk, Wv, Q, K, V);

    // attention (raw partials OP + sums SS), then combine -> O
    attn4<<<dim3(L_ / LT, SPLITS, B_), 256, ATTN_SMEM>>>(Q, K, V, af, OP, SS);
    combine_kernel<<<(B_ * L_ * D_ / 4) / 256, 256>>>(OP, SS, O);

    // output proj (split-K=2, partials M+T) + LN1 (sums partials) -> Q (reused)
    gemm_splitk<<<dim3(4, ML / 64, 2), 128>>>(O, Wm, M, T, 256, 128, 256, 256);
    ln_kernel<false, true><<<ML, 256>>>(M, T, g1, b1, nullptr, Q);

    // MLP: h = relu([x, LN1] @ W1^T)
    gemm64<true, true><<<dim3(8, ML / 64), 128>>>(x, Q, W1, HB, 512, 512, 256, 512);
    // W2 (split-K=2, partials M+T)
    gemm_splitk<<<dim3(4, ML / 64, 2), 128>>>(HB, W2, M, T, 256, 256, 512, 512);

    // LN2 (sums partials) + residual -> out
    ln_kernel<true, true><<<ML, 256>>>(M, T, g2, b2, x, out);
}

// round 11
// speedup vs baseline: 1.3952x; 1.0607x over previous
#include <cuda_runtime.h>
#include <math.h>

typedef unsigned long long ull;
typedef unsigned int u32;

#define B_  2
#define L_  2048
#define S_  2048
#define D_  256
#define H_  8
#define SPLITS 2
#define SHALF (S_ / SPLITS)      // 1024
#define LT 32                    // l-rows per block
#define ST 16
#define NT (SHALF / ST)          // 64

// ---------------- f32x2 packed math ----------------
#define PACK2(d, x, y) asm("mov.b64 %0, {%1, %2};" : "=l"(d) : "r"(__float_as_uint(x)), "r"(__float_as_uint(y)))
#define UNPACK2(x, y, d) do { u32 _lo, _hi; \
    asm("mov.b64 {%0, %1}, %2;" : "=r"(_lo), "=r"(_hi) : "l"(d)); \
    (x) = __uint_as_float(_lo); (y) = __uint_as_float(_hi); } while (0)
#define FMA2(d, a, b, c) asm("fma.rn.f32x2 %0, %1, %2, %3;" : "=l"(d) : "l"(a), "l"(b), "l"(c))
#define MUL2(d, a, b)    asm("mul.rn.f32x2 %0, %1, %2;"     : "=l"(d) : "l"(a), "l"(b))
#define ADD2(d, a, b)    asm("add.rn.f32x2 %0, %1, %2;"     : "=l"(d) : "l"(a), "l"(b))

__device__ __forceinline__ float ex2f(float x) {
    float r;
    asm("ex2.approx.ftz.f32 %0, %1;" : "=f"(r) : "f"(x));
    return r;
}

// ---------------- scratch ----------------
__device__ float g_Q[(size_t)B_ * L_ * D_];
__device__ float g_K[(size_t)B_ * S_ * D_];
__device__ float g_V[(size_t)B_ * S_ * D_];
__device__ float g_OP[(size_t)SPLITS * B_ * L_ * D_];
__device__ float g_SS[(size_t)SPLITS * B_ * H_ * L_];
__device__ float g_O[(size_t)B_ * L_ * D_];
__device__ float g_M[(size_t)B_ * L_ * D_];
__device__ float g_HB[(size_t)B_ * L_ * 2 * D_];
__device__ float g_T[(size_t)B_ * L_ * D_];

// ---------------- GEMM core (proven 128-thread 4x8 inner loop) ----------------
// Tile 64x64, 128 threads, microtile 4(m)x8(n), f32x2 pairs along n.
// MODE 0: plain (ldx),  MODE 1: X=[X|X2] along K (each 256 wide),
// MODE 2: combine loader — X=(OP0+OP1)*inv(SS0+SS1); kz = absolute k offset.
template <bool RELU, int MODE>
__device__ __forceinline__ void gemm_body(
    const float* __restrict__ X, const float* __restrict__ X2,
    const float* __restrict__ SSp,
    const float* __restrict__ W, float* __restrict__ Y,
    int N, int K, int ldx, int ldw, int bm, int bn, int kz) {
    __shared__ float XsT[16][68];   // [k][m]
    __shared__ float BsT[16][72];   // [k][n]
    const int t = threadIdx.x, tx = t & 7, ty = t >> 3;
    const int NTk = K >> 4;

    float4 xr[2], wr[2];
    #define LOAD_XW(kc_) do { \
        int kc = (kc_); \
        _Pragma("unroll") \
        for (int i = 0; i < 2; i++) { \
            int idx = t + 128 * i; int r = idx >> 2; int c = (idx & 3) * 4 + kc; \
            if (MODE == 1) { \
                xr[i] = (c < 256) ? *(const float4*)(X + (size_t)(bm + r) * 256 + c) \
                                  : *(const float4*)(X2 + (size_t)(bm + r) * 256 + (c - 256)); \
            } else if (MODE == 2) { \
                size_t row = bm + r; \
                int kabs = kz + c; \
                size_t e = row * 256 + kabs; \
                float4 a = *(const float4*)(X + e); \
                float4 c2 = *(const float4*)(X2 + e); \
                size_t bb = row >> 11; size_t l = row & 2047; \
                int h = kabs >> 5; \
                float s = SSp[(bb * H_ + h) * L_ + l] \
                        + SSp[(size_t)B_ * H_ * L_ + (bb * H_ + h) * L_ + l]; \
                float inv = 1.0f / s; \
                xr[i].x = (a.x + c2.x) * inv; xr[i].y = (a.y + c2.y) * inv; \
                xr[i].z = (a.z + c2.z) * inv; xr[i].w = (a.w + c2.w) * inv; \
            } else { \
                xr[i] = *(const float4*)(X + (size_t)(bm + r) * ldx + c); \
            } \
            wr[i] = *(const float4*)(W + (size_t)(bn + r) * ldw + c); \
        } \
    } while (0)

    LOAD_XW(0);

    ull acc[4][4]; ull zero; PACK2(zero, 0.0f, 0.0f);
    #pragma unroll
    for (int m = 0; m < 4; m++)
        #pragma unroll
        for (int n = 0; n < 4; n++) acc[m][n] = zero;

    for (int kt = 0; kt < NTk; kt++) {
        __syncthreads();
        #pragma unroll
        for (int i = 0; i < 2; i++) {
            int idx = t + 128 * i; int r = idx >> 2; int c = (idx & 3) * 4;
            XsT[c + 0][r] = xr[i].x; XsT[c + 1][r] = xr[i].y;
            XsT[c + 2][r] = xr[i].z; XsT[c + 3][r] = xr[i].w;
            BsT[c + 0][r] = wr[i].x; BsT[c + 1][r] = wr[i].y;
            BsT[c + 2][r] = wr[i].z; BsT[c + 3][r] = wr[i].w;
        }
        if (kt + 1 < NTk) LOAD_XW((kt + 1) * 16);
        __syncthreads();
        #pragma unroll
        for (int kk = 0; kk < 16; kk++) {
            float4 a4 = *(const float4*)&XsT[kk][ty * 4];
            ulonglong2 b01 = *(const ulonglong2*)&BsT[kk][tx * 8];
            ulonglong2 b23 = *(const ulonglong2*)&BsT[kk][tx * 8 + 4];
            ull am;
            PACK2(am, a4.x, a4.x);
            FMA2(acc[0][0], am, b01.x, acc[0][0]); FMA2(acc[0][1], am, b01.y, acc[0][1]);
            FMA2(acc[0][2], am, b23.x, acc[0][2]); FMA2(acc[0][3], am, b23.y, acc[0][3]);
            PACK2(am, a4.y, a4.y);
            FMA2(acc[1][0], am, b01.x, acc[1][0]); FMA2(acc[1][1], am, b01.y, acc[1][1]);
            FMA2(acc[1][2], am, b23.x, acc[1][2]); FMA2(acc[1][3], am, b23.y, acc[1][3]);
            PACK2(am, a4.z, a4.z);
            FMA2(acc[2][0], am, b01.x, acc[2][0]); FMA2(acc[2][1], am, b01.y, acc[2][1]);
            FMA2(acc[2][2], am, b23.x, acc[2][2]); FMA2(acc[2][3], am, b23.y, acc[2][3]);
            PACK2(am, a4.w, a4.w);
            FMA2(acc[3][0], am, b01.x, acc[3][0]); FMA2(acc[3][1], am, b01.y, acc[3][1]);
            FMA2(acc[3][2], am, b23.x, acc[3][2]); FMA2(acc[3][3], am, b23.y, acc[3][3]);
        }
    }
    #undef LOAD_XW

    float o[4][8];
    #pragma unroll
    for (int m = 0; m < 4; m++)
        #pragma unroll
        for (int np = 0; np < 4; np++)
            UNPACK2(o[m][2 * np], o[m][2 * np + 1], acc[m][np]);
    #pragma unroll
    for (int r = 0; r < 4; r++) {
        if (RELU)
            #pragma unroll
            for (int n = 0; n < 8; n++) o[r][n] = fmaxf(o[r][n], 0.0f);
        float4 w0, w1;
        w0.x = o[r][0]; w0.y = o[r][1]; w0.z = o[r][2]; w0.w = o[r][3];
        w1.x = o[r][4]; w1.y = o[r][5]; w1.z = o[r][6]; w1.w = o[r][7];
        float* yp = Y + (size_t)(bm + ty * 4 + r) * N + bn + tx * 8;
        *(float4*)yp = w0;
        *(float4*)(yp + 4) = w1;
    }
}

// fused QKV projections
__global__ void __launch_bounds__(128) gemm_qkv(
    const float* __restrict__ x, const float* __restrict__ src,
    const float* __restrict__ Wq, const float* __restrict__ Wk,
    const float* __restrict__ Wv,
    float* __restrict__ Q, float* __restrict__ K, float* __restrict__ V) {
    const int z = blockIdx.z;
    const float* X = (z == 0) ? x : src;
    const float* W = (z == 0) ? Wq : (z == 1) ? Wk : Wv;
    float* Y = (z == 0) ? Q : (z == 1) ? K : V;
    gemm_body<false, 0>(X, nullptr, nullptr, W, Y, 256, 256, 256, 256,
                        blockIdx.y * 64, blockIdx.x * 64, 0);
}

// Wm with fused attention-combine, split-K=2 (z picks K-half; partials Y0/Y1)
__global__ void __launch_bounds__(128) gemm_wm_combine(
    const float* __restrict__ OP0, const float* __restrict__ OP1,
    const float* __restrict__ SSp, const float* __restrict__ Wm,
    float* __restrict__ Y0, float* __restrict__ Y1) {
    const int z = blockIdx.z;
    const int kz = z * 128;
    gemm_body<false, 2>(OP0, OP1, SSp, Wm + kz, z ? Y1 : Y0,
                        256, 128, 256, 256, blockIdx.y * 64, blockIdx.x * 64, kz);
}

// W2 split-K=4 (z picks K-quarter; partials Y0..Y3)
__global__ void __launch_bounds__(128) gemm_w2_splitk(
    const float* __restrict__ X, const float* __restrict__ W,
    float* __restrict__ Y0, float* __restrict__ Y1,
    float* __restrict__ Y2, float* __restrict__ Y3) {
    const int z = blockIdx.z;
    float* Y = (z == 0) ? Y0 : (z == 1) ? Y1 : (z == 2) ? Y2 : Y3;
    gemm_body<false, 0>(X + z * 128, nullptr, nullptr, W + z * 128, Y,
                        256, 128, 512, 512, blockIdx.y * 64, blockIdx.x * 64, 0);
}

// ---------------- W1 GEMM: 64x32 tiles (1024 blocks), SPLIT X = [x | ln1] ----------------
__global__ void __launch_bounds__(128) gemm_w1(
    const float* __restrict__ X, const float* __restrict__ X2,
    const float* __restrict__ W, float* __restrict__ Y) {
    __shared__ float XsT[16][68];   // [k][m=64]
    __shared__ float BsT[16][36];   // [k][n=32]
    const int bm = blockIdx.y * 64, bn = blockIdx.x * 32;
    const int t = threadIdx.x, tx = t & 7, ty = t >> 3;
    const int NTk = 512 >> 4;       // 32

    float4 xr[2], wr;
    #define LOAD_XW1(kc_) do { \
        int kc = (kc_); \
        _Pragma("unroll") \
        for (int i = 0; i < 2; i++) { \
            int idx = t + 128 * i; int r = idx >> 2; int c = (idx & 3) * 4 + kc; \
            xr[i] = (c < 256) ? *(const float4*)(X + (size_t)(bm + r) * 256 + c) \
                              : *(const float4*)(X2 + (size_t)(bm + r) * 256 + (c - 256)); \
        } \
        { int r = t >> 2; int c = (t & 3) * 4 + kc; \
          wr = *(const float4*)(W + (size_t)(bn + r) * 512 + c); } \
    } while (0)

    LOAD_XW1(0);

    ull acc[4][2]; ull zero; PACK2(zero, 0.0f, 0.0f);
    #pragma unroll
    for (int m = 0; m < 4; m++) { acc[m][0] = zero; acc[m][1] = zero; }

    for (int kt = 0; kt < NTk; kt++) {
        __syncthreads();
        #pragma unroll
        for (int i = 0; i < 2; i++) {
            int idx = t + 128 * i; int r = idx >> 2; int c = (idx & 3) * 4;
            XsT[c + 0][r] = xr[i].x; XsT[c + 1][r] = xr[i].y;
            XsT[c + 2][r] = xr[i].z; XsT[c + 3][r] = xr[i].w;
        }
        {
            int r = t >> 2; int c = (t & 3) * 4;
            BsT[c + 0][r] = wr.x; BsT[c + 1][r] = wr.y;
            BsT[c + 2][r] = wr.z; BsT[c + 3][r] = wr.w;
        }
        if (kt + 1 < NTk) LOAD_XW1((kt + 1) * 16);
        __syncthreads();
        #pragma unroll
        for (int kk = 0; kk < 16; kk++) {
            float4 a4 = *(const float4*)&XsT[kk][ty * 4];
            ulonglong2 b01 = *(const ulonglong2*)&BsT[kk][tx * 4];
            ull am;
            PACK2(am, a4.x, a4.x);
            FMA2(acc[0][0], am, b01.x, acc[0][0]); FMA2(acc[0][1], am, b01.y, acc[0][1]);
            PACK2(am, a4.y, a4.y);
            FMA2(acc[1][0], am, b01.x, acc[1][0]); FMA2(acc[1][1], am, b01.y, acc[1][1]);
            PACK2(am, a4.z, a4.z);
            FMA2(acc[2][0], am, b01.x, acc[2][0]); FMA2(acc[2][1], am, b01.y, acc[2][1]);
            PACK2(am, a4.w, a4.w);
            FMA2(acc[3][0], am, b01.x, acc[3][0]); FMA2(acc[3][1], am, b01.y, acc[3][1]);
        }
    }
    #undef LOAD_XW1

    #pragma unroll
    for (int r = 0; r < 4; r++) {
        float v0, v1, v2, v3;
        UNPACK2(v0, v1, acc[r][0]);
        UNPACK2(v2, v3, acc[r][1]);
        float4 w0;
        w0.x = fmaxf(v0, 0.0f); w0.y = fmaxf(v1, 0.0f);
        w0.z = fmaxf(v2, 0.0f); w0.w = fmaxf(v3, 0.0f);
        *(float4*)(Y + (size_t)(bm + ty * 4 + r) * 512 + bn + tx * 4) = w0;
    }
}

// ---------------- fused attention (R7-verbatim): 2 rows/thread ----------------
#define ATTN_SMEM 70016

#define ISSUE_KV(t_, buf_) do { \
    const float* ksrc_ = Kb + (size_t)(sbase + (t_) * ST) * D_; \
    const float* vsrc_ = Vb + (size_t)(sbase + (t_) * ST) * D_; \
    u32 kd_ = kbase + (u32)(buf_) * 16384; \
    u32 vd_ = vbase + (u32)(buf_) * 16384; \
    _Pragma("unroll") \
    for (int i_ = 0; i_ < 4; i_++) { \
        int idx_ = tid + 256 * i_; int s_ = idx_ >> 6; int c_ = (idx_ & 63) * 4; \
        asm volatile("cp.async.cg.shared.global [%0], [%1], 16;" :: \
            "r"(kd_ + (u32)(s_ * 256 + c_) * 4), "l"(ksrc_ + s_ * 256 + c_)); \
        asm volatile("cp.async.cg.shared.global [%0], [%1], 16;" :: \
            "r"(vd_ + (u32)(s_ * 256 + c_) * 4), "l"(vsrc_ + s_ * 256 + c_)); \
    } \
    asm volatile("cp.async.commit_group;"); \
} while (0)

#define LOAD_AF(t_) do { \
    afr0 = afb[(size_t)(tid >> 4) * S_ + (t_) * ST + (tid & 15)]; \
    afr1 = afb[(size_t)((tid >> 4) + 16) * S_ + (t_) * ST + (tid & 15)]; \
} while (0)

#define STORE_AF(buf_) do { \
    Afs[(buf_) * 544 + (tid >> 4) * 17 + (tid & 15)] = afr0; \
    Afs[(buf_) * 544 + ((tid >> 4) + 16) * 17 + (tid & 15)] = afr1; \
} while (0)

__global__ void __launch_bounds__(256, 2) attn4(
    const float* __restrict__ Qg, const float* __restrict__ Kg,
    const float* __restrict__ Vg, const float* __restrict__ af,
    float* __restrict__ Op, float* __restrict__ SSp) {
    extern __shared__ float sm[];
    float* Ksm = sm;                 // 2*16*256 = 8192 floats
    float* Vsm = sm + 8192;          // 8192
    float* Afs = sm + 16384;         // 2*32*17 = 1088

    const int b = blockIdx.z, sp = blockIdx.y;
    const int l0 = blockIdx.x * LT;
    const int tid = threadIdx.x;
    const int w = tid >> 5, lane = tid & 31;
    const int lr = lane & 15, half = lane >> 4;
    const int dimoff = w * 32 + half * 16;
    const int sbase = sp * SHALF;
    const float* Kb  = Kg + (size_t)b * S_ * D_;
    const float* Vb  = Vg + (size_t)b * S_ * D_;
    const float* afb = af + ((size_t)b * L_ + l0) * S_ + sbase;
    const u32 smb = (u32)__cvta_generic_to_shared(sm);
    const u32 kbase = smb;
    const u32 vbase = smb + 8192 * 4;

    ull q0[8], q1[8];
    {
        const float QS = 0.25503486f;  // 1.4426950408889634 / sqrt(32)
        const float* qr0 = Qg + ((size_t)b * L_ + l0 + lr) * D_ + dimoff;
        const float* qr1 = qr0 + 16 * D_;
        #pragma unroll
        for (int i = 0; i < 4; i++) {
            float4 f = *(const float4*)(qr0 + i * 4);
            f.x *= QS; f.y *= QS; f.z *= QS; f.w *= QS;
            PACK2(q0[2 * i], f.x, f.y);
            PACK2(q0[2 * i + 1], f.z, f.w);
            float4 g = *(const float4*)(qr1 + i * 4);
            g.x *= QS; g.y *= QS; g.z *= QS; g.w *= QS;
            PACK2(q1[2 * i], g.x, g.y);
            PACK2(q1[2 * i + 1], g.z, g.w);
        }
    }
    ull zero; PACK2(zero, 0.0f, 0.0f);
    ull o0[8], o1[8];
    #pragma unroll
    for (int i = 0; i < 8; i++) { o0[i] = zero; o1[i] = zero; }
    float ssum0 = 0.0f, ssum1 = 0.0f;
    float afr0, afr1;

    ISSUE_KV(0, 0);
    LOAD_AF(0);
    ISSUE_KV(1, 1);
    STORE_AF(0);
    LOAD_AF(1);

    for (int t = 0; t < NT; t++) {
        const int buf = t & 1;
        if (t + 1 < NT) asm volatile("cp.async.wait_group 1;");
        else            asm volatile("cp.async.wait_group 0;");
        __syncthreads();
        if (t + 1 < NT) STORE_AF(buf ^ 1);
        if (t + 2 < NT) LOAD_AF(t + 2);

        const float* ks   = Ksm + buf * 4096 + dimoff;
        const float* vs   = Vsm + buf * 4096 + dimoff;
        const float* afl0 = Afs + buf * 544 + lr * 17;
        const float* afl1 = afl0 + 16 * 17;

        #pragma unroll 4
        for (int s = 0; s < ST; s++) {
            const ulonglong2* kp = (const ulonglong2*)(ks + s * 256);
            ull a0, a1, c0, c1;
            {
                ulonglong2 kv = kp[0];
                MUL2(a0, q0[0], kv.x); MUL2(a1, q0[1], kv.y);
                MUL2(c0, q1[0], kv.x); MUL2(c1, q1[1], kv.y);
            }
            { ulonglong2 kv = kp[1];
              FMA2(a0, q0[2], kv.x, a0); FMA2(a1, q0[3], kv.y, a1);
              FMA2(c0, q1[2], kv.x, c0); FMA2(c1, q1[3], kv.y, c1); }
            { ulonglong2 kv = kp[2];
              FMA2(a0, q0[4], kv.x, a0); FMA2(a1, q0[5], kv.y, a1);
              FMA2(c0, q1[4], kv.x, c0); FMA2(c1, q1[5], kv.y, c1); }
            { ulonglong2 kv = kp[3];
              FMA2(a0, q0[6], kv.x, a0); FMA2(a1, q0[7], kv.y, a1);
              FMA2(c0, q1[6], kv.x, c0); FMA2(c1, q1[7], kv.y, c1); }
            ADD2(a0, a0, a1); ADD2(c0, c0, c1);
            float xa0, xa1, xc0, xc1;
            UNPACK2(xa0, xa1, a0);
            UNPACK2(xc0, xc1, c0);
            float xa = xa0 + xa1;
            float xc = xc0 + xc1;
            xa += __shfl_xor_sync(0xffffffffu, xa, 16);
            xc += __shfl_xor_sync(0xffffffffu, xc, 16);
            float p0 = ex2f(xa * afl0[s]);
            float p1 = ex2f(xc * afl1[s]);
            ssum0 += p0; ssum1 += p1;
            ull pp0, pp1; PACK2(pp0, p0, p0); PACK2(pp1, p1, p1);
            const ulonglong2* vp = (const ulonglong2*)(vs + s * 256);
            #pragma unroll
            for (int j = 0; j < 4; j++) {
                ulonglong2 vv = vp[j];
                FMA2(o0[2 * j],     pp0, vv.x, o0[2 * j]);
                FMA2(o0[2 * j + 1], pp0, vv.y, o0[2 * j + 1]);
                FMA2(o1[2 * j],     pp1, vv.x, o1[2 * j]);
                FMA2(o1[2 * j + 1], pp1, vv.y, o1[2 * j + 1]);
            }
        }
        __syncthreads();
        if (t + 2 < NT) ISSUE_KV(t + 2, buf);
    }

    float* op0 = Op + (((size_t)sp * B_ + b) * L_ + l0 + lr) * D_ + dimoff;
    float* op1 = op0 + 16 * D_;
    #pragma unroll
    for (int j = 0; j < 2; j++) {
        float v0, v1, v2, v3;
        UNPACK2(v0, v1, o0[2 * j * 2]);     UNPACK2(v2, v3, o0[2 * j * 2 + 1]);
        float4 f; f.x = v0; f.y = v1; f.z = v2; f.w = v3;
        *(float4*)(op0 + j * 8) = f;
        UNPACK2(v0, v1, o0[2 * j * 2 + 2]); UNPACK2(v2, v3, o0[2 * j * 2 + 3]);
        float4 g; g.x = v0; g.y = v1; g.z = v2; g.w = v3;
        *(float4*)(op0 + j * 8 + 4) = g;
        UNPACK2(v0, v1, o1[2 * j * 2]);     UNPACK2(v2, v3, o1[2 * j * 2 + 1]);
        float4 h; h.x = v0; h.y = v1; h.z = v2; h.w = v3;
        *(float4*)(op1 + j * 8) = h;
        UNPACK2(v0, v1, o1[2 * j * 2 + 2]); UNPACK2(v2, v3, o1[2 * j * 2 + 3]);
        float4 e; e.x = v0; e.y = v1; e.z = v2; e.w = v3;
        *(float4*)(op1 + j * 8 + 4) = e;
    }
    if (half == 0) {
        size_t ssb = (((size_t)sp * B_ + b) * H_ + w) * L_ + l0;
        SSp[ssb + lr] = ssum0;
        SSp[ssb + 16 + lr] = ssum1;
    }
}

// ---------------- LayerNorm over D=256, NIN summed inputs, shuffle reduce ----------------
template <bool RESID, int NIN>
__global__ void ln_kernel(const float* __restrict__ in0, const float* __restrict__ in1,
                          const float* __restrict__ in2, const float* __restrict__ in3,
                          const float* __restrict__ g, const float* __restrict__ bt,
                          const float* __restrict__ resid, float* __restrict__ out) {
    const size_t row = blockIdx.x;
    const int tid = threadIdx.x;
    const int lane = tid & 31, wid = tid >> 5;
    float x = in0[row * D_ + tid];
    if (NIN > 1) x += in1[row * D_ + tid];
    if (NIN > 2) x += in2[row * D_ + tid];
    if (NIN > 3) x += in3[row * D_ + tid];
    __shared__ float ws[8];

    float v = x;
    #pragma unroll
    for (int off = 16; off > 0; off >>= 1) v += __shfl_xor_sync(0xffffffffu, v, off);
    if (lane == 0) ws[wid] = v;
    __syncthreads();
    float mean = 0.0f;
    #pragma unroll
    for (int i = 0; i < 8; i++) mean += ws[i];
    mean *= (1.0f / D_);
    __syncthreads();

    const float d = x - mean;
    v = d * d;
    #pragma unroll
    for (int off = 16; off > 0; off >>= 1) v += __shfl_xor_sync(0xffffffffu, v, off);
    if (lane == 0) ws[wid] = v;
    __syncthreads();
    float var = 0.0f;
    #pragma unroll
    for (int i = 0; i < 8; i++) var += ws[i];
    var *= (1.0f / D_);

    float y = d * rsqrtf(var + 1e-5f) * g[tid] + bt[tid];
    if (RESID) y += resid[row * D_ + tid];
    out[row * D_ + tid] = y;
}

// ---------------- launch ----------------
extern "C" void kernel_launch(void* const* d_in, const int* in_sizes, int n_in,
                              void* d_out, int out_size) {
    const float* x   = (const float*)d_in[0];
    const float* src = (const float*)d_in[1];
    const float* af  = (const float*)d_in[2];
    const float* Wq  = (const float*)d_in[3];
    const float* Wk  = (const float*)d_in[4];
    const float* Wv  = (const float*)d_in[5];
    const float* Wm  = (const float*)d_in[6];
    const float* W1  = (const float*)d_in[7];
    const float* W2  = (const float*)d_in[8];
    const float* g1  = (const float*)d_in[9];
    const float* b1  = (const float*)d_in[10];
    const float* g2  = (const float*)d_in[11];
    const float* b2  = (const float*)d_in[12];
    float* out = (float*)d_out;

    float *Q, *K, *V, *OP, *SS, *O, *M, *HB, *T;
    cudaGetSymbolAddress((void**)&Q,  g_Q);
    cudaGetSymbolAddress((void**)&K,  g_K);
    cudaGetSymbolAddress((void**)&V,  g_V);
    cudaGetSymbolAddress((void**)&OP, g_OP);
    cudaGetSymbolAddress((void**)&SS, g_SS);
    cudaGetSymbolAddress((void**)&O,  g_O);
    cudaGetSymbolAddress((void**)&M,  g_M);
    cudaGetSymbolAddress((void**)&HB, g_HB);
    cudaGetSymbolAddress((void**)&T,  g_T);

    cudaFuncSetAttribute(attn4, cudaFuncAttributeMaxDynamicSharedMemorySize, ATTN_SMEM);

    const int ML = B_ * L_;  // 4096
    float* OP1 = OP + (size_t)B_ * L_ * D_;

    // projections (one launch, grid.z selects Q/K/V)
    gemm_qkv<<<dim3(4, ML / 64, 3), 128>>>(x, src, Wq, Wk, Wv, Q, K, V);

    // attention (raw partials OP + sums SS)
    attn4<<<dim3(L_ / LT, SPLITS, B_), 256, ATTN_SMEM>>>(Q, K, V, af, OP, SS);

    // Wm with fused combine, split-K=2 (partials M,T) + LN1 (sums) -> O
    gemm_wm_combine<<<dim3(4, ML / 64, 2), 128>>>(OP, OP1, SS, Wm, M, T);
    ln_kernel<false, 2><<<ML, 256>>>(M, T, nullptr, nullptr, g1, b1, nullptr, O);

    // MLP: h = relu([x, LN1] @ W1^T), 64x32 tiles
    gemm_w1<<<dim3(16, ML / 64), 128>>>(x, O, W1, HB);
    // W2 split-K=4 (partials M,T,Q,K — Q/K free after attention)
    gemm_w2_splitk<<<dim3(4, ML / 64, 4), 128>>>(HB, W2, M, T, Q, K);

    // LN2 (sums 4 partials) + residual -> out
    ln_kernel<true, 4><<<ML, 256>>>(M, T, Q, K, g2, b2, x, out);
}

// round 13
// speedup vs baseline: 1.7403x; 1.2474x over previous
#include <cuda_runtime.h>
#include <math.h>

typedef unsigned long long ull;
typedef unsigned int u32;

#define B_  2
#define L_  2048
#define S_  2048
#define D_  256
#define H_  8
#define SPLITS 2
#define SHALF (S_ / SPLITS)      // 1024
#define NT (SHALF / 16)          // 64 s-tiles of 16

// ---------------- f32x2 packed math ----------------
#define PACK2(d, x, y) asm("mov.b64 %0, {%1, %2};" : "=l"(d) : "r"(__float_as_uint(x)), "r"(__float_as_uint(y)))
#define UNPACK2(x, y, d) do { u32 _lo, _hi; \
    asm("mov.b64 {%0, %1}, %2;" : "=r"(_lo), "=r"(_hi) : "l"(d)); \
    (x) = __uint_as_float(_lo); (y) = __uint_as_float(_hi); } while (0)
#define FMA2(d, a, b, c) asm("fma.rn.f32x2 %0, %1, %2, %3;" : "=l"(d) : "l"(a), "l"(b), "l"(c))

__device__ __forceinline__ float ex2f(float x) {
    float r;
    asm("ex2.approx.ftz.f32 %0, %1;" : "=f"(r) : "f"(x));
    return r;
}
__device__ __forceinline__ u32 tf32r(float x) {
    u32 r;
    asm("cvt.rna.tf32.f32 %0, %1;" : "=r"(r) : "f"(x));
    return r;
}

// mma.sync m16n8k8 tf32: D += A*B (C==D registers)
#define MMA_TF32(d, a, b) \
    asm volatile("mma.sync.aligned.m16n8k8.row.col.f32.tf32.tf32.f32 " \
        "{%0,%1,%2,%3},{%4,%5,%6,%7},{%8,%9},{%0,%1,%2,%3};" \
        : "+f"((d)[0]), "+f"((d)[1]), "+f"((d)[2]), "+f"((d)[3]) \
        : "r"((a)[0]), "r"((a)[1]), "r"((a)[2]), "r"((a)[3]), \
          "r"((b)[0]), "r"((b)[1]));

// ---------------- scratch ----------------
__device__ float g_Q[(size_t)B_ * L_ * D_];
__device__ float g_K[(size_t)B_ * S_ * D_];
__device__ float g_V[(size_t)B_ * S_ * D_];
__device__ float g_OP[(size_t)SPLITS * B_ * L_ * D_];
__device__ float g_SS[(size_t)SPLITS * B_ * H_ * L_];
__device__ float g_O[(size_t)B_ * L_ * D_];
__device__ float g_M[(size_t)B_ * L_ * D_];
__device__ float g_HB[(size_t)B_ * L_ * 2 * D_];
__device__ float g_T[(size_t)B_ * L_ * D_];

// ---------------- GEMM core (proven 128-thread 4x8 inner loop) ----------------
// MODE 0: plain, MODE 2: combine loader. CVT: tf32-round outputs (for K/V).
template <bool RELU, int MODE, bool CVT>
__device__ __forceinline__ void gemm_body(
    const float* __restrict__ X, const float* __restrict__ X2,
    const float* __restrict__ SSp,
    const float* __restrict__ W, float* __restrict__ Y,
    int N, int K, int ldx, int ldw, int bm, int bn, int kz) {
    __shared__ float XsT[16][68];
    __shared__ float BsT[16][72];
    const int t = threadIdx.x, tx = t & 7, ty = t >> 3;
    const int NTk = K >> 4;

    float4 xr[2], wr[2];
    #define LOAD_XW(kc_) do { \
        int kc = (kc_); \
        _Pragma("unroll") \
        for (int i = 0; i < 2; i++) { \
            int idx = t + 128 * i; int r = idx >> 2; int c = (idx & 3) * 4 + kc; \
            if (MODE == 1) { \
                xr[i] = (c < 256) ? *(const float4*)(X + (size_t)(bm + r) * 256 + c) \
                                  : *(const float4*)(X2 + (size_t)(bm + r) * 256 + (c - 256)); \
            } else if (MODE == 2) { \
                size_t row = bm + r; \
                int kabs = kz + c; \
                size_t e = row * 256 + kabs; \
                float4 a = *(const float4*)(X + e); \
                float4 c2 = *(const float4*)(X2 + e); \
                size_t bb = row >> 11; size_t l = row & 2047; \
                int h = kabs >> 5; \
                float s = SSp[(bb * H_ + h) * L_ + l] \
                        + SSp[(size_t)B_ * H_ * L_ + (bb * H_ + h) * L_ + l]; \
                float inv = 1.0f / s; \
                xr[i].x = (a.x + c2.x) * inv; xr[i].y = (a.y + c2.y) * inv; \
                xr[i].z = (a.z + c2.z) * inv; xr[i].w = (a.w + c2.w) * inv; \
            } else { \
                xr[i] = *(const float4*)(X + (size_t)(bm + r) * ldx + c); \
            } \
            wr[i] = *(const float4*)(W + (size_t)(bn + r) * ldw + c); \
        } \
    } while (0)

    LOAD_XW(0);

    ull acc[4][4]; ull zero; PACK2(zero, 0.0f, 0.0f);
    #pragma unroll
    for (int m = 0; m < 4; m++)
        #pragma unroll
        for (int n = 0; n < 4; n++) acc[m][n] = zero;

    for (int kt = 0; kt < NTk; kt++) {
        __syncthreads();
        #pragma unroll
        for (int i = 0; i < 2; i++) {
            int idx = t + 128 * i; int r = idx >> 2; int c = (idx & 3) * 4;
            XsT[c + 0][r] = xr[i].x; XsT[c + 1][r] = xr[i].y;
            XsT[c + 2][r] = xr[i].z; XsT[c + 3][r] = xr[i].w;
            BsT[c + 0][r] = wr[i].x; BsT[c + 1][r] = wr[i].y;
            BsT[c + 2][r] = wr[i].z; BsT[c + 3][r] = wr[i].w;
        }
        if (kt + 1 < NTk) LOAD_XW((kt + 1) * 16);
        __syncthreads();
        #pragma unroll
        for (int kk = 0; kk < 16; kk++) {
            float4 a4 = *(const float4*)&XsT[kk][ty * 4];
            ulonglong2 b01 = *(const ulonglong2*)&BsT[kk][tx * 8];
            ulonglong2 b23 = *(const ulonglong2*)&BsT[kk][tx * 8 + 4];
            ull am;
            PACK2(am, a4.x, a4.x);
            FMA2(acc[0][0], am, b01.x, acc[0][0]); FMA2(acc[0][1], am, b01.y, acc[0][1]);
            FMA2(acc[0][2], am, b23.x, acc[0][2]); FMA2(acc[0][3], am, b23.y, acc[0][3]);
            PACK2(am, a4.y, a4.y);
            FMA2(acc[1][0], am, b01.x, acc[1][0]); FMA2(acc[1][1], am, b01.y, acc[1][1]);
            FMA2(acc[1][2], am, b23.x, acc[1][2]); FMA2(acc[1][3], am, b23.y, acc[1][3]);
            PACK2(am, a4.z, a4.z);
            FMA2(acc[2][0], am, b01.x, acc[2][0]); FMA2(acc[2][1], am, b01.y, acc[2][1]);
            FMA2(acc[2][2], am, b23.x, acc[2][2]); FMA2(acc[2][3], am, b23.y, acc[2][3]);
            PACK2(am, a4.w, a4.w);
            FMA2(acc[3][0], am, b01.x, acc[3][0]); FMA2(acc[3][1], am, b01.y, acc[3][1]);
            FMA2(acc[3][2], am, b23.x, acc[3][2]); FMA2(acc[3][3], am, b23.y, acc[3][3]);
        }
    }
    #undef LOAD_XW

    float o[4][8];
    #pragma unroll
    for (int m = 0; m < 4; m++)
        #pragma unroll
        for (int np = 0; np < 4; np++)
            UNPACK2(o[m][2 * np], o[m][2 * np + 1], acc[m][np]);
    #pragma unroll
    for (int r = 0; r < 4; r++) {
        #pragma unroll
        for (int n = 0; n < 8; n++) {
            if (RELU) o[r][n] = fmaxf(o[r][n], 0.0f);
            if (CVT)  o[r][n] = __uint_as_float(tf32r(o[r][n]));
        }
        float4 w0, w1;
        w0.x = o[r][0]; w0.y = o[r][1]; w0.z = o[r][2]; w0.w = o[r][3];
        w1.x = o[r][4]; w1.y = o[r][5]; w1.z = o[r][6]; w1.w = o[r][7];
        float* yp = Y + (size_t)(bm + ty * 4 + r) * N + bn + tx * 8;
        *(float4*)yp = w0;
        *(float4*)(yp + 4) = w1;
    }
}

// fused QKV projections; K,V get tf32 rounding for the mma attention
__global__ void __launch_bounds__(128) gemm_qkv(
    const float* __restrict__ x, const float* __restrict__ src,
    const float* __restrict__ Wq, const float* __restrict__ Wk,
    const float* __restrict__ Wv,
    float* __restrict__ Q, float* __restrict__ K, float* __restrict__ V) {
    const int z = blockIdx.z;
    if (z == 0) {
        gemm_body<false, 0, false>(x, nullptr, nullptr, Wq, Q, 256, 256, 256, 256,
                                   blockIdx.y * 64, blockIdx.x * 64, 0);
    } else {
        const float* W = (z == 1) ? Wk : Wv;
        float* Y = (z == 1) ? K : V;
        gemm_body<false, 0, true>(src, nullptr, nullptr, W, Y, 256, 256, 256, 256,
                                  blockIdx.y * 64, blockIdx.x * 64, 0);
    }
}

// Wm with fused attention-combine, split-K=2
__global__ void __launch_bounds__(128) gemm_wm_combine(
    const float* __restrict__ OP0, const float* __restrict__ OP1,
    const float* __restrict__ SSp, const float* __restrict__ Wm,
    float* __restrict__ Y0, float* __restrict__ Y1) {
    const int z = blockIdx.z;
    const int kz = z * 128;
    gemm_body<false, 2, false>(OP0, OP1, SSp, Wm + kz, z ? Y1 : Y0,
                               256, 128, 256, 256, blockIdx.y * 64, blockIdx.x * 64, kz);
}

// W2 split-K=4
__global__ void __launch_bounds__(128) gemm_w2_splitk(
    const float* __restrict__ X, const float* __restrict__ W,
    float* __restrict__ Y0, float* __restrict__ Y1,
    float* __restrict__ Y2, float* __restrict__ Y3) {
    const int z = blockIdx.z;
    float* Y = (z == 0) ? Y0 : (z == 1) ? Y1 : (z == 2) ? Y2 : Y3;
    gemm_body<false, 0, false>(X + z * 128, nullptr, nullptr, W + z * 128, Y,
                               256, 128, 512, 512, blockIdx.y * 64, blockIdx.x * 64, 0);
}

// ---------------- W1 GEMM: 64x32 tiles, SPLIT X = [x | ln1] ----------------
__global__ void __launch_bounds__(128) gemm_w1(
    const float* __restrict__ X, const float* __restrict__ X2,
    const float* __restrict__ W, float* __restrict__ Y) {
    __shared__ float XsT[16][68];
    __shared__ float BsT[16][36];
    const int bm = blockIdx.y * 64, bn = blockIdx.x * 32;
    const int t = threadIdx.x, tx = t & 7, ty = t >> 3;
    const int NTk = 512 >> 4;

    float4 xr[2], wr;
    #define LOAD_XW1(kc_) do { \
        int kc = (kc_); \
        _Pragma("unroll") \
        for (int i = 0; i < 2; i++) { \
            int idx = t + 128 * i; int r = idx >> 2; int c = (idx & 3) * 4 + kc; \
            xr[i] = (c < 256) ? *(const float4*)(X + (size_t)(bm + r) * 256 + c) \
                              : *(const float4*)(X2 + (size_t)(bm + r) * 256 + (c - 256)); \
        } \
        { int r = t >> 2; int c = (t & 3) * 4 + kc; \
          wr = *(const float4*)(W + (size_t)(bn + r) * 512 + c); } \
    } while (0)

    LOAD_XW1(0);

    ull acc[4][2]; ull zero; PACK2(zero, 0.0f, 0.0f);
    #pragma unroll
    for (int m = 0; m < 4; m++) { acc[m][0] = zero; acc[m][1] = zero; }

    for (int kt = 0; kt < NTk; kt++) {
        __syncthreads();
        #pragma unroll
        for (int i = 0; i < 2; i++) {
            int idx = t + 128 * i; int r = idx >> 2; int c = (idx & 3) * 4;
            XsT[c + 0][r] = xr[i].x; XsT[c + 1][r] = xr[i].y;
            XsT[c + 2][r] = xr[i].z; XsT[c + 3][r] = xr[i].w;
        }
        {
            int r = t >> 2; int c = (t & 3) * 4;
            BsT[c + 0][r] = wr.x; BsT[c + 1][r] = wr.y;
            BsT[c + 2][r] = wr.z; BsT[c + 3][r] = wr.w;
        }
        if (kt + 1 < NTk) LOAD_XW1((kt + 1) * 16);
        __syncthreads();
        #pragma unroll
        for (int kk = 0; kk < 16; kk++) {
            float4 a4 = *(const float4*)&XsT[kk][ty * 4];
            ulonglong2 b01 = *(const ulonglong2*)&BsT[kk][tx * 4];
            ull am;
            PACK2(am, a4.x, a4.x);
            FMA2(acc[0][0], am, b01.x, acc[0][0]); FMA2(acc[0][1], am, b01.y, acc[0][1]);
            PACK2(am, a4.y, a4.y);
            FMA2(acc[1][0], am, b01.x, acc[1][0]); FMA2(acc[1][1], am, b01.y, acc[1][1]);
            PACK2(am, a4.z, a4.z);
            FMA2(acc[2][0], am, b01.x, acc[2][0]); FMA2(acc[2][1], am, b01.y, acc[2][1]);
            PACK2(am, a4.w, a4.w);
            FMA2(acc[3][0], am, b01.x, acc[3][0]); FMA2(acc[3][1], am, b01.y, acc[3][1]);
        }
    }
    #undef LOAD_XW1

    #pragma unroll
    for (int r = 0; r < 4; r++) {
        float v0, v1, v2, v3;
        UNPACK2(v0, v1, acc[r][0]);
        UNPACK2(v2, v3, acc[r][1]);
        float4 w0;
        w0.x = fmaxf(v0, 0.0f); w0.y = fmaxf(v1, 0.0f);
        w0.z = fmaxf(v2, 0.0f); w0.w = fmaxf(v3, 0.0f);
        *(float4*)(Y + (size_t)(bm + ty * 4 + r) * 512 + bn + tx * 4) = w0;
    }
}

// ---------------- attn5: tf32 mma.sync flash attention ----------------
// Block: 256 thr = 8 warps (warp = head), 16 l-rows/block. Grid (L/16, SPLITS, B).
// smem bytes: K 2*16*260*4=33280 | V 2*16*264*4=33792 | Af 2*16*18*4=2304 |
//             P 8*16*20*4=10240  -> total 79616.
#define ATTN_SMEM 79616

#define ISSUE_KV(t_, buf_) do { \
    const float* ksrc_ = Kb + (size_t)(sbase + (t_) * 16) * D_; \
    const float* vsrc_ = Vb + (size_t)(sbase + (t_) * 16) * D_; \
    u32 kd_ = kbase + (u32)(buf_) * 16640; \
    u32 vd_ = vbase + (u32)(buf_) * 16896; \
    _Pragma("unroll") \
    for (int i_ = 0; i_ < 4; i_++) { \
        int idx_ = tid + 256 * i_; int s_ = idx_ >> 6; int c_ = (idx_ & 63) * 4; \
        asm volatile("cp.async.cg.shared.global [%0], [%1], 16;" :: \
            "r"(kd_ + (u32)(s_ * 1040 + c_ * 4)), "l"(ksrc_ + s_ * 256 + c_)); \
        asm volatile("cp.async.cg.shared.global [%0], [%1], 16;" :: \
            "r"(vd_ + (u32)(s_ * 1056 + c_ * 4)), "l"(vsrc_ + s_ * 256 + c_)); \
    } \
    asm volatile("cp.async.commit_group;"); \
} while (0)

#define LOAD_AF(t_)  do { afr = afb[(size_t)(tid >> 4) * S_ + (t_) * 16 + (tid & 15)]; } while (0)
#define STORE_AF(buf_) do { Afs[(buf_) * 288 + (tid >> 4) * 18 + (tid & 15)] = afr; } while (0)

__global__ void __launch_bounds__(256, 2) attn5(
    const float* __restrict__ Qg, const float* __restrict__ Kg,
    const float* __restrict__ Vg, const float* __restrict__ af,
    float* __restrict__ Op, float* __restrict__ SSp) {
    extern __shared__ float sm[];
    float* Ksm = sm;                  // buf stride 4160 floats (row pad 260)
    float* Vsm = sm + 8320;           // buf stride 4224 floats (row pad 264)
    float* Afs = sm + 16768;          // buf stride 288 floats (row pad 18)

    const int b = blockIdx.z, sp = blockIdx.y;
    const int l0 = blockIdx.x * 16;
    const int tid = threadIdx.x;
    const int w = tid >> 5, lane = tid & 31;
    const int g = lane >> 2, t = lane & 3;
    float* Pw = sm + 17344 + w * 320; // per-warp 16x20

    const int sbase = sp * SHALF;
    const float* Kb  = Kg + (size_t)b * S_ * D_;
    const float* Vb  = Vg + (size_t)b * S_ * D_;
    const float* afb = af + ((size_t)b * L_ + l0) * S_ + sbase;
    const u32 smb = (u32)__cvta_generic_to_shared(sm);
    const u32 kbase = smb;
    const u32 vbase = smb + 33280;

    // Q fragments (16x32 per head), pre-scaled by log2e/sqrt(32), tf32-rounded
    u32 qf[4][4];
    {
        const float QS = 0.25503486f;
        const float* qb = Qg + (size_t)b * L_ * D_;
        #pragma unroll
        for (int kt = 0; kt < 4; kt++) {
            int d0 = w * 32 + kt * 8 + t;
            qf[kt][0] = tf32r(qb[(size_t)(l0 + g) * 256 + d0] * QS);
            qf[kt][1] = tf32r(qb[(size_t)(l0 + g + 8) * 256 + d0] * QS);
            qf[kt][2] = tf32r(qb[(size_t)(l0 + g) * 256 + d0 + 4] * QS);
            qf[kt][3] = tf32r(qb[(size_t)(l0 + g + 8) * 256 + d0 + 4] * QS);
        }
    }

    float oa[4][4];
    #pragma unroll
    for (int dn = 0; dn < 4; dn++)
        #pragma unroll
        for (int c = 0; c < 4; c++) oa[dn][c] = 0.0f;
    float ssum0 = 0.0f, ssum1 = 0.0f;
    float afr;

    ISSUE_KV(0, 0);
    LOAD_AF(0);
    ISSUE_KV(1, 1);
    STORE_AF(0);
    LOAD_AF(1);

    for (int st = 0; st < NT; st++) {
        const int buf = st & 1;
        if (st + 1 < NT) asm volatile("cp.async.wait_group 1;");
        else             asm volatile("cp.async.wait_group 0;");
        __syncthreads();
        if (st + 1 < NT) STORE_AF(buf ^ 1);
        if (st + 2 < NT) LOAD_AF(st + 2);

        const float* ks  = Ksm + buf * 4160 + w * 32;   // head slab (THE FIX)
        const float* vs  = Vsm + buf * 4224;
        const float* afl = Afs + buf * 288;

        // ---- QK: scores 16l x 16s ----
        float sc[2][4];
        #pragma unroll
        for (int nt = 0; nt < 2; nt++)
            #pragma unroll
            for (int c = 0; c < 4; c++) sc[nt][c] = 0.0f;
        #pragma unroll
        for (int kt = 0; kt < 4; kt++) {
            u32 bk0[2], bk1[2];
            bk0[0] = __float_as_uint(ks[(size_t)g * 260 + kt * 8 + t]);
            bk0[1] = __float_as_uint(ks[(size_t)g * 260 + kt * 8 + t + 4]);
            bk1[0] = __float_as_uint(ks[(size_t)(g + 8) * 260 + kt * 8 + t]);
            bk1[1] = __float_as_uint(ks[(size_t)(g + 8) * 260 + kt * 8 + t + 4]);
            MMA_TF32(sc[0], qf[kt], bk0);
            MMA_TF32(sc[1], qf[kt], bk1);
        }

        // ---- softmax epilogue ----
        u32 pv[2][4];
        float rs0 = 0.0f, rs1 = 0.0f;
        #pragma unroll
        for (int nt = 0; nt < 2; nt++) {
            float2 afA = *(const float2*)&afl[g * 18 + nt * 8 + 2 * t];
            float2 afB = *(const float2*)&afl[(g + 8) * 18 + nt * 8 + 2 * t];
            float p0 = ex2f(sc[nt][0] * afA.x);
            float p1 = ex2f(sc[nt][1] * afA.y);
            float p2 = ex2f(sc[nt][2] * afB.x);
            float p3 = ex2f(sc[nt][3] * afB.y);
            pv[nt][0] = tf32r(p0); pv[nt][1] = tf32r(p1);
            pv[nt][2] = tf32r(p2); pv[nt][3] = tf32r(p3);
            rs0 += __uint_as_float(pv[nt][0]) + __uint_as_float(pv[nt][1]);
            rs1 += __uint_as_float(pv[nt][2]) + __uint_as_float(pv[nt][3]);
        }
        rs0 += __shfl_xor_sync(0xffffffffu, rs0, 1);
        rs0 += __shfl_xor_sync(0xffffffffu, rs0, 2);
        rs1 += __shfl_xor_sync(0xffffffffu, rs1, 1);
        rs1 += __shfl_xor_sync(0xffffffffu, rs1, 2);
        ssum0 += rs0; ssum1 += rs1;

        // ---- P -> smem (C layout), reload as A fragments ----
        #pragma unroll
        for (int nt = 0; nt < 2; nt++) {
            float2 v0; v0.x = __uint_as_float(pv[nt][0]); v0.y = __uint_as_float(pv[nt][1]);
            float2 v1; v1.x = __uint_as_float(pv[nt][2]); v1.y = __uint_as_float(pv[nt][3]);
            *(float2*)&Pw[g * 20 + nt * 8 + 2 * t] = v0;
            *(float2*)&Pw[(g + 8) * 20 + nt * 8 + 2 * t] = v1;
        }
        __syncwarp();
        u32 pa[2][4];
        #pragma unroll
        for (int ksx = 0; ksx < 2; ksx++) {
            pa[ksx][0] = __float_as_uint(Pw[g * 20 + ksx * 8 + t]);
            pa[ksx][1] = __float_as_uint(Pw[(g + 8) * 20 + ksx * 8 + t]);
            pa[ksx][2] = __float_as_uint(Pw[g * 20 + ksx * 8 + t + 4]);
            pa[ksx][3] = __float_as_uint(Pw[(g + 8) * 20 + ksx * 8 + t + 4]);
        }

        // ---- AV: O += P @ V ----
        #pragma unroll
        for (int dn = 0; dn < 4; dn++) {
            u32 bv0[2], bv1[2];
            int dcol = w * 32 + dn * 8 + g;  // V smem holds full 256 dims
            bv0[0] = __float_as_uint(vs[(size_t)t * 264 + dcol]);
            bv0[1] = __float_as_uint(vs[(size_t)(t + 4) * 264 + dcol]);
            bv1[0] = __float_as_uint(vs[(size_t)(8 + t) * 264 + dcol]);
            bv1[1] = __float_as_uint(vs[(size_t)(8 + t + 4) * 264 + dcol]);
            MMA_TF32(oa[dn], pa[0], bv0);
            MMA_TF32(oa[dn], pa[1], bv1);
        }
        __syncthreads();
        if (st + 2 < NT) ISSUE_KV(st + 2, buf);
    }

    // write raw partials + sums (combine fused into Wm GEMM)
    {
        float* opg  = Op + (((size_t)sp * B_ + b) * L_ + l0 + g) * 256 + w * 32;
        float* opg8 = opg + 8 * 256;
        #pragma unroll
        for (int dn = 0; dn < 4; dn++) {
            float2 v0; v0.x = oa[dn][0]; v0.y = oa[dn][1];
            float2 v1; v1.x = oa[dn][2]; v1.y = oa[dn][3];
            *(float2*)(opg + dn * 8 + 2 * t) = v0;
            *(float2*)(opg8 + dn * 8 + 2 * t) = v1;
        }
        if (t == 0) {
            size_t ssb = (((size_t)sp * B_ + b) * H_ + w) * L_ + l0;
            SSp[ssb + g] = ssum0;
            SSp[ssb + g + 8] = ssum1;
        }
    }
}

// ---------------- LayerNorm over D=256, NIN summed inputs ----------------
template <bool RESID, int NIN>
__global__ void ln_kernel(const float* __restrict__ in0, const float* __restrict__ in1,
                          const float* __restrict__ in2, const float* __restrict__ in3,
                          const float* __restrict__ g, const float* __restrict__ bt,
                          const float* __restrict__ resid, float* __restrict__ out) {
    const size_t row = blockIdx.x;
    const int tid = threadIdx.x;
    const int lane = tid & 31, wid = tid >> 5;
    float x = in0[row * D_ + tid];
    if (NIN > 1) x += in1[row * D_ + tid];
    if (NIN > 2) x += in2[row * D_ + tid];
    if (NIN > 3) x += in3[row * D_ + tid];
    __shared__ float ws[8];

    float v = x;
    #pragma unroll
    for (int off = 16; off > 0; off >>= 1) v += __shfl_xor_sync(0xffffffffu, v, off);
    if (lane == 0) ws[wid] = v;
    __syncthreads();
    float mean = 0.0f;
    #pragma unroll
    for (int i = 0; i < 8; i++) mean += ws[i];
    mean *= (1.0f / D_);
    __syncthreads();

    const float d = x - mean;
    v = d * d;
    #pragma unroll
    for (int off = 16; off > 0; off >>= 1) v += __shfl_xor_sync(0xffffffffu, v, off);
    if (lane == 0) ws[wid] = v;
    __syncthreads();
    float var = 0.0f;
    #pragma unroll
    for (int i = 0; i < 8; i++) var += ws[i];
    var *= (1.0f / D_);

    float y = d * rsqrtf(var + 1e-5f) * g[tid] + bt[tid];
    if (RESID) y += resid[row * D_ + tid];
    out[row * D_ + tid] = y;
}

// ---------------- launch ----------------
extern "C" void kernel_launch(void* const* d_in, const int* in_sizes, int n_in,
                              void* d_out, int out_size) {
    const float* x   = (const float*)d_in[0];
    const float* src = (const float*)d_in[1];
    const float* af  = (const float*)d_in[2];
    const float* Wq  = (const float*)d_in[3];
    const float* Wk  = (const float*)d_in[4];
    const float* Wv  = (const float*)d_in[5];
    const float* Wm  = (const float*)d_in[6];
    const float* W1  = (const float*)d_in[7];
    const float* W2  = (const float*)d_in[8];
    const float* g1  = (const float*)d_in[9];
    const float* b1  = (const float*)d_in[10];
    const float* g2  = (const float*)d_in[11];
    const float* b2  = (const float*)d_in[12];
    float* out = (float*)d_out;

    float *Q, *K, *V, *OP, *SS, *O, *M, *HB, *T;
    cudaGetSymbolAddress((void**)&Q,  g_Q);
    cudaGetSymbolAddress((void**)&K,  g_K);
    cudaGetSymbolAddress((void**)&V,  g_V);
    cudaGetSymbolAddress((void**)&OP, g_OP);
    cudaGetSymbolAddress((void**)&SS, g_SS);
    cudaGetSymbolAddress((void**)&O,  g_O);
    cudaGetSymbolAddress((void**)&M,  g_M);
    cudaGetSymbolAddress((void**)&HB, g_HB);
    cudaGetSymbolAddress((void**)&T,  g_T);

    cudaFuncSetAttribute(attn5, cudaFuncAttributeMaxDynamicSharedMemorySize, ATTN_SMEM);

    const int ML = B_ * L_;  // 4096
    float* OP1 = OP + (size_t)B_ * L_ * D_;

    // projections (one launch, grid.z selects Q/K/V; K,V tf32-rounded)
    gemm_qkv<<<dim3(4, ML / 64, 3), 128>>>(x, src, Wq, Wk, Wv, Q, K, V);

    // attention (tf32 mma) -> raw partials OP + sums SS
    attn5<<<dim3(L_ / 16, SPLITS, B_), 256, ATTN_SMEM>>>(Q, K, V, af, OP, SS);

    // Wm with fused combine, split-K=2 (partials M,T) + LN1 (sums) -> O
    gemm_wm_combine<<<dim3(4, ML / 64, 2), 128>>>(OP, OP1, SS, Wm, M, T);
    ln_kernel<false, 2><<<ML, 256>>>(M, T, nullptr, nullptr, g1, b1, nullptr, O);

    // MLP: h = relu([x, LN1] @ W1^T)
    gemm_w1<<<dim3(16, ML / 64), 128>>>(x, O, W1, HB);
    // W2 split-K=4 (partials M,T,Q,K — Q/K free after attention)
    gemm_w2_splitk<<<dim3(4, ML / 64, 4), 128>>>(HB, W2, M, T, Q, K);

    // LN2 (sums 4 partials) + residual -> out
    ln_kernel<true, 4><<<ML, 256>>>(M, T, Q, K, g2, b2, x, out);
}

// round 14
// speedup vs baseline: 2.4840x; 1.4273x over previous
#include <cuda_runtime.h>
#include <math.h>

typedef unsigned long long ull;
typedef unsigned int u32;

#define B_  2
#define L_  2048
#define S_  2048
#define D_  256
#define H_  8
#define SPLITS 2
#define SHALF (S_ / SPLITS)      // 1024
#define NT (SHALF / 16)          // 64 s-tiles of 16

__device__ __forceinline__ float ex2f(float x) {
    float r;
    asm("ex2.approx.ftz.f32 %0, %1;" : "=f"(r) : "f"(x));
    return r;
}
__device__ __forceinline__ u32 tf32r(float x) {
    u32 r;
    asm("cvt.rna.tf32.f32 %0, %1;" : "=r"(r) : "f"(x));
    return r;
}

// mma.sync m16n8k8 tf32: D += A*B (C==D registers)
#define MMA_TF32(d, a, b) \
    asm volatile("mma.sync.aligned.m16n8k8.row.col.f32.tf32.tf32.f32 " \
        "{%0,%1,%2,%3},{%4,%5,%6,%7},{%8,%9},{%0,%1,%2,%3};" \
        : "+f"((d)[0]), "+f"((d)[1]), "+f"((d)[2]), "+f"((d)[3]) \
        : "r"((a)[0]), "r"((a)[1]), "r"((a)[2]), "r"((a)[3]), \
          "r"((b)[0]), "r"((b)[1]));

// ---------------- scratch ----------------
__device__ float g_Q[(size_t)B_ * L_ * D_];
__device__ float g_K[(size_t)B_ * S_ * D_];
__device__ float g_V[(size_t)B_ * S_ * D_];
__device__ float g_OP[(size_t)SPLITS * B_ * L_ * D_];
__device__ float g_SS[(size_t)SPLITS * B_ * H_ * L_];
__device__ float g_O[(size_t)B_ * L_ * D_];
__device__ float g_M[(size_t)B_ * L_ * D_];
__device__ float g_HB[(size_t)B_ * L_ * 2 * D_];
__device__ float g_T[(size_t)B_ * L_ * D_];

// ---------------- tf32 mma GEMM: Y[M,N] = X[M,K] @ W[N,K]^T ----------------
// 256 threads = 8 warps (4m x 2n), tile 64x64, warp = 16m x 32n.
// MODE 0: plain (ldx), MODE 1: X = [X|X2] along K (each 256 wide),
// MODE 2: combine loader — X = (OP0+OP1)*inv(SS0+SS1), kz = abs k offset.
// Operands tf32-rounded at smem staging. CVT: tf32-round outputs too (K/V).
template <bool RELU, int MODE, bool CVT>
__device__ __forceinline__ void mgemm_body(
    const float* __restrict__ X, const float* __restrict__ X2,
    const float* __restrict__ SSp,
    const float* __restrict__ W, float* __restrict__ Y,
    int N, int K, int ldx, int ldw, int bm, int bn, int kz) {
    __shared__ float Xs[64][20];   // [row][k], pad 20 (conflict-free g*20+t)
    __shared__ float Ws[64][20];   // [n][k]
    const int tid = threadIdx.x;
    const int wid = tid >> 5, lane = tid & 31;
    const int wm = wid >> 1, wn = wid & 1;
    const int g = lane >> 2, t = lane & 3;
    const int r = tid >> 2, c4 = (tid & 3) * 4;   // staging coords
    const int NTk = K >> 4;

    float4 xr, wr;
    #define MLOAD(kc_) do { \
        int c = c4 + (kc_); \
        if (MODE == 1) { \
            xr = (c < 256) ? *(const float4*)(X + (size_t)(bm + r) * 256 + c) \
                           : *(const float4*)(X2 + (size_t)(bm + r) * 256 + (c - 256)); \
        } else if (MODE == 2) { \
            size_t row = bm + r; \
            int kabs = kz + c; \
            size_t e = row * 256 + kabs; \
            float4 a = *(const float4*)(X + e); \
            float4 c2 = *(const float4*)(X2 + e); \
            size_t bb = row >> 11; size_t l = row & 2047; \
            int h = kabs >> 5; \
            float s = SSp[(bb * H_ + h) * L_ + l] \
                    + SSp[(size_t)B_ * H_ * L_ + (bb * H_ + h) * L_ + l]; \
            float inv = 1.0f / s; \
            xr.x = (a.x + c2.x) * inv; xr.y = (a.y + c2.y) * inv; \
            xr.z = (a.z + c2.z) * inv; xr.w = (a.w + c2.w) * inv; \
        } else { \
            xr = *(const float4*)(X + (size_t)(bm + r) * ldx + c); \
        } \
        wr = *(const float4*)(W + (size_t)(bn + r) * ldw + c); \
    } while (0)

    MLOAD(0);

    float ca[4][4];
    #pragma unroll
    for (int ns = 0; ns < 4; ns++)
        #pragma unroll
        for (int i = 0; i < 4; i++) ca[ns][i] = 0.0f;

    for (int kt = 0; kt < NTk; kt++) {
        __syncthreads();
        {
            float4 xv = xr, wv = wr;
            xv.x = __uint_as_float(tf32r(xv.x)); xv.y = __uint_as_float(tf32r(xv.y));
            xv.z = __uint_as_float(tf32r(xv.z)); xv.w = __uint_as_float(tf32r(xv.w));
            wv.x = __uint_as_float(tf32r(wv.x)); wv.y = __uint_as_float(tf32r(wv.y));
            wv.z = __uint_as_float(tf32r(wv.z)); wv.w = __uint_as_float(tf32r(wv.w));
            *(float4*)&Xs[r][c4] = xv;
            *(float4*)&Ws[r][c4] = wv;
        }
        if (kt + 1 < NTk) MLOAD((kt + 1) * 16);
        __syncthreads();
        #pragma unroll
        for (int ks = 0; ks < 2; ks++) {
            u32 a[4];
            a[0] = __float_as_uint(Xs[wm * 16 + g][ks * 8 + t]);
            a[1] = __float_as_uint(Xs[wm * 16 + g + 8][ks * 8 + t]);
            a[2] = __float_as_uint(Xs[wm * 16 + g][ks * 8 + t + 4]);
            a[3] = __float_as_uint(Xs[wm * 16 + g + 8][ks * 8 + t + 4]);
            #pragma unroll
            for (int ns = 0; ns < 4; ns++) {
                u32 bf[2];
                bf[0] = __float_as_uint(Ws[wn * 32 + ns * 8 + g][ks * 8 + t]);
                bf[1] = __float_as_uint(Ws[wn * 32 + ns * 8 + g][ks * 8 + t + 4]);
                MMA_TF32(ca[ns], a, bf);
            }
        }
    }
    #undef MLOAD

    #pragma unroll
    for (int ns = 0; ns < 4; ns++) {
        float v0 = ca[ns][0], v1 = ca[ns][1], v2 = ca[ns][2], v3 = ca[ns][3];
        if (RELU) {
            v0 = fmaxf(v0, 0.0f); v1 = fmaxf(v1, 0.0f);
            v2 = fmaxf(v2, 0.0f); v3 = fmaxf(v3, 0.0f);
        }
        if (CVT) {
            v0 = __uint_as_float(tf32r(v0)); v1 = __uint_as_float(tf32r(v1));
            v2 = __uint_as_float(tf32r(v2)); v3 = __uint_as_float(tf32r(v3));
        }
        int col = bn + wn * 32 + ns * 8 + 2 * t;
        float2 p0; p0.x = v0; p0.y = v1;
        float2 p1; p1.x = v2; p1.y = v3;
        *(float2*)(Y + (size_t)(bm + wm * 16 + g) * N + col) = p0;
        *(float2*)(Y + (size_t)(bm + wm * 16 + g + 8) * N + col) = p1;
    }
}

// fused QKV projections; K,V get tf32-rounded outputs for the mma attention
__global__ void __launch_bounds__(256) gemm_qkv(
    const float* __restrict__ x, const float* __restrict__ src,
    const float* __restrict__ Wq, const float* __restrict__ Wk,
    const float* __restrict__ Wv,
    float* __restrict__ Q, float* __restrict__ K, float* __restrict__ V) {
    const int z = blockIdx.z;
    if (z == 0) {
        mgemm_body<false, 0, false>(x, nullptr, nullptr, Wq, Q, 256, 256, 256, 256,
                                    blockIdx.y * 64, blockIdx.x * 64, 0);
    } else {
        const float* W = (z == 1) ? Wk : Wv;
        float* Y = (z == 1) ? K : V;
        mgemm_body<false, 0, true>(src, nullptr, nullptr, W, Y, 256, 256, 256, 256,
                                   blockIdx.y * 64, blockIdx.x * 64, 0);
    }
}

// Wm with fused attention-combine, split-K=2
__global__ void __launch_bounds__(256) gemm_wm_combine(
    const float* __restrict__ OP0, const float* __restrict__ OP1,
    const float* __restrict__ SSp, const float* __restrict__ Wm,
    float* __restrict__ Y0, float* __restrict__ Y1) {
    const int z = blockIdx.z;
    const int kz = z * 128;
    mgemm_body<false, 2, false>(OP0, OP1, SSp, Wm + kz, z ? Y1 : Y0,
                                256, 128, 256, 256, blockIdx.y * 64, blockIdx.x * 64, kz);
}

// W2 split-K=4
__global__ void __launch_bounds__(256) gemm_w2_splitk(
    const float* __restrict__ X, const float* __restrict__ W,
    float* __restrict__ Y0, float* __restrict__ Y1,
    float* __restrict__ Y2, float* __restrict__ Y3) {
    const int z = blockIdx.z;
    float* Y = (z == 0) ? Y0 : (z == 1) ? Y1 : (z == 2) ? Y2 : Y3;
    mgemm_body<false, 0, false>(X + z * 128, nullptr, nullptr, W + z * 128, Y,
                                256, 128, 512, 512, blockIdx.y * 64, blockIdx.x * 64, 0);
}

// W1: relu([x | ln1] @ W1^T), MODE 1 split-X, N=512 K=512
__global__ void __launch_bounds__(256) gemm_w1(
    const float* __restrict__ X, const float* __restrict__ X2,
    const float* __restrict__ W, float* __restrict__ Y) {
    mgemm_body<true, 1, false>(X, X2, nullptr, W, Y, 512, 512, 256, 512,
                               blockIdx.y * 64, blockIdx.x * 64, 0);
}

// ---------------- attn5: tf32 mma.sync flash attention (R12-verbatim) ----------------
// Block: 256 thr = 8 warps (warp = head), 16 l-rows/block. Grid (L/16, SPLITS, B).
#define ATTN_SMEM 79616

#define ISSUE_KV(t_, buf_) do { \
    const float* ksrc_ = Kb + (size_t)(sbase + (t_) * 16) * D_; \
    const float* vsrc_ = Vb + (size_t)(sbase + (t_) * 16) * D_; \
    u32 kd_ = kbase + (u32)(buf_) * 16640; \
    u32 vd_ = vbase + (u32)(buf_) * 16896; \
    _Pragma("unroll") \
    for (int i_ = 0; i_ < 4; i_++) { \
        int idx_ = tid + 256 * i_; int s_ = idx_ >> 6; int c_ = (idx_ & 63) * 4; \
        asm volatile("cp.async.cg.shared.global [%0], [%1], 16;" :: \
            "r"(kd_ + (u32)(s_ * 1040 + c_ * 4)), "l"(ksrc_ + s_ * 256 + c_)); \
        asm volatile("cp.async.cg.shared.global [%0], [%1], 16;" :: \
            "r"(vd_ + (u32)(s_ * 1056 + c_ * 4)), "l"(vsrc_ + s_ * 256 + c_)); \
    } \
    asm volatile("cp.async.commit_group;"); \
} while (0)

#define LOAD_AF(t_)  do { afr = afb[(size_t)(tid >> 4) * S_ + (t_) * 16 + (tid & 15)]; } while (0)
#define STORE_AF(buf_) do { Afs[(buf_) * 288 + (tid >> 4) * 18 + (tid & 15)] = afr; } while (0)

__global__ void __launch_bounds__(256, 2) attn5(
    const float* __restrict__ Qg, const float* __restrict__ Kg,
    const float* __restrict__ Vg, const float* __restrict__ af,
    float* __restrict__ Op, float* __restrict__ SSp) {
    extern __shared__ float sm[];
    float* Ksm = sm;                  // buf stride 4160 floats (row pad 260)
    float* Vsm = sm + 8320;           // buf stride 4224 floats (row pad 264)
    float* Afs = sm + 16768;          // buf stride 288 floats (row pad 18)

    const int b = blockIdx.z, sp = blockIdx.y;
    const int l0 = blockIdx.x * 16;
    const int tid = threadIdx.x;
    const int w = tid >> 5, lane = tid & 31;
    const int g = lane >> 2, t = lane & 3;
    float* Pw = sm + 17344 + w * 320; // per-warp 16x20

    const int sbase = sp * SHALF;
    const float* Kb  = Kg + (size_t)b * S_ * D_;
    const float* Vb  = Vg + (size_t)b * S_ * D_;
    const float* afb = af + ((size_t)b * L_ + l0) * S_ + sbase;
    const u32 smb = (u32)__cvta_generic_to_shared(sm);
    const u32 kbase = smb;
    const u32 vbase = smb + 33280;

    // Q fragments (16x32 per head), pre-scaled by log2e/sqrt(32), tf32-rounded
    u32 qf[4][4];
    {
        const float QS = 0.25503486f;
        const float* qb = Qg + (size_t)b * L_ * D_;
        #pragma unroll
        for (int kt = 0; kt < 4; kt++) {
            int d0 = w * 32 + kt * 8 + t;
            qf[kt][0] = tf32r(qb[(size_t)(l0 + g) * 256 + d0] * QS);
            qf[kt][1] = tf32r(qb[(size_t)(l0 + g + 8) * 256 + d0] * QS);
            qf[kt][2] = tf32r(qb[(size_t)(l0 + g) * 256 + d0 + 4] * QS);
            qf[kt][3] = tf32r(qb[(size_t)(l0 + g + 8) * 256 + d0 + 4] * QS);
        }
    }

    float oa[4][4];
    #pragma unroll
    for (int dn = 0; dn < 4; dn++)
        #pragma unroll
        for (int c = 0; c < 4; c++) oa[dn][c] = 0.0f;
    float ssum0 = 0.0f, ssum1 = 0.0f;
    float afr;

    ISSUE_KV(0, 0);
    LOAD_AF(0);
    ISSUE_KV(1, 1);
    STORE_AF(0);
    LOAD_AF(1);

    for (int st = 0; st < NT; st++) {
        const int buf = st & 1;
        if (st + 1 < NT) asm volatile("cp.async.wait_group 1;");
        else             asm volatile("cp.async.wait_group 0;");
        __syncthreads();
        if (st + 1 < NT) STORE_AF(buf ^ 1);
        if (st + 2 < NT) LOAD_AF(st + 2);

        const float* ks  = Ksm + buf * 4160 + w * 32;   // head slab
        const float* vs  = Vsm + buf * 4224;
        const float* afl = Afs + buf * 288;

        // ---- QK: scores 16l x 16s ----
        float sc[2][4];
        #pragma unroll
        for (int nt = 0; nt < 2; nt++)
            #pragma unroll
            for (int c = 0; c < 4; c++) sc[nt][c] = 0.0f;
        #pragma unroll
        for (int kt = 0; kt < 4; kt++) {
            u32 bk0[2], bk1[2];
            bk0[0] = __float_as_uint(ks[(size_t)g * 260 + kt * 8 + t]);
            bk0[1] = __float_as_uint(ks[(size_t)g * 260 + kt * 8 + t + 4]);
            bk1[0] = __float_as_uint(ks[(size_t)(g + 8) * 260 + kt * 8 + t]);
            bk1[1] = __float_as_uint(ks[(size_t)(g + 8) * 260 + kt * 8 + t + 4]);
            MMA_TF32(sc[0], qf[kt], bk0);
            MMA_TF32(sc[1], qf[kt], bk1);
        }

        // ---- softmax epilogue ----
        u32 pv[2][4];
        float rs0 = 0.0f, rs1 = 0.0f;
        #pragma unroll
        for (int nt = 0; nt < 2; nt++) {
            float2 afA = *(const float2*)&afl[g * 18 + nt * 8 + 2 * t];
            float2 afB = *(const float2*)&afl[(g + 8) * 18 + nt * 8 + 2 * t];
            float p0 = ex2f(sc[nt][0] * afA.x);
            float p1 = ex2f(sc[nt][1] * afA.y);
            float p2 = ex2f(sc[nt][2] * afB.x);
            float p3 = ex2f(sc[nt][3] * afB.y);
            pv[nt][0] = tf32r(p0); pv[nt][1] = tf32r(p1);
            pv[nt][2] = tf32r(p2); pv[nt][3] = tf32r(p3);
            rs0 += __uint_as_float(pv[nt][0]) + __uint_as_float(pv[nt][1]);
            rs1 += __uint_as_float(pv[nt][2]) + __uint_as_float(pv[nt][3]);
        }
        rs0 += __shfl_xor_sync(0xffffffffu, rs0, 1);
        rs0 += __shfl_xor_sync(0xffffffffu, rs0, 2);
        rs1 += __shfl_xor_sync(0xffffffffu, rs1, 1);
        rs1 += __shfl_xor_sync(0xffffffffu, rs1, 2);
        ssum0 += rs0; ssum1 += rs1;

        // ---- P -> smem (C layout), reload as A fragments ----
        #pragma unroll
        for (int nt = 0; nt < 2; nt++) {
            float2 v0; v0.x = __uint_as_float(pv[nt][0]); v0.y = __uint_as_float(pv[nt][1]);
            float2 v1; v1.x = __uint_as_float(pv[nt][2]); v1.y = __uint_as_float(pv[nt][3]);
            *(float2*)&Pw[g * 20 + nt * 8 + 2 * t] = v0;
            *(float2*)&Pw[(g + 8) * 20 + nt * 8 + 2 * t] = v1;
        }
        __syncwarp();
        u32 pa[2][4];
        #pragma unroll
        for (int ksx = 0; ksx < 2; ksx++) {
            pa[ksx][0] = __float_as_uint(Pw[g * 20 + ksx * 8 + t]);
            pa[ksx][1] = __float_as_uint(Pw[(g + 8) * 20 + ksx * 8 + t]);
            pa[ksx][2] = __float_as_uint(Pw[g * 20 + ksx * 8 + t + 4]);
            pa[ksx][3] = __float_as_uint(Pw[(g + 8) * 20 + ksx * 8 + t + 4]);
        }

        // ---- AV: O += P @ V ----
        #pragma unroll
        for (int dn = 0; dn < 4; dn++) {
            u32 bv0[2], bv1[2];
            int dcol = w * 32 + dn * 8 + g;
            bv0[0] = __float_as_uint(vs[(size_t)t * 264 + dcol]);
            bv0[1] = __float_as_uint(vs[(size_t)(t + 4) * 264 + dcol]);
            bv1[0] = __float_as_uint(vs[(size_t)(8 + t) * 264 + dcol]);
            bv1[1] = __float_as_uint(vs[(size_t)(8 + t + 4) * 264 + dcol]);
            MMA_TF32(oa[dn], pa[0], bv0);
            MMA_TF32(oa[dn], pa[1], bv1);
        }
        __syncthreads();
        if (st + 2 < NT) ISSUE_KV(st + 2, buf);
    }

    // write raw partials + sums (combine fused into Wm GEMM)
    {
        float* opg  = Op + (((size_t)sp * B_ + b) * L_ + l0 + g) * 256 + w * 32;
        float* opg8 = opg + 8 * 256;
        #pragma unroll
        for (int dn = 0; dn < 4; dn++) {
            float2 v0; v0.x = oa[dn][0]; v0.y = oa[dn][1];
            float2 v1; v1.x = oa[dn][2]; v1.y = oa[dn][3];
            *(float2*)(opg + dn * 8 + 2 * t) = v0;
            *(float2*)(opg8 + dn * 8 + 2 * t) = v1;
        }
        if (t == 0) {
            size_t ssb = (((size_t)sp * B_ + b) * H_ + w) * L_ + l0;
            SSp[ssb + g] = ssum0;
            SSp[ssb + g + 8] = ssum1;
        }
    }
}

// ---------------- LayerNorm over D=256, NIN summed inputs ----------------
template <bool RESID, int NIN>
__global__ void ln_kernel(const float* __restrict__ in0, const float* __restrict__ in1,
                          const float* __restrict__ in2, const float* __restrict__ in3,
                          const float* __restrict__ g, const float* __restrict__ bt,
                          const float* __restrict__ resid, float* __restrict__ out) {
    const size_t row = blockIdx.x;
    const int tid = threadIdx.x;
    const int lane = tid & 31, wid = tid >> 5;
    float x = in0[row * D_ + tid];
    if (NIN > 1) x += in1[row * D_ + tid];
    if (NIN > 2) x += in2[row * D_ + tid];
    if (NIN > 3) x += in3[row * D_ + tid];
    __shared__ float ws[8];

    float v = x;
    #pragma unroll
    for (int off = 16; off > 0; off >>= 1) v += __shfl_xor_sync(0xffffffffu, v, off);
    if (lane == 0) ws[wid] = v;
    __syncthreads();
    float mean = 0.0f;
    #pragma unroll
    for (int i = 0; i < 8; i++) mean += ws[i];
    mean *= (1.0f / D_);
    __syncthreads();

    const float d = x - mean;
    v = d * d;
    #pragma unroll
    for (int off = 16; off > 0; off >>= 1) v += __shfl_xor_sync(0xffffffffu, v, off);
    if (lane == 0) ws[wid] = v;
    __syncthreads();
    float var = 0.0f;
    #pragma unroll
    for (int i = 0; i < 8; i++) var += ws[i];
    var *= (1.0f / D_);

    float y = d * rsqrtf(var + 1e-5f) * g[tid] + bt[tid];
    if (RESID) y += resid[row * D_ + tid];
    out[row * D_ + tid] = y;
}

// ---------------- launch ----------------
extern "C" void kernel_launch(void* const* d_in, const int* in_sizes, int n_in,
                              void* d_out, int out_size) {
    const float* x   = (const float*)d_in[0];
    const float* src = (const float*)d_in[1];
    const float* af  = (const float*)d_in[2];
    const float* Wq  = (const float*)d_in[3];
    const float* Wk  = (const float*)d_in[4];
    const float* Wv  = (const float*)d_in[5];
    const float* Wm  = (const float*)d_in[6];
    const float* W1  = (const float*)d_in[7];
    const float* W2  = (const float*)d_in[8];
    const float* g1  = (const float*)d_in[9];
    const float* b1  = (const float*)d_in[10];
    const float* g2  = (const float*)d_in[11];
    const float* b2  = (const float*)d_in[12];
    float* out = (float*)d_out;

    float *Q, *K, *V, *OP, *SS, *O, *M, *HB, *T;
    cudaGetSymbolAddress((void**)&Q,  g_Q);
    cudaGetSymbolAddress((void**)&K,  g_K);
    cudaGetSymbolAddress((void**)&V,  g_V);
    cudaGetSymbolAddress((void**)&OP, g_OP);
    cudaGetSymbolAddress((void**)&SS, g_SS);
    cudaGetSymbolAddress((void**)&O,  g_O);
    cudaGetSymbolAddress((void**)&M,  g_M);
    cudaGetSymbolAddress((void**)&HB, g_HB);
    cudaGetSymbolAddress((void**)&T,  g_T);

    cudaFuncSetAttribute(attn5, cudaFuncAttributeMaxDynamicSharedMemorySize, ATTN_SMEM);

    const int ML = B_ * L_;  // 4096
    float* OP1 = OP + (size_t)B_ * L_ * D_;

    // projections (one launch, grid.z selects Q/K/V; K,V tf32-rounded)
    gemm_qkv<<<dim3(4, ML / 64, 3), 256>>>(x, src, Wq, Wk, Wv, Q, K, V);

    // attention (tf32 mma) -> raw partials OP + sums SS
    attn5<<<dim3(L_ / 16, SPLITS, B_), 256, ATTN_SMEM>>>(Q, K, V, af, OP, SS);

    // Wm with fused combine, split-K=2 (partials M,T) + LN1 (sums) -> O
    gemm_wm_combine<<<dim3(4, ML / 64, 2), 256>>>(OP, OP1, SS, Wm, M, T);
    ln_kernel<false, 2><<<ML, 256>>>(M, T, nullptr, nullptr, g1, b1, nullptr, O);

    // MLP: h = relu([x, LN1] @ W1^T)
    gemm_w1<<<dim3(8, ML / 64), 256>>>(x, O, W1, HB);
    // W2 split-K=4 (partials M,T,Q,K — Q/K free after attention)
    gemm_w2_splitk<<<dim3(4, ML / 64, 4), 256>>>(HB, W2, M, T, Q, K);

    // LN2 (sums 4 partials) + residual -> out
    ln_kernel<true, 4><<<ML, 256>>>(M, T, Q, K, g2, b2, x, out);
}

// round 15
// speedup vs baseline: 2.8970x; 1.1663x over previous
#include <cuda_runtime.h>
#include <math.h>

typedef unsigned long long ull;
typedef unsigned int u32;

#define B_  2
#define L_  2048
#define S_  2048
#define D_  256
#define H_  8
#define SPLITS 2
#define SHALF (S_ / SPLITS)      // 1024
#define NT (SHALF / 16)          // 64 s-tiles of 16

__device__ __forceinline__ float ex2f(float x) {
    float r;
    asm("ex2.approx.ftz.f32 %0, %1;" : "=f"(r) : "f"(x));
    return r;
}
__device__ __forceinline__ u32 tf32r(float x) {
    u32 r;
    asm("cvt.rna.tf32.f32 %0, %1;" : "=r"(r) : "f"(x));
    return r;
}

// mma.sync m16n8k8 tf32: D += A*B (C==D registers)
#define MMA_TF32(d, a, b) \
    asm volatile("mma.sync.aligned.m16n8k8.row.col.f32.tf32.tf32.f32 " \
        "{%0,%1,%2,%3},{%4,%5,%6,%7},{%8,%9},{%0,%1,%2,%3};" \
        : "+f"((d)[0]), "+f"((d)[1]), "+f"((d)[2]), "+f"((d)[3]) \
        : "r"((a)[0]), "r"((a)[1]), "r"((a)[2]), "r"((a)[3]), \
          "r"((b)[0]), "r"((b)[1]));

// ---------------- scratch ----------------
__device__ float g_Q[(size_t)B_ * L_ * D_];
__device__ float g_K[(size_t)B_ * S_ * D_];
__device__ float g_V[(size_t)B_ * S_ * D_];
__device__ float g_OP[(size_t)SPLITS * B_ * L_ * D_];
__device__ float g_SS[(size_t)SPLITS * B_ * H_ * L_];
__device__ float g_O[(size_t)B_ * L_ * D_];
__device__ float g_M[(size_t)B_ * L_ * D_];
__device__ float g_HB[(size_t)B_ * L_ * 2 * D_];
__device__ float g_T[(size_t)B_ * L_ * D_];

// ---------------- tf32 mma GEMM: Y[M,N] = X[M,K] @ W[N,K]^T ----------------
// (R14-verbatim, proven)
template <bool RELU, int MODE, bool CVT>
__device__ __forceinline__ void mgemm_body(
    const float* __restrict__ X, const float* __restrict__ X2,
    const float* __restrict__ SSp,
    const float* __restrict__ W, float* __restrict__ Y,
    int N, int K, int ldx, int ldw, int bm, int bn, int kz) {
    __shared__ float Xs[64][20];
    __shared__ float Ws[64][20];
    const int tid = threadIdx.x;
    const int wid = tid >> 5, lane = tid & 31;
    const int wm = wid >> 1, wn = wid & 1;
    const int g = lane >> 2, t = lane & 3;
    const int r = tid >> 2, c4 = (tid & 3) * 4;
    const int NTk = K >> 4;

    float4 xr, wr;
    #define MLOAD(kc_) do { \
        int c = c4 + (kc_); \
        if (MODE == 1) { \
            xr = (c < 256) ? *(const float4*)(X + (size_t)(bm + r) * 256 + c) \
                           : *(const float4*)(X2 + (size_t)(bm + r) * 256 + (c - 256)); \
        } else if (MODE == 2) { \
            size_t row = bm + r; \
            int kabs = kz + c; \
            size_t e = row * 256 + kabs; \
            float4 a = *(const float4*)(X + e); \
            float4 c2 = *(const float4*)(X2 + e); \
            size_t bb = row >> 11; size_t l = row & 2047; \
            int h = kabs >> 5; \
            float s = SSp[(bb * H_ + h) * L_ + l] \
                    + SSp[(size_t)B_ * H_ * L_ + (bb * H_ + h) * L_ + l]; \
            float inv = 1.0f / s; \
            xr.x = (a.x + c2.x) * inv; xr.y = (a.y + c2.y) * inv; \
            xr.z = (a.z + c2.z) * inv; xr.w = (a.w + c2.w) * inv; \
        } else { \
            xr = *(const float4*)(X + (size_t)(bm + r) * ldx + c); \
        } \
        wr = *(const float4*)(W + (size_t)(bn + r) * ldw + c); \
    } while (0)

    MLOAD(0);

    float ca[4][4];
    #pragma unroll
    for (int ns = 0; ns < 4; ns++)
        #pragma unroll
        for (int i = 0; i < 4; i++) ca[ns][i] = 0.0f;

    for (int kt = 0; kt < NTk; kt++) {
        __syncthreads();
        {
            float4 xv = xr, wv = wr;
            xv.x = __uint_as_float(tf32r(xv.x)); xv.y = __uint_as_float(tf32r(xv.y));
            xv.z = __uint_as_float(tf32r(xv.z)); xv.w = __uint_as_float(tf32r(xv.w));
            wv.x = __uint_as_float(tf32r(wv.x)); wv.y = __uint_as_float(tf32r(wv.y));
            wv.z = __uint_as_float(tf32r(wv.z)); wv.w = __uint_as_float(tf32r(wv.w));
            *(float4*)&Xs[r][c4] = xv;
            *(float4*)&Ws[r][c4] = wv;
        }
        if (kt + 1 < NTk) MLOAD((kt + 1) * 16);
        __syncthreads();
        #pragma unroll
        for (int ks = 0; ks < 2; ks++) {
            u32 a[4];
            a[0] = __float_as_uint(Xs[wm * 16 + g][ks * 8 + t]);
            a[1] = __float_as_uint(Xs[wm * 16 + g + 8][ks * 8 + t]);
            a[2] = __float_as_uint(Xs[wm * 16 + g][ks * 8 + t + 4]);
            a[3] = __float_as_uint(Xs[wm * 16 + g + 8][ks * 8 + t + 4]);
            #pragma unroll
            for (int ns = 0; ns < 4; ns++) {
                u32 bf[2];
                bf[0] = __float_as_uint(Ws[wn * 32 + ns * 8 + g][ks * 8 + t]);
                bf[1] = __float_as_uint(Ws[wn * 32 + ns * 8 + g][ks * 8 + t + 4]);
                MMA_TF32(ca[ns], a, bf);
            }
        }
    }
    #undef MLOAD

    #pragma unroll
    for (int ns = 0; ns < 4; ns++) {
        float v0 = ca[ns][0], v1 = ca[ns][1], v2 = ca[ns][2], v3 = ca[ns][3];
        if (RELU) {
            v0 = fmaxf(v0, 0.0f); v1 = fmaxf(v1, 0.0f);
            v2 = fmaxf(v2, 0.0f); v3 = fmaxf(v3, 0.0f);
        }
        if (CVT) {
            v0 = __uint_as_float(tf32r(v0)); v1 = __uint_as_float(tf32r(v1));
            v2 = __uint_as_float(tf32r(v2)); v3 = __uint_as_float(tf32r(v3));
        }
        int col = bn + wn * 32 + ns * 8 + 2 * t;
        float2 p0; p0.x = v0; p0.y = v1;
        float2 p1; p1.x = v2; p1.y = v3;
        *(float2*)(Y + (size_t)(bm + wm * 16 + g) * N + col) = p0;
        *(float2*)(Y + (size_t)(bm + wm * 16 + g + 8) * N + col) = p1;
    }
}

__global__ void __launch_bounds__(256) gemm_qkv(
    const float* __restrict__ x, const float* __restrict__ src,
    const float* __restrict__ Wq, const float* __restrict__ Wk,
    const float* __restrict__ Wv,
    float* __restrict__ Q, float* __restrict__ K, float* __restrict__ V) {
    const int z = blockIdx.z;
    if (z == 0) {
        mgemm_body<false, 0, false>(x, nullptr, nullptr, Wq, Q, 256, 256, 256, 256,
                                    blockIdx.y * 64, blockIdx.x * 64, 0);
    } else {
        const float* W = (z == 1) ? Wk : Wv;
        float* Y = (z == 1) ? K : V;
        mgemm_body<false, 0, true>(src, nullptr, nullptr, W, Y, 256, 256, 256, 256,
                                   blockIdx.y * 64, blockIdx.x * 64, 0);
    }
}

__global__ void __launch_bounds__(256) gemm_wm_combine(
    const float* __restrict__ OP0, const float* __restrict__ OP1,
    const float* __restrict__ SSp, const float* __restrict__ Wm,
    float* __restrict__ Y0, float* __restrict__ Y1) {
    const int z = blockIdx.z;
    const int kz = z * 128;
    mgemm_body<false, 2, false>(OP0, OP1, SSp, Wm + kz, z ? Y1 : Y0,
                                256, 128, 256, 256, blockIdx.y * 64, blockIdx.x * 64, kz);
}

__global__ void __launch_bounds__(256) gemm_w2_splitk(
    const float* __restrict__ X, const float* __restrict__ W,
    float* __restrict__ Y0, float* __restrict__ Y1,
    float* __restrict__ Y2, float* __restrict__ Y3) {
    const int z = blockIdx.z;
    float* Y = (z == 0) ? Y0 : (z == 1) ? Y1 : (z == 2) ? Y2 : Y3;
    mgemm_body<false, 0, false>(X + z * 128, nullptr, nullptr, W + z * 128, Y,
                                256, 128, 512, 512, blockIdx.y * 64, blockIdx.x * 64, 0);
}

__global__ void __launch_bounds__(256) gemm_w1(
    const float* __restrict__ X, const float* __restrict__ X2,
    const float* __restrict__ W, float* __restrict__ Y) {
    mgemm_body<true, 1, false>(X, X2, nullptr, W, Y, 512, 512, 256, 512,
                               blockIdx.y * 64, blockIdx.x * 64, 0);
}

// ---------------- attn6: tf32 mma flash attention, 32 l-rows/block ----------------
// Block: 256 thr = 8 warps (warp = head). Two 16-row groups processed
// sequentially per s-tile — every K/V tile serves 32 rows.
// smem floats: K 2*4160=8320 | V 2*4224=8448 @8320 | Af 2*576=1152 @16768 |
//              P 8*320=2560 @17920  -> 20480 floats = 81920 B.
#define ATTN_SMEM 81920

#define ISSUE_KV(t_, buf_) do { \
    const float* ksrc_ = Kb + (size_t)(sbase + (t_) * 16) * D_; \
    const float* vsrc_ = Vb + (size_t)(sbase + (t_) * 16) * D_; \
    u32 kd_ = kbase + (u32)(buf_) * 16640; \
    u32 vd_ = vbase + (u32)(buf_) * 16896; \
    _Pragma("unroll") \
    for (int i_ = 0; i_ < 4; i_++) { \
        int idx_ = tid + 256 * i_; int s_ = idx_ >> 6; int c_ = (idx_ & 63) * 4; \
        asm volatile("cp.async.cg.shared.global [%0], [%1], 16;" :: \
            "r"(kd_ + (u32)(s_ * 1040 + c_ * 4)), "l"(ksrc_ + s_ * 256 + c_)); \
        asm volatile("cp.async.cg.shared.global [%0], [%1], 16;" :: \
            "r"(vd_ + (u32)(s_ * 1056 + c_ * 4)), "l"(vsrc_ + s_ * 256 + c_)); \
    } \
    asm volatile("cp.async.commit_group;"); \
} while (0)

#define LOAD_AF(t_) do { \
    afr0 = afb[(size_t)(tid >> 4) * S_ + (t_) * 16 + (tid & 15)]; \
    afr1 = afb[(size_t)((tid >> 4) + 16) * S_ + (t_) * 16 + (tid & 15)]; \
} while (0)

#define STORE_AF(buf_) do { \
    Afs[(buf_) * 576 + (tid >> 4) * 18 + (tid & 15)] = afr0; \
    Afs[(buf_) * 576 + ((tid >> 4) + 16) * 18 + (tid & 15)] = afr1; \
} while (0)

__global__ void __launch_bounds__(256, 2) attn6(
    const float* __restrict__ Qg, const float* __restrict__ Kg,
    const float* __restrict__ Vg, const float* __restrict__ af,
    float* __restrict__ Op, float* __restrict__ SSp) {
    extern __shared__ float sm[];
    float* Ksm = sm;                  // buf stride 4160 (row pad 260)
    float* Vsm = sm + 8320;           // buf stride 4224 (row pad 264)
    float* Afs = sm + 16768;          // buf stride 576 (row pad 18, 32 rows)

    const int b = blockIdx.z, sp = blockIdx.y;
    const int l0 = blockIdx.x * 32;
    const int tid = threadIdx.x;
    const int w = tid >> 5, lane = tid & 31;
    const int g = lane >> 2, t = lane & 3;
    float* Pw = sm + 17920 + w * 320; // per-warp 16x20 (reused per row-group)

    const int sbase = sp * SHALF;
    const float* Kb  = Kg + (size_t)b * S_ * D_;
    const float* Vb  = Vg + (size_t)b * S_ * D_;
    const float* afb = af + ((size_t)b * L_ + l0) * S_ + sbase;
    const u32 smb = (u32)__cvta_generic_to_shared(sm);
    const u32 kbase = smb;
    const u32 vbase = smb + 33280;

    // Q fragments for both 16-row groups (per head 32x32), scaled+tf32
    u32 qf[2][4][4];
    {
        const float QS = 0.25503486f;  // log2(e)/sqrt(32)
        const float* qb = Qg + (size_t)b * L_ * D_;
        #pragma unroll
        for (int rg = 0; rg < 2; rg++) {
            int lr = l0 + rg * 16;
            #pragma unroll
            for (int kt = 0; kt < 4; kt++) {
                int d0 = w * 32 + kt * 8 + t;
                qf[rg][kt][0] = tf32r(qb[(size_t)(lr + g) * 256 + d0] * QS);
                qf[rg][kt][1] = tf32r(qb[(size_t)(lr + g + 8) * 256 + d0] * QS);
                qf[rg][kt][2] = tf32r(qb[(size_t)(lr + g) * 256 + d0 + 4] * QS);
                qf[rg][kt][3] = tf32r(qb[(size_t)(lr + g + 8) * 256 + d0 + 4] * QS);
            }
        }
    }

    float oa[2][4][4];
    #pragma unroll
    for (int rg = 0; rg < 2; rg++)
        #pragma unroll
        for (int dn = 0; dn < 4; dn++)
            #pragma unroll
            for (int c = 0; c < 4; c++) oa[rg][dn][c] = 0.0f;
    float ss[4];
    #pragma unroll
    for (int i = 0; i < 4; i++) ss[i] = 0.0f;
    float afr0, afr1;

    ISSUE_KV(0, 0);
    LOAD_AF(0);
    ISSUE_KV(1, 1);
    STORE_AF(0);
    LOAD_AF(1);

    for (int st = 0; st < NT; st++) {
        const int buf = st & 1;
        if (st + 1 < NT) asm volatile("cp.async.wait_group 1;");
        else             asm volatile("cp.async.wait_group 0;");
        __syncthreads();
        if (st + 1 < NT) STORE_AF(buf ^ 1);
        if (st + 2 < NT) LOAD_AF(st + 2);

        const float* ks  = Ksm + buf * 4160 + w * 32;   // head slab
        const float* vs  = Vsm + buf * 4224;
        const float* afl = Afs + buf * 576;

        // K fragments loaded once, reused by both row-groups
        u32 bk[4][2][2];
        #pragma unroll
        for (int kt = 0; kt < 4; kt++) {
            bk[kt][0][0] = __float_as_uint(ks[(size_t)g * 260 + kt * 8 + t]);
            bk[kt][0][1] = __float_as_uint(ks[(size_t)g * 260 + kt * 8 + t + 4]);
            bk[kt][1][0] = __float_as_uint(ks[(size_t)(g + 8) * 260 + kt * 8 + t]);
            bk[kt][1][1] = __float_as_uint(ks[(size_t)(g + 8) * 260 + kt * 8 + t + 4]);
        }

        #pragma unroll
        for (int rg = 0; rg < 2; rg++) {
            // ---- QK: 16l x 16s ----
            float sc[2][4];
            #pragma unroll
            for (int nt = 0; nt < 2; nt++)
                #pragma unroll
                for (int c = 0; c < 4; c++) sc[nt][c] = 0.0f;
            #pragma unroll
            for (int kt = 0; kt < 4; kt++) {
                MMA_TF32(sc[0], qf[rg][kt], bk[kt][0]);
                MMA_TF32(sc[1], qf[rg][kt], bk[kt][1]);
            }

            // ---- softmax epilogue ----
            const float* afr = afl + (rg * 16) * 18;
            u32 pv[2][4];
            float rs0 = 0.0f, rs1 = 0.0f;
            #pragma unroll
            for (int nt = 0; nt < 2; nt++) {
                float2 afA = *(const float2*)&afr[g * 18 + nt * 8 + 2 * t];
                float2 afB = *(const float2*)&afr[(g + 8) * 18 + nt * 8 + 2 * t];
                float p0 = ex2f(sc[nt][0] * afA.x);
                float p1 = ex2f(sc[nt][1] * afA.y);
                float p2 = ex2f(sc[nt][2] * afB.x);
                float p3 = ex2f(sc[nt][3] * afB.y);
                pv[nt][0] = tf32r(p0); pv[nt][1] = tf32r(p1);
                pv[nt][2] = tf32r(p2); pv[nt][3] = tf32r(p3);
                rs0 += __uint_as_float(pv[nt][0]) + __uint_as_float(pv[nt][1]);
                rs1 += __uint_as_float(pv[nt][2]) + __uint_as_float(pv[nt][3]);
            }
            rs0 += __shfl_xor_sync(0xffffffffu, rs0, 1);
            rs0 += __shfl_xor_sync(0xffffffffu, rs0, 2);
            rs1 += __shfl_xor_sync(0xffffffffu, rs1, 1);
            rs1 += __shfl_xor_sync(0xffffffffu, rs1, 2);
            ss[rg * 2 + 0] += rs0;
            ss[rg * 2 + 1] += rs1;

            // ---- P -> smem (C layout), reload as A fragments ----
            __syncwarp();
            #pragma unroll
            for (int nt = 0; nt < 2; nt++) {
                float2 v0; v0.x = __uint_as_float(pv[nt][0]); v0.y = __uint_as_float(pv[nt][1]);
                float2 v1; v1.x = __uint_as_float(pv[nt][2]); v1.y = __uint_as_float(pv[nt][3]);
                *(float2*)&Pw[g * 20 + nt * 8 + 2 * t] = v0;
                *(float2*)&Pw[(g + 8) * 20 + nt * 8 + 2 * t] = v1;
            }
            __syncwarp();
            u32 pa[2][4];
            #pragma unroll
            for (int ksx = 0; ksx < 2; ksx++) {
                pa[ksx][0] = __float_as_uint(Pw[g * 20 + ksx * 8 + t]);
                pa[ksx][1] = __float_as_uint(Pw[(g + 8) * 20 + ksx * 8 + t]);
                pa[ksx][2] = __float_as_uint(Pw[g * 20 + ksx * 8 + t + 4]);
                pa[ksx][3] = __float_as_uint(Pw[(g + 8) * 20 + ksx * 8 + t + 4]);
            }

            // ---- AV: O += P @ V ----
            #pragma unroll
            for (int dn = 0; dn < 4; dn++) {
                u32 bv0[2], bv1[2];
                int dcol = w * 32 + dn * 8 + g;
                bv0[0] = __float_as_uint(vs[(size_t)t * 264 + dcol]);
                bv0[1] = __float_as_uint(vs[(size_t)(t + 4) * 264 + dcol]);
                bv1[0] = __float_as_uint(vs[(size_t)(8 + t) * 264 + dcol]);
                bv1[1] = __float_as_uint(vs[(size_t)(8 + t + 4) * 264 + dcol]);
                MMA_TF32(oa[rg][dn], pa[0], bv0);
                MMA_TF32(oa[rg][dn], pa[1], bv1);
            }
        }
        __syncthreads();
        if (st + 2 < NT) ISSUE_KV(st + 2, buf);
    }

    // write raw partials + sums (combine fused into Wm GEMM)
    #pragma unroll
    for (int rg = 0; rg < 2; rg++) {
        int lr = l0 + rg * 16;
        float* opg  = Op + (((size_t)sp * B_ + b) * L_ + lr + g) * 256 + w * 32;
        float* opg8 = opg + 8 * 256;
        #pragma unroll
        for (int dn = 0; dn < 4; dn++) {
            float2 v0; v0.x = oa[rg][dn][0]; v0.y = oa[rg][dn][1];
            float2 v1; v1.x = oa[rg][dn][2]; v1.y = oa[rg][dn][3];
            *(float2*)(opg + dn * 8 + 2 * t) = v0;
            *(float2*)(opg8 + dn * 8 + 2 * t) = v1;
        }
        if (t == 0) {
            size_t ssb = (((size_t)sp * B_ + b) * H_ + w) * L_ + lr;
            SSp[ssb + g] = ss[rg * 2 + 0];
            SSp[ssb + g + 8] = ss[rg * 2 + 1];
        }
    }
}

// ---------------- LayerNorm over D=256, NIN summed inputs ----------------
template <bool RESID, int NIN>
__global__ void ln_kernel(const float* __restrict__ in0, const float* __restrict__ in1,
                          const float* __restrict__ in2, const float* __restrict__ in3,
                          const float* __restrict__ g, const float* __restrict__ bt,
                          const float* __restrict__ resid, float* __restrict__ out) {
    const size_t row = blockIdx.x;
    const int tid = threadIdx.x;
    const int lane = tid & 31, wid = tid >> 5;
    float x = in0[row * D_ + tid];
    if (NIN > 1) x += in1[row * D_ + tid];
    if (NIN > 2) x += in2[row * D_ + tid];
    if (NIN > 3) x += in3[row * D_ + tid];
    __shared__ float ws[8];

    float v = x;
    #pragma unroll
    for (int off = 16; off > 0; off >>= 1) v += __shfl_xor_sync(0xffffffffu, v, off);
    if (lane == 0) ws[wid] = v;
    __syncthreads();
    float mean = 0.0f;
    #pragma unroll
    for (int i = 0; i < 8; i++) mean += ws[i];
    mean *= (1.0f / D_);
    __syncthreads();

    const float d = x - mean;
    v = d * d;
    #pragma unroll
    for (int off = 16; off > 0; off >>= 1) v += __shfl_xor_sync(0xffffffffu, v, off);
    if (lane == 0) ws[wid] = v;
    __syncthreads();
    float var = 0.0f;
    #pragma unroll
    for (int i = 0; i < 8; i++) var += ws[i];
    var *= (1.0f / D_);

    float y = d * rsqrtf(var + 1e-5f) * g[tid] + bt[tid];
    if (RESID) y += resid[row * D_ + tid];
    out[row * D_ + tid] = y;
}

// ---------------- launch ----------------
extern "C" void kernel_launch(void* const* d_in, const int* in_sizes, int n_in,
                              void* d_out, int out_size) {
    const float* x   = (const float*)d_in[0];
    const float* src = (const float*)d_in[1];
    const float* af  = (const float*)d_in[2];
    const float* Wq  = (const float*)d_in[3];
    const float* Wk  = (const float*)d_in[4];
    const float* Wv  = (const float*)d_in[5];
    const float* Wm  = (const float*)d_in[6];
    const float* W1  = (const float*)d_in[7];
    const float* W2  = (const float*)d_in[8];
    const float* g1  = (const float*)d_in[9];
    const float* b1  = (const float*)d_in[10];
    const float* g2  = (const float*)d_in[11];
    const float* b2  = (const float*)d_in[12];
    float* out = (float*)d_out;

    float *Q, *K, *V, *OP, *SS, *O, *M, *HB, *T;
    cudaGetSymbolAddress((void**)&Q,  g_Q);
    cudaGetSymbolAddress((void**)&K,  g_K);
    cudaGetSymbolAddress((void**)&V,  g_V);
    cudaGetSymbolAddress((void**)&OP, g_OP);
    cudaGetSymbolAddress((void**)&SS, g_SS);
    cudaGetSymbolAddress((void**)&O,  g_O);
    cudaGetSymbolAddress((void**)&M,  g_M);
    cudaGetSymbolAddress((void**)&HB, g_HB);
    cudaGetSymbolAddress((void**)&T,  g_T);

    cudaFuncSetAttribute(attn6, cudaFuncAttributeMaxDynamicSharedMemorySize, ATTN_SMEM);

    const int ML = B_ * L_;  // 4096
    float* OP1 = OP + (size_t)B_ * L_ * D_;

    // projections (one launch, grid.z selects Q/K/V; K,V tf32-rounded)
    gemm_qkv<<<dim3(4, ML / 64, 3), 256>>>(x, src, Wq, Wk, Wv, Q, K, V);

    // attention (tf32 mma, 32 rows/block) -> raw partials OP + sums SS
    attn6<<<dim3(L_ / 32, SPLITS, B_), 256, ATTN_SMEM>>>(Q, K, V, af, OP, SS);

    // Wm with fused combine, split-K=2 (partials M,T) + LN1 (sums) -> O
    gemm_wm_combine<<<dim3(4, ML / 64, 2), 256>>>(OP, OP1, SS, Wm, M, T);
    ln_kernel<false, 2><<<ML, 256>>>(M, T, nullptr, nullptr, g1, b1, nullptr, O);

    // MLP: h = relu([x, LN1] @ W1^T)
    gemm_w1<<<dim3(8, ML / 64), 256>>>(x, O, W1, HB);
    // W2 split-K=4 (partials M,T,Q,K — Q/K free after attention)
    gemm_w2_splitk<<<dim3(4, ML / 64, 4), 256>>>(HB, W2, M, T, Q, K);

    // LN2 (sums 4 partials) + residual -> out
    ln_kernel<true, 4><<<ML, 256>>>(M, T, Q, K, g2, b2, x, out);
}

// round 16
// speedup vs baseline: 3.2585x; 1.1248x over previous
#include <cuda_runtime.h>
#include <math.h>

typedef unsigned long long ull;
typedef unsigned int u32;

#define B_  2
#define L_  2048
#define S_  2048
#define D_  256
#define H_  8
#define SPLITS 2
#define SHALF (S_ / SPLITS)      // 1024
#define NT (SHALF / 16)          // 64 s-tiles of 16

__device__ __forceinline__ float ex2f(float x) {
    float r;
    asm("ex2.approx.ftz.f32 %0, %1;" : "=f"(r) : "f"(x));
    return r;
}
__device__ __forceinline__ u32 tf32r(float x) {
    u32 r;
    asm("cvt.rna.tf32.f32 %0, %1;" : "=r"(r) : "f"(x));
    return r;
}

// mma.sync m16n8k8 tf32: D += A*B (C==D registers)
#define MMA_TF32(d, a, b) \
    asm volatile("mma.sync.aligned.m16n8k8.row.col.f32.tf32.tf32.f32 " \
        "{%0,%1,%2,%3},{%4,%5,%6,%7},{%8,%9},{%0,%1,%2,%3};" \
        : "+f"((d)[0]), "+f"((d)[1]), "+f"((d)[2]), "+f"((d)[3]) \
        : "r"((a)[0]), "r"((a)[1]), "r"((a)[2]), "r"((a)[3]), \
          "r"((b)[0]), "r"((b)[1]));

// ---------------- scratch ----------------
__device__ float g_Q[(size_t)B_ * L_ * D_];
__device__ float g_K[(size_t)B_ * S_ * D_];
__device__ float g_V[(size_t)B_ * S_ * D_];
__device__ float g_OP[(size_t)SPLITS * B_ * L_ * D_];
__device__ float g_SS[(size_t)SPLITS * B_ * H_ * L_];
__device__ float g_O[(size_t)B_ * L_ * D_];
__device__ float g_M[(size_t)B_ * L_ * D_];
__device__ float g_HB[(size_t)B_ * L_ * 2 * D_];
__device__ float g_T[(size_t)B_ * L_ * D_];

// ---------------- tf32 mma GEMM: Y[M,N] = X[M,K] @ W[N,K]^T ----------------
// 256 threads = 8 warps (4m x 2n), tile 64x64, warp = 16m x 32n, K-tile 32.
// MODE 0: plain (ldx), MODE 1: X=[X|X2] along K, MODE 2: combine loader.
template <bool RELU, int MODE, bool CVT>
__device__ __forceinline__ void mgemm_body(
    const float* __restrict__ X, const float* __restrict__ X2,
    const float* __restrict__ SSp,
    const float* __restrict__ W, float* __restrict__ Y,
    int N, int K, int ldx, int ldw, int bm, int bn, int kz) {
    __shared__ float Xs[64][36];   // [row][k], pad 36 (36%32==4, conflict-free)
    __shared__ float Ws[64][36];   // [n][k]
    const int tid = threadIdx.x;
    const int wid = tid >> 5, lane = tid & 31;
    const int wm = wid >> 1, wn = wid & 1;
    const int g = lane >> 2, t = lane & 3;
    const int NTk = K >> 5;

    float4 xr[2], wr[2];
    #define MLOAD(kc_) do { \
        _Pragma("unroll") \
        for (int i = 0; i < 2; i++) { \
            int idx = tid + 256 * i; \
            int r = idx >> 3; int c = ((idx & 7) * 4) + (kc_); \
            if (MODE == 1) { \
                xr[i] = (c < 256) ? *(const float4*)(X + (size_t)(bm + r) * 256 + c) \
                                  : *(const float4*)(X2 + (size_t)(bm + r) * 256 + (c - 256)); \
            } else if (MODE == 2) { \
                size_t row = bm + r; \
                int kabs = kz + c; \
                size_t e = row * 256 + kabs; \
                float4 a = *(const float4*)(X + e); \
                float4 c2 = *(const float4*)(X2 + e); \
                size_t bb = row >> 11; size_t l = row & 2047; \
                int h = kabs >> 5; \
                float s = SSp[(bb * H_ + h) * L_ + l] \
                        + SSp[(size_t)B_ * H_ * L_ + (bb * H_ + h) * L_ + l]; \
                float inv = 1.0f / s; \
                xr[i].x = (a.x + c2.x) * inv; xr[i].y = (a.y + c2.y) * inv; \
                xr[i].z = (a.z + c2.z) * inv; xr[i].w = (a.w + c2.w) * inv; \
            } else { \
                xr[i] = *(const float4*)(X + (size_t)(bm + r) * ldx + c); \
            } \
            wr[i] = *(const float4*)(W + (size_t)(bn + r) * ldw + c); \
        } \
    } while (0)

    MLOAD(0);

    float ca[4][4];
    #pragma unroll
    for (int ns = 0; ns < 4; ns++)
        #pragma unroll
        for (int i = 0; i < 4; i++) ca[ns][i] = 0.0f;

    for (int kt = 0; kt < NTk; kt++) {
        __syncthreads();
        #pragma unroll
        for (int i = 0; i < 2; i++) {
            int idx = tid + 256 * i;
            int r = idx >> 3; int c4 = (idx & 7) * 4;
            float4 xv = xr[i], wv = wr[i];
            xv.x = __uint_as_float(tf32r(xv.x)); xv.y = __uint_as_float(tf32r(xv.y));
            xv.z = __uint_as_float(tf32r(xv.z)); xv.w = __uint_as_float(tf32r(xv.w));
            wv.x = __uint_as_float(tf32r(wv.x)); wv.y = __uint_as_float(tf32r(wv.y));
            wv.z = __uint_as_float(tf32r(wv.z)); wv.w = __uint_as_float(tf32r(wv.w));
            *(float4*)&Xs[r][c4] = xv;
            *(float4*)&Ws[r][c4] = wv;
        }
        if (kt + 1 < NTk) MLOAD((kt + 1) * 32);
        __syncthreads();
        #pragma unroll
        for (int ks = 0; ks < 4; ks++) {
            u32 a[4];
            a[0] = __float_as_uint(Xs[wm * 16 + g][ks * 8 + t]);
            a[1] = __float_as_uint(Xs[wm * 16 + g + 8][ks * 8 + t]);
            a[2] = __float_as_uint(Xs[wm * 16 + g][ks * 8 + t + 4]);
            a[3] = __float_as_uint(Xs[wm * 16 + g + 8][ks * 8 + t + 4]);
            #pragma unroll
            for (int ns = 0; ns < 4; ns++) {
                u32 bf[2];
                bf[0] = __float_as_uint(Ws[wn * 32 + ns * 8 + g][ks * 8 + t]);
                bf[1] = __float_as_uint(Ws[wn * 32 + ns * 8 + g][ks * 8 + t + 4]);
                MMA_TF32(ca[ns], a, bf);
            }
        }
    }
    #undef MLOAD

    #pragma unroll
    for (int ns = 0; ns < 4; ns++) {
        float v0 = ca[ns][0], v1 = ca[ns][1], v2 = ca[ns][2], v3 = ca[ns][3];
        if (RELU) {
            v0 = fmaxf(v0, 0.0f); v1 = fmaxf(v1, 0.0f);
            v2 = fmaxf(v2, 0.0f); v3 = fmaxf(v3, 0.0f);
        }
        if (CVT) {
            v0 = __uint_as_float(tf32r(v0)); v1 = __uint_as_float(tf32r(v1));
            v2 = __uint_as_float(tf32r(v2)); v3 = __uint_as_float(tf32r(v3));
        }
        int col = bn + wn * 32 + ns * 8 + 2 * t;
        float2 p0; p0.x = v0; p0.y = v1;
        float2 p1; p1.x = v2; p1.y = v3;
        *(float2*)(Y + (size_t)(bm + wm * 16 + g) * N + col) = p0;
        *(float2*)(Y + (size_t)(bm + wm * 16 + g + 8) * N + col) = p1;
    }
}

__global__ void __launch_bounds__(256) gemm_qkv(
    const float* __restrict__ x, const float* __restrict__ src,
    const float* __restrict__ Wq, const float* __restrict__ Wk,
    const float* __restrict__ Wv,
    float* __restrict__ Q, float* __restrict__ K, float* __restrict__ V) {
    const int z = blockIdx.z;
    if (z == 0) {
        mgemm_body<false, 0, false>(x, nullptr, nullptr, Wq, Q, 256, 256, 256, 256,
                                    blockIdx.y * 64, blockIdx.x * 64, 0);
    } else {
        const float* W = (z == 1) ? Wk : Wv;
        float* Y = (z == 1) ? K : V;
        mgemm_body<false, 0, true>(src, nullptr, nullptr, W, Y, 256, 256, 256, 256,
                                   blockIdx.y * 64, blockIdx.x * 64, 0);
    }
}

__global__ void __launch_bounds__(256) gemm_wm_combine(
    const float* __restrict__ OP0, const float* __restrict__ OP1,
    const float* __restrict__ SSp, const float* __restrict__ Wm,
    float* __restrict__ Y0, float* __restrict__ Y1) {
    const int z = blockIdx.z;
    const int kz = z * 128;
    mgemm_body<false, 2, false>(OP0, OP1, SSp, Wm + kz, z ? Y1 : Y0,
                                256, 128, 256, 256, blockIdx.y * 64, blockIdx.x * 64, kz);
}

__global__ void __launch_bounds__(256) gemm_w2_splitk(
    const float* __restrict__ X, const float* __restrict__ W,
    float* __restrict__ Y0, float* __restrict__ Y1,
    float* __restrict__ Y2, float* __restrict__ Y3) {
    const int z = blockIdx.z;
    float* Y = (z == 0) ? Y0 : (z == 1) ? Y1 : (z == 2) ? Y2 : Y3;
    mgemm_body<false, 0, false>(X + z * 128, nullptr, nullptr, W + z * 128, Y,
                                256, 128, 512, 512, blockIdx.y * 64, blockIdx.x * 64, 0);
}

__global__ void __launch_bounds__(256) gemm_w1(
    const float* __restrict__ X, const float* __restrict__ X2,
    const float* __restrict__ W, float* __restrict__ Y) {
    mgemm_body<true, 1, false>(X, X2, nullptr, W, Y, 512, 512, 256, 512,
                               blockIdx.y * 64, blockIdx.x * 64, 0);
}

// ---------------- attn6: tf32 mma flash attention, 32 l-rows/block ----------------
// (R15-verbatim, proven)
#define ATTN_SMEM 81920

#define ISSUE_KV(t_, buf_) do { \
    const float* ksrc_ = Kb + (size_t)(sbase + (t_) * 16) * D_; \
    const float* vsrc_ = Vb + (size_t)(sbase + (t_) * 16) * D_; \
    u32 kd_ = kbase + (u32)(buf_) * 16640; \
    u32 vd_ = vbase + (u32)(buf_) * 16896; \
    _Pragma("unroll") \
    for (int i_ = 0; i_ < 4; i_++) { \
        int idx_ = tid + 256 * i_; int s_ = idx_ >> 6; int c_ = (idx_ & 63) * 4; \
        asm volatile("cp.async.cg.shared.global [%0], [%1], 16;" :: \
            "r"(kd_ + (u32)(s_ * 1040 + c_ * 4)), "l"(ksrc_ + s_ * 256 + c_)); \
        asm volatile("cp.async.cg.shared.global [%0], [%1], 16;" :: \
            "r"(vd_ + (u32)(s_ * 1056 + c_ * 4)), "l"(vsrc_ + s_ * 256 + c_)); \
    } \
    asm volatile("cp.async.commit_group;"); \
} while (0)

#define LOAD_AF(t_) do { \
    afr0 = afb[(size_t)(tid >> 4) * S_ + (t_) * 16 + (tid & 15)]; \
    afr1 = afb[(size_t)((tid >> 4) + 16) * S_ + (t_) * 16 + (tid & 15)]; \
} while (0)

#define STORE_AF(buf_) do { \
    Afs[(buf_) * 576 + (tid >> 4) * 18 + (tid & 15)] = afr0; \
    Afs[(buf_) * 576 + ((tid >> 4) + 16) * 18 + (tid & 15)] = afr1; \
} while (0)

__global__ void __launch_bounds__(256, 2) attn6(
    const float* __restrict__ Qg, const float* __restrict__ Kg,
    const float* __restrict__ Vg, const float* __restrict__ af,
    float* __restrict__ Op, float* __restrict__ SSp) {
    extern __shared__ float sm[];
    float* Ksm = sm;                  // buf stride 4160 (row pad 260)
    float* Vsm = sm + 8320;           // buf stride 4224 (row pad 264)
    float* Afs = sm + 16768;          // buf stride 576 (row pad 18, 32 rows)

    const int b = blockIdx.z, sp = blockIdx.y;
    const int l0 = blockIdx.x * 32;
    const int tid = threadIdx.x;
    const int w = tid >> 5, lane = tid & 31;
    const int g = lane >> 2, t = lane & 3;
    float* Pw = sm + 17920 + w * 320; // per-warp 16x20 (reused per row-group)

    const int sbase = sp * SHALF;
    const float* Kb  = Kg + (size_t)b * S_ * D_;
    const float* Vb  = Vg + (size_t)b * S_ * D_;
    const float* afb = af + ((size_t)b * L_ + l0) * S_ + sbase;
    const u32 smb = (u32)__cvta_generic_to_shared(sm);
    const u32 kbase = smb;
    const u32 vbase = smb + 33280;

    u32 qf[2][4][4];
    {
        const float QS = 0.25503486f;  // log2(e)/sqrt(32)
        const float* qb = Qg + (size_t)b * L_ * D_;
        #pragma unroll
        for (int rg = 0; rg < 2; rg++) {
            int lr = l0 + rg * 16;
            #pragma unroll
            for (int kt = 0; kt < 4; kt++) {
                int d0 = w * 32 + kt * 8 + t;
                qf[rg][kt][0] = tf32r(qb[(size_t)(lr + g) * 256 + d0] * QS);
                qf[rg][kt][1] = tf32r(qb[(size_t)(lr + g + 8) * 256 + d0] * QS);
                qf[rg][kt][2] = tf32r(qb[(size_t)(lr + g) * 256 + d0 + 4] * QS);
                qf[rg][kt][3] = tf32r(qb[(size_t)(lr + g + 8) * 256 + d0 + 4] * QS);
            }
        }
    }

    float oa[2][4][4];
    #pragma unroll
    for (int rg = 0; rg < 2; rg++)
        #pragma unroll
        for (int dn = 0; dn < 4; dn++)
            #pragma unroll
            for (int c = 0; c < 4; c++) oa[rg][dn][c] = 0.0f;
    float ss[4];
    #pragma unroll
    for (int i = 0; i < 4; i++) ss[i] = 0.0f;
    float afr0, afr1;

    ISSUE_KV(0, 0);
    LOAD_AF(0);
    ISSUE_KV(1, 1);
    STORE_AF(0);
    LOAD_AF(1);

    for (int st = 0; st < NT; st++) {
        const int buf = st & 1;
        if (st + 1 < NT) asm volatile("cp.async.wait_group 1;");
        else             asm volatile("cp.async.wait_group 0;");
        __syncthreads();
        if (st + 1 < NT) STORE_AF(buf ^ 1);
        if (st + 2 < NT) LOAD_AF(st + 2);

        const float* ks  = Ksm + buf * 4160 + w * 32;   // head slab
        const float* vs  = Vsm + buf * 4224;
        const float* afl = Afs + buf * 576;

        u32 bk[4][2][2];
        #pragma unroll
        for (int kt = 0; kt < 4; kt++) {
            bk[kt][0][0] = __float_as_uint(ks[(size_t)g * 260 + kt * 8 + t]);
            bk[kt][0][1] = __float_as_uint(ks[(size_t)g * 260 + kt * 8 + t + 4]);
            bk[kt][1][0] = __float_as_uint(ks[(size_t)(g + 8) * 260 + kt * 8 + t]);
            bk[kt][1][1] = __float_as_uint(ks[(size_t)(g + 8) * 260 + kt * 8 + t + 4]);
        }

        #pragma unroll
        for (int rg = 0; rg < 2; rg++) {
            float sc[2][4];
            #pragma unroll
            for (int nt = 0; nt < 2; nt++)
                #pragma unroll
                for (int c = 0; c < 4; c++) sc[nt][c] = 0.0f;
            #pragma unroll
            for (int kt = 0; kt < 4; kt++) {
                MMA_TF32(sc[0], qf[rg][kt], bk[kt][0]);
                MMA_TF32(sc[1], qf[rg][kt], bk[kt][1]);
            }

            const float* afr = afl + (rg * 16) * 18;
            u32 pv[2][4];
            float rs0 = 0.0f, rs1 = 0.0f;
            #pragma unroll
            for (int nt = 0; nt < 2; nt++) {
                float2 afA = *(const float2*)&afr[g * 18 + nt * 8 + 2 * t];
                float2 afB = *(const float2*)&afr[(g + 8) * 18 + nt * 8 + 2 * t];
                float p0 = ex2f(sc[nt][0] * afA.x);
                float p1 = ex2f(sc[nt][1] * afA.y);
                float p2 = ex2f(sc[nt][2] * afB.x);
                float p3 = ex2f(sc[nt][3] * afB.y);
                pv[nt][0] = tf32r(p0); pv[nt][1] = tf32r(p1);
                pv[nt][2] = tf32r(p2); pv[nt][3] = tf32r(p3);
                rs0 += __uint_as_float(pv[nt][0]) + __uint_as_float(pv[nt][1]);
                rs1 += __uint_as_float(pv[nt][2]) + __uint_as_float(pv[nt][3]);
            }
            rs0 += __shfl_xor_sync(0xffffffffu, rs0, 1);
            rs0 += __shfl_xor_sync(0xffffffffu, rs0, 2);
            rs1 += __shfl_xor_sync(0xffffffffu, rs1, 1);
            rs1 += __shfl_xor_sync(0xffffffffu, rs1, 2);
            ss[rg * 2 + 0] += rs0;
            ss[rg * 2 + 1] += rs1;

            __syncwarp();
            #pragma unroll
            for (int nt = 0; nt < 2; nt++) {
                float2 v0; v0.x = __uint_as_float(pv[nt][0]); v0.y = __uint_as_float(pv[nt][1]);
                float2 v1; v1.x = __uint_as_float(pv[nt][2]); v1.y = __uint_as_float(pv[nt][3]);
                *(float2*)&Pw[g * 20 + nt * 8 + 2 * t] = v0;
                *(float2*)&Pw[(g + 8) * 20 + nt * 8 + 2 * t] = v1;
            }
            __syncwarp();
            u32 pa[2][4];
            #pragma unroll
            for (int ksx = 0; ksx < 2; ksx++) {
                pa[ksx][0] = __float_as_uint(Pw[g * 20 + ksx * 8 + t]);
                pa[ksx][1] = __float_as_uint(Pw[(g + 8) * 20 + ksx * 8 + t]);
                pa[ksx][2] = __float_as_uint(Pw[g * 20 + ksx * 8 + t + 4]);
                pa[ksx][3] = __float_as_uint(Pw[(g + 8) * 20 + ksx * 8 + t + 4]);
            }

            #pragma unroll
            for (int dn = 0; dn < 4; dn++) {
                u32 bv0[2], bv1[2];
                int dcol = w * 32 + dn * 8 + g;
                bv0[0] = __float_as_uint(vs[(size_t)t * 264 + dcol]);
                bv0[1] = __float_as_uint(vs[(size_t)(t + 4) * 264 + dcol]);
                bv1[0] = __float_as_uint(vs[(size_t)(8 + t) * 264 + dcol]);
                bv1[1] = __float_as_uint(vs[(size_t)(8 + t + 4) * 264 + dcol]);
                MMA_TF32(oa[rg][dn], pa[0], bv0);
                MMA_TF32(oa[rg][dn], pa[1], bv1);
            }
        }
        __syncthreads();
        if (st + 2 < NT) ISSUE_KV(st + 2, buf);
    }

    #pragma unroll
    for (int rg = 0; rg < 2; rg++) {
        int lr = l0 + rg * 16;
        float* opg  = Op + (((size_t)sp * B_ + b) * L_ + lr + g) * 256 + w * 32;
        float* opg8 = opg + 8 * 256;
        #pragma unroll
        for (int dn = 0; dn < 4; dn++) {
            float2 v0; v0.x = oa[rg][dn][0]; v0.y = oa[rg][dn][1];
            float2 v1; v1.x = oa[rg][dn][2]; v1.y = oa[rg][dn][3];
            *(float2*)(opg + dn * 8 + 2 * t) = v0;
            *(float2*)(opg8 + dn * 8 + 2 * t) = v1;
        }
        if (t == 0) {
            size_t ssb = (((size_t)sp * B_ + b) * H_ + w) * L_ + lr;
            SSp[ssb + g] = ss[rg * 2 + 0];
            SSp[ssb + g + 8] = ss[rg * 2 + 1];
        }
    }
}

// ---------------- LayerNorm: 4 rows/block, 64 thr/row, float4 I/O ----------------
template <bool RESID, int NIN>
__global__ void __launch_bounds__(256) ln_kernel(
    const float* __restrict__ in0, const float* __restrict__ in1,
    const float* __restrict__ in2, const float* __restrict__ in3,
    const float* __restrict__ g, const float* __restrict__ bt,
    const float* __restrict__ resid, float* __restrict__ out) {
    const int tid = threadIdx.x;
    const int rloc = tid >> 6;          // 0..3 row within block
    const int l64 = tid & 63;           // 0..63 thread within row
    const size_t row = (size_t)blockIdx.x * 4 + rloc;
    const size_t e = row * D_ + l64 * 4;
    const int lane = tid & 31;

    float4 x4 = *(const float4*)(in0 + e);
    if (NIN > 1) {
        float4 a = *(const float4*)(in1 + e);
        x4.x += a.x; x4.y += a.y; x4.z += a.z; x4.w += a.w;
    }
    if (NIN > 2) {
        float4 a = *(const float4*)(in2 + e);
        x4.x += a.x; x4.y += a.y; x4.z += a.z; x4.w += a.w;
    }
    if (NIN > 3) {
        float4 a = *(const float4*)(in3 + e);
        x4.x += a.x; x4.y += a.y; x4.z += a.z; x4.w += a.w;
    }
    __shared__ float ws[8];

    float v = (x4.x + x4.y) + (x4.z + x4.w);
    #pragma unroll
    for (int off = 16; off > 0; off >>= 1) v += __shfl_xor_sync(0xffffffffu, v, off);
    if (lane == 0) ws[tid >> 5] = v;
    __syncthreads();
    const float mean = (ws[rloc * 2] + ws[rloc * 2 + 1]) * (1.0f / D_);
    __syncthreads();

    float4 d4;
    d4.x = x4.x - mean; d4.y = x4.y - mean; d4.z = x4.z - mean; d4.w = x4.w - mean;
    v = (d4.x * d4.x + d4.y * d4.y) + (d4.z * d4.z + d4.w * d4.w);
    #pragma unroll
    for (int off = 16; off > 0; off >>= 1) v += __shfl_xor_sync(0xffffffffu, v, off);
    if (lane == 0) ws[tid >> 5] = v;
    __syncthreads();
    const float var = (ws[rloc * 2] + ws[rloc * 2 + 1]) * (1.0f / D_);
    const float rs = rsqrtf(var + 1e-5f);

    float4 g4 = *(const float4*)(g + l64 * 4);
    float4 b4 = *(const float4*)(bt + l64 * 4);
    float4 y;
    y.x = d4.x * rs * g4.x + b4.x;
    y.y = d4.y * rs * g4.y + b4.y;
    y.z = d4.z * rs * g4.z + b4.z;
    y.w = d4.w * rs * g4.w + b4.w;
    if (RESID) {
        float4 r4 = *(const float4*)(resid + e);
        y.x += r4.x; y.y += r4.y; y.z += r4.z; y.w += r4.w;
    }
    *(float4*)(out + e) = y;
}

// ---------------- launch ----------------
extern "C" void kernel_launch(void* const* d_in, const int* in_sizes, int n_in,
                              void* d_out, int out_size) {
    const float* x   = (const float*)d_in[0];
    const float* src = (const float*)d_in[1];
    const float* af  = (const float*)d_in[2];
    const float* Wq  = (const float*)d_in[3];
    const float* Wk  = (const float*)d_in[4];
    const float* Wv  = (const float*)d_in[5];
    const float* Wm  = (const float*)d_in[6];
    const float* W1  = (const float*)d_in[7];
    const float* W2  = (const float*)d_in[8];
    const float* g1  = (const float*)d_in[9];
    const float* b1  = (const float*)d_in[10];
    const float* g2  = (const float*)d_in[11];
    const float* b2  = (const float*)d_in[12];
    float* out = (float*)d_out;

    float *Q, *K, *V, *OP, *SS, *O, *M, *HB, *T;
    cudaGetSymbolAddress((void**)&Q,  g_Q);
    cudaGetSymbolAddress((void**)&K,  g_K);
    cudaGetSymbolAddress((void**)&V,  g_V);
    cudaGetSymbolAddress((void**)&OP, g_OP);
    cudaGetSymbolAddress((void**)&SS, g_SS);
    cudaGetSymbolAddress((void**)&O,  g_O);
    cudaGetSymbolAddress((void**)&M,  g_M);
    cudaGetSymbolAddress((void**)&HB, g_HB);
    cudaGetSymbolAddress((void**)&T,  g_T);

    cudaFuncSetAttribute(attn6, cudaFuncAttributeMaxDynamicSharedMemorySize, ATTN_SMEM);

    const int ML = B_ * L_;  // 4096
    float* OP1 = OP + (size_t)B_ * L_ * D_;

    // projections (one launch, grid.z selects Q/K/V; K,V tf32-rounded)
    gemm_qkv<<<dim3(4, ML / 64, 3), 256>>>(x, src, Wq, Wk, Wv, Q, K, V);

    // attention (tf32 mma, 32 rows/block) -> raw partials OP + sums SS
    attn6<<<dim3(L_ / 32, SPLITS, B_), 256, ATTN_SMEM>>>(Q, K, V, af, OP, SS);

    // Wm with fused combine, split-K=2 (partials M,T) + LN1 (sums) -> O
    gemm_wm_combine<<<dim3(4, ML / 64, 2), 256>>>(OP, OP1, SS, Wm, M, T);
    ln_kernel<false, 2><<<ML / 4, 256>>>(M, T, nullptr, nullptr, g1, b1, nullptr, O);

    // MLP: h = relu([x, LN1] @ W1^T)
    gemm_w1<<<dim3(8, ML / 64), 256>>>(x, O, W1, HB);
    // W2 split-K=4 (partials M,T,Q,K — Q/K free after attention)
    gemm_w2_splitk<<<dim3(4, ML / 64, 4), 256>>>(HB, W2, M, T, Q, K);

    // LN2 (sums 4 partials) + residual -> out
    ln_kernel<true, 4><<<ML / 4, 256>>>(M, T, Q, K, g2, b2, x, out);
}

// round 17
// speedup vs baseline: 3.4222x; 1.0503x over previous
#include <cuda_runtime.h>
#include <math.h>

typedef unsigned long long ull;
typedef unsigned int u32;

#define B_  2
#define L_  2048
#define S_  2048
#define D_  256
#define H_  8
#define SPLITS 2
#define SHALF (S_ / SPLITS)      // 1024
#define NT (SHALF / 16)          // 64 s-tiles of 16

__device__ __forceinline__ float ex2f(float x) {
    float r;
    asm("ex2.approx.ftz.f32 %0, %1;" : "=f"(r) : "f"(x));
    return r;
}
__device__ __forceinline__ u32 tf32r(float x) {
    u32 r;
    asm("cvt.rna.tf32.f32 %0, %1;" : "=r"(r) : "f"(x));
    return r;
}

// mma.sync m16n8k8 tf32: D += A*B (C==D registers)
#define MMA_TF32(d, a, b) \
    asm volatile("mma.sync.aligned.m16n8k8.row.col.f32.tf32.tf32.f32 " \
        "{%0,%1,%2,%3},{%4,%5,%6,%7},{%8,%9},{%0,%1,%2,%3};" \
        : "+f"((d)[0]), "+f"((d)[1]), "+f"((d)[2]), "+f"((d)[3]) \
        : "r"((a)[0]), "r"((a)[1]), "r"((a)[2]), "r"((a)[3]), \
          "r"((b)[0]), "r"((b)[1]));

// ---------------- scratch ----------------
__device__ float g_Q[(size_t)B_ * L_ * D_];
__device__ float g_K[(size_t)B_ * S_ * D_];
__device__ float g_V[(size_t)B_ * S_ * D_];
__device__ float g_OP[(size_t)SPLITS * B_ * L_ * D_];
__device__ float g_SS[(size_t)SPLITS * B_ * H_ * L_];
__device__ float g_O[(size_t)B_ * L_ * D_];
__device__ float g_M[(size_t)B_ * L_ * D_];
__device__ float g_HB[(size_t)B_ * L_ * 2 * D_];
__device__ float g_T[(size_t)B_ * L_ * D_];

// ---------------- tf32 mma GEMM (R16-verbatim, proven) ----------------
template <bool RELU, int MODE, bool CVT>
__device__ __forceinline__ void mgemm_body(
    const float* __restrict__ X, const float* __restrict__ X2,
    const float* __restrict__ SSp,
    const float* __restrict__ W, float* __restrict__ Y,
    int N, int K, int ldx, int ldw, int bm, int bn, int kz) {
    __shared__ float Xs[64][36];
    __shared__ float Ws[64][36];
    const int tid = threadIdx.x;
    const int wid = tid >> 5, lane = tid & 31;
    const int wm = wid >> 1, wn = wid & 1;
    const int g = lane >> 2, t = lane & 3;
    const int NTk = K >> 5;

    float4 xr[2], wr[2];
    #define MLOAD(kc_) do { \
        _Pragma("unroll") \
        for (int i = 0; i < 2; i++) { \
            int idx = tid + 256 * i; \
            int r = idx >> 3; int c = ((idx & 7) * 4) + (kc_); \
            if (MODE == 1) { \
                xr[i] = (c < 256) ? *(const float4*)(X + (size_t)(bm + r) * 256 + c) \
                                  : *(const float4*)(X2 + (size_t)(bm + r) * 256 + (c - 256)); \
            } else if (MODE == 2) { \
                size_t row = bm + r; \
                int kabs = kz + c; \
                size_t e = row * 256 + kabs; \
                float4 a = *(const float4*)(X + e); \
                float4 c2 = *(const float4*)(X2 + e); \
                size_t bb = row >> 11; size_t l = row & 2047; \
                int h = kabs >> 5; \
                float s = SSp[(bb * H_ + h) * L_ + l] \
                        + SSp[(size_t)B_ * H_ * L_ + (bb * H_ + h) * L_ + l]; \
                float inv = 1.0f / s; \
                xr[i].x = (a.x + c2.x) * inv; xr[i].y = (a.y + c2.y) * inv; \
                xr[i].z = (a.z + c2.z) * inv; xr[i].w = (a.w + c2.w) * inv; \
            } else { \
                xr[i] = *(const float4*)(X + (size_t)(bm + r) * ldx + c); \
            } \
            wr[i] = *(const float4*)(W + (size_t)(bn + r) * ldw + c); \
        } \
    } while (0)

    MLOAD(0);

    float ca[4][4];
    #pragma unroll
    for (int ns = 0; ns < 4; ns++)
        #pragma unroll
        for (int i = 0; i < 4; i++) ca[ns][i] = 0.0f;

    for (int kt = 0; kt < NTk; kt++) {
        __syncthreads();
        #pragma unroll
        for (int i = 0; i < 2; i++) {
            int idx = tid + 256 * i;
            int r = idx >> 3; int c4 = (idx & 7) * 4;
            float4 xv = xr[i], wv = wr[i];
            xv.x = __uint_as_float(tf32r(xv.x)); xv.y = __uint_as_float(tf32r(xv.y));
            xv.z = __uint_as_float(tf32r(xv.z)); xv.w = __uint_as_float(tf32r(xv.w));
            wv.x = __uint_as_float(tf32r(wv.x)); wv.y = __uint_as_float(tf32r(wv.y));
            wv.z = __uint_as_float(tf32r(wv.z)); wv.w = __uint_as_float(tf32r(wv.w));
            *(float4*)&Xs[r][c4] = xv;
            *(float4*)&Ws[r][c4] = wv;
        }
        if (kt + 1 < NTk) MLOAD((kt + 1) * 32);
        __syncthreads();
        #pragma unroll
        for (int ks = 0; ks < 4; ks++) {
            u32 a[4];
            a[0] = __float_as_uint(Xs[wm * 16 + g][ks * 8 + t]);
            a[1] = __float_as_uint(Xs[wm * 16 + g + 8][ks * 8 + t]);
            a[2] = __float_as_uint(Xs[wm * 16 + g][ks * 8 + t + 4]);
            a[3] = __float_as_uint(Xs[wm * 16 + g + 8][ks * 8 + t + 4]);
            #pragma unroll
            for (int ns = 0; ns < 4; ns++) {
                u32 bf[2];
                bf[0] = __float_as_uint(Ws[wn * 32 + ns * 8 + g][ks * 8 + t]);
                bf[1] = __float_as_uint(Ws[wn * 32 + ns * 8 + g][ks * 8 + t + 4]);
                MMA_TF32(ca[ns], a, bf);
            }
        }
    }
    #undef MLOAD

    #pragma unroll
    for (int ns = 0; ns < 4; ns++) {
        float v0 = ca[ns][0], v1 = ca[ns][1], v2 = ca[ns][2], v3 = ca[ns][3];
        if (RELU) {
            v0 = fmaxf(v0, 0.0f); v1 = fmaxf(v1, 0.0f);
            v2 = fmaxf(v2, 0.0f); v3 = fmaxf(v3, 0.0f);
        }
        if (CVT) {
            v0 = __uint_as_float(tf32r(v0)); v1 = __uint_as_float(tf32r(v1));
            v2 = __uint_as_float(tf32r(v2)); v3 = __uint_as_float(tf32r(v3));
        }
        int col = bn + wn * 32 + ns * 8 + 2 * t;
        float2 p0; p0.x = v0; p0.y = v1;
        float2 p1; p1.x = v2; p1.y = v3;
        *(float2*)(Y + (size_t)(bm + wm * 16 + g) * N + col) = p0;
        *(float2*)(Y + (size_t)(bm + wm * 16 + g + 8) * N + col) = p1;
    }
}

__global__ void __launch_bounds__(256) gemm_qkv(
    const float* __restrict__ x, const float* __restrict__ src,
    const float* __restrict__ Wq, const float* __restrict__ Wk,
    const float* __restrict__ Wv,
    float* __restrict__ Q, float* __restrict__ K, float* __restrict__ V) {
    const int z = blockIdx.z;
    if (z == 0) {
        mgemm_body<false, 0, false>(x, nullptr, nullptr, Wq, Q, 256, 256, 256, 256,
                                    blockIdx.y * 64, blockIdx.x * 64, 0);
    } else {
        const float* W = (z == 1) ? Wk : Wv;
        float* Y = (z == 1) ? K : V;
        mgemm_body<false, 0, true>(src, nullptr, nullptr, W, Y, 256, 256, 256, 256,
                                   blockIdx.y * 64, blockIdx.x * 64, 0);
    }
}

__global__ void __launch_bounds__(256) gemm_wm_combine(
    const float* __restrict__ OP0, const float* __restrict__ OP1,
    const float* __restrict__ SSp, const float* __restrict__ Wm,
    float* __restrict__ Y0, float* __restrict__ Y1) {
    const int z = blockIdx.z;
    const int kz = z * 128;
    mgemm_body<false, 2, false>(OP0, OP1, SSp, Wm + kz, z ? Y1 : Y0,
                                256, 128, 256, 256, blockIdx.y * 64, blockIdx.x * 64, kz);
}

__global__ void __launch_bounds__(256) gemm_w2_splitk(
    const float* __restrict__ X, const float* __restrict__ W,
    float* __restrict__ Y0, float* __restrict__ Y1,
    float* __restrict__ Y2, float* __restrict__ Y3) {
    const int z = blockIdx.z;
    float* Y = (z == 0) ? Y0 : (z == 1) ? Y1 : (z == 2) ? Y2 : Y3;
    mgemm_body<false, 0, false>(X + z * 128, nullptr, nullptr, W + z * 128, Y,
                                256, 128, 512, 512, blockIdx.y * 64, blockIdx.x * 64, 0);
}

__global__ void __launch_bounds__(256) gemm_w1(
    const float* __restrict__ X, const float* __restrict__ X2,
    const float* __restrict__ W, float* __restrict__ Y) {
    mgemm_body<true, 1, false>(X, X2, nullptr, W, Y, 512, 512, 256, 512,
                               blockIdx.y * 64, blockIdx.x * 64, 0);
}

// ---------------- attn7: tf32 mma flash attention, 32 l-rows, shared V frags ----------------
// smem floats: K 2*4160=8320 | V 2*4224=8448 @8320 | Af 2*576=1152 @16768 |
//              P 8*640=5120 @17920  -> 23040 floats = 92160 B.
#define ATTN_SMEM 92160

#define ISSUE_KV(t_, buf_) do { \
    const float* ksrc_ = Kb + (size_t)(sbase + (t_) * 16) * D_; \
    const float* vsrc_ = Vb + (size_t)(sbase + (t_) * 16) * D_; \
    u32 kd_ = kbase + (u32)(buf_) * 16640; \
    u32 vd_ = vbase + (u32)(buf_) * 16896; \
    _Pragma("unroll") \
    for (int i_ = 0; i_ < 4; i_++) { \
        int idx_ = tid + 256 * i_; int s_ = idx_ >> 6; int c_ = (idx_ & 63) * 4; \
        asm volatile("cp.async.cg.shared.global [%0], [%1], 16;" :: \
            "r"(kd_ + (u32)(s_ * 1040 + c_ * 4)), "l"(ksrc_ + s_ * 256 + c_)); \
        asm volatile("cp.async.cg.shared.global [%0], [%1], 16;" :: \
            "r"(vd_ + (u32)(s_ * 1056 + c_ * 4)), "l"(vsrc_ + s_ * 256 + c_)); \
    } \
    asm volatile("cp.async.commit_group;"); \
} while (0)

#define LOAD_AF(t_) do { \
    afr0 = afb[(size_t)(tid >> 4) * S_ + (t_) * 16 + (tid & 15)]; \
    afr1 = afb[(size_t)((tid >> 4) + 16) * S_ + (t_) * 16 + (tid & 15)]; \
} while (0)

#define STORE_AF(buf_) do { \
    Afs[(buf_) * 576 + (tid >> 4) * 18 + (tid & 15)] = afr0; \
    Afs[(buf_) * 576 + ((tid >> 4) + 16) * 18 + (tid & 15)] = afr1; \
} while (0)

__global__ void __launch_bounds__(256, 2) attn7(
    const float* __restrict__ Qg, const float* __restrict__ Kg,
    const float* __restrict__ Vg, const float* __restrict__ af,
    float* __restrict__ Op, float* __restrict__ SSp) {
    extern __shared__ float sm[];
    float* Ksm = sm;
    float* Vsm = sm + 8320;
    float* Afs = sm + 16768;

    const int b = blockIdx.z, sp = blockIdx.y;
    const int l0 = blockIdx.x * 32;
    const int tid = threadIdx.x;
    const int w = tid >> 5, lane = tid & 31;
    const int g = lane >> 2, t = lane & 3;
    float* Pw = sm + 17920 + w * 640;   // two 16x20 tiles per warp

    const int sbase = sp * SHALF;
    const float* Kb  = Kg + (size_t)b * S_ * D_;
    const float* Vb  = Vg + (size_t)b * S_ * D_;
    const float* afb = af + ((size_t)b * L_ + l0) * S_ + sbase;
    const u32 smb = (u32)__cvta_generic_to_shared(sm);
    const u32 kbase = smb;
    const u32 vbase = smb + 33280;

    u32 qf[2][4][4];
    {
        const float QS = 0.25503486f;  // log2(e)/sqrt(32)
        const float* qb = Qg + (size_t)b * L_ * D_;
        #pragma unroll
        for (int rg = 0; rg < 2; rg++) {
            int lr = l0 + rg * 16;
            #pragma unroll
            for (int kt = 0; kt < 4; kt++) {
                int d0 = w * 32 + kt * 8 + t;
                qf[rg][kt][0] = tf32r(qb[(size_t)(lr + g) * 256 + d0] * QS);
                qf[rg][kt][1] = tf32r(qb[(size_t)(lr + g + 8) * 256 + d0] * QS);
                qf[rg][kt][2] = tf32r(qb[(size_t)(lr + g) * 256 + d0 + 4] * QS);
                qf[rg][kt][3] = tf32r(qb[(size_t)(lr + g + 8) * 256 + d0 + 4] * QS);
            }
        }
    }

    float oa[2][4][4];
    #pragma unroll
    for (int rg = 0; rg < 2; rg++)
        #pragma unroll
        for (int dn = 0; dn < 4; dn++)
            #pragma unroll
            for (int c = 0; c < 4; c++) oa[rg][dn][c] = 0.0f;
    float ss[4];
    #pragma unroll
    for (int i = 0; i < 4; i++) ss[i] = 0.0f;
    float afr0, afr1;

    ISSUE_KV(0, 0);
    LOAD_AF(0);
    ISSUE_KV(1, 1);
    STORE_AF(0);
    LOAD_AF(1);

    for (int st = 0; st < NT; st++) {
        const int buf = st & 1;
        if (st + 1 < NT) asm volatile("cp.async.wait_group 1;");
        else             asm volatile("cp.async.wait_group 0;");
        __syncthreads();
        if (st + 1 < NT) STORE_AF(buf ^ 1);
        if (st + 2 < NT) LOAD_AF(st + 2);

        const float* ks  = Ksm + buf * 4160 + w * 32;
        const float* vs  = Vsm + buf * 4224;
        const float* afl = Afs + buf * 576;

        // K fragments, shared across row-groups
        u32 bk[4][2][2];
        #pragma unroll
        for (int kt = 0; kt < 4; kt++) {
            bk[kt][0][0] = __float_as_uint(ks[(size_t)g * 260 + kt * 8 + t]);
            bk[kt][0][1] = __float_as_uint(ks[(size_t)g * 260 + kt * 8 + t + 4]);
            bk[kt][1][0] = __float_as_uint(ks[(size_t)(g + 8) * 260 + kt * 8 + t]);
            bk[kt][1][1] = __float_as_uint(ks[(size_t)(g + 8) * 260 + kt * 8 + t + 4]);
        }

        // ---- QK + softmax for both row-groups, P tiles to smem ----
        #pragma unroll
        for (int rg = 0; rg < 2; rg++) {
            float sc[2][4];
            #pragma unroll
            for (int nt = 0; nt < 2; nt++)
                #pragma unroll
                for (int c = 0; c < 4; c++) sc[nt][c] = 0.0f;
            #pragma unroll
            for (int kt = 0; kt < 4; kt++) {
                MMA_TF32(sc[0], qf[rg][kt], bk[kt][0]);
                MMA_TF32(sc[1], qf[rg][kt], bk[kt][1]);
            }

            const float* afr = afl + (rg * 16) * 18;
            u32 pv[2][4];
            float rs0 = 0.0f, rs1 = 0.0f;
            #pragma unroll
            for (int nt = 0; nt < 2; nt++) {
                float2 afA = *(const float2*)&afr[g * 18 + nt * 8 + 2 * t];
                float2 afB = *(const float2*)&afr[(g + 8) * 18 + nt * 8 + 2 * t];
                float p0 = ex2f(sc[nt][0] * afA.x);
                float p1 = ex2f(sc[nt][1] * afA.y);
                float p2 = ex2f(sc[nt][2] * afB.x);
                float p3 = ex2f(sc[nt][3] * afB.y);
                pv[nt][0] = tf32r(p0); pv[nt][1] = tf32r(p1);
                pv[nt][2] = tf32r(p2); pv[nt][3] = tf32r(p3);
                rs0 += __uint_as_float(pv[nt][0]) + __uint_as_float(pv[nt][1]);
                rs1 += __uint_as_float(pv[nt][2]) + __uint_as_float(pv[nt][3]);
            }
            rs0 += __shfl_xor_sync(0xffffffffu, rs0, 1);
            rs0 += __shfl_xor_sync(0xffffffffu, rs0, 2);
            rs1 += __shfl_xor_sync(0xffffffffu, rs1, 1);
            rs1 += __shfl_xor_sync(0xffffffffu, rs1, 2);
            ss[rg * 2 + 0] += rs0;
            ss[rg * 2 + 1] += rs1;

            float* Prg = Pw + rg * 320;
            #pragma unroll
            for (int nt = 0; nt < 2; nt++) {
                float2 v0; v0.x = __uint_as_float(pv[nt][0]); v0.y = __uint_as_float(pv[nt][1]);
                float2 v1; v1.x = __uint_as_float(pv[nt][2]); v1.y = __uint_as_float(pv[nt][3]);
                *(float2*)&Prg[g * 20 + nt * 8 + 2 * t] = v0;
                *(float2*)&Prg[(g + 8) * 20 + nt * 8 + 2 * t] = v1;
            }
        }
        __syncwarp();

        // ---- reload both P tiles as A fragments ----
        u32 pa[2][2][4];
        #pragma unroll
        for (int rg = 0; rg < 2; rg++) {
            const float* Prg = Pw + rg * 320;
            #pragma unroll
            for (int ksx = 0; ksx < 2; ksx++) {
                pa[rg][ksx][0] = __float_as_uint(Prg[g * 20 + ksx * 8 + t]);
                pa[rg][ksx][1] = __float_as_uint(Prg[(g + 8) * 20 + ksx * 8 + t]);
                pa[rg][ksx][2] = __float_as_uint(Prg[g * 20 + ksx * 8 + t + 4]);
                pa[rg][ksx][3] = __float_as_uint(Prg[(g + 8) * 20 + ksx * 8 + t + 4]);
            }
        }

        // ---- AV: V fragments loaded ONCE, used by both row-groups ----
        #pragma unroll
        for (int dn = 0; dn < 4; dn++) {
            u32 bv0[2], bv1[2];
            int dcol = w * 32 + dn * 8 + g;
            bv0[0] = __float_as_uint(vs[(size_t)t * 264 + dcol]);
            bv0[1] = __float_as_uint(vs[(size_t)(t + 4) * 264 + dcol]);
            bv1[0] = __float_as_uint(vs[(size_t)(8 + t) * 264 + dcol]);
            bv1[1] = __float_as_uint(vs[(size_t)(8 + t + 4) * 264 + dcol]);
            MMA_TF32(oa[0][dn], pa[0][0], bv0);
            MMA_TF32(oa[0][dn], pa[0][1], bv1);
            MMA_TF32(oa[1][dn], pa[1][0], bv0);
            MMA_TF32(oa[1][dn], pa[1][1], bv1);
        }
        __syncthreads();
        if (st + 2 < NT) ISSUE_KV(st + 2, buf);
    }

    #pragma unroll
    for (int rg = 0; rg < 2; rg++) {
        int lr = l0 + rg * 16;
        float* opg  = Op + (((size_t)sp * B_ + b) * L_ + lr + g) * 256 + w * 32;
        float* opg8 = opg + 8 * 256;
        #pragma unroll
        for (int dn = 0; dn < 4; dn++) {
            float2 v0; v0.x = oa[rg][dn][0]; v0.y = oa[rg][dn][1];
            float2 v1; v1.x = oa[rg][dn][2]; v1.y = oa[rg][dn][3];
            *(float2*)(opg + dn * 8 + 2 * t) = v0;
            *(float2*)(opg8 + dn * 8 + 2 * t) = v1;
        }
        if (t == 0) {
            size_t ssb = (((size_t)sp * B_ + b) * H_ + w) * L_ + lr;
            SSp[ssb + g] = ss[rg * 2 + 0];
            SSp[ssb + g + 8] = ss[rg * 2 + 1];
        }
    }
}

// ---------------- LayerNorm: warp-per-row, 8 rows/block, no block syncs ----------------
template <bool RESID, int NIN>
__global__ void __launch_bounds__(256) ln_kernel(
    const float* __restrict__ in0, const float* __restrict__ in1,
    const float* __restrict__ in2, const float* __restrict__ in3,
    const float* __restrict__ g, const float* __restrict__ bt,
    const float* __restrict__ resid, float* __restrict__ out) {
    const int tid = threadIdx.x;
    const int wrp = tid >> 5, lane = tid & 31;
    const size_t row = (size_t)blockIdx.x * 8 + wrp;
    const size_t e0 = row * D_ + lane * 4;
    const size_t e1 = e0 + 128;

    float4 a4 = *(const float4*)(in0 + e0);
    float4 b4 = *(const float4*)(in0 + e1);
    if (NIN > 1) {
        float4 u = *(const float4*)(in1 + e0), v = *(const float4*)(in1 + e1);
        a4.x += u.x; a4.y += u.y; a4.z += u.z; a4.w += u.w;
        b4.x += v.x; b4.y += v.y; b4.z += v.z; b4.w += v.w;
    }
    if (NIN > 2) {
        float4 u = *(const float4*)(in2 + e0), v = *(const float4*)(in2 + e1);
        a4.x += u.x; a4.y += u.y; a4.z += u.z; a4.w += u.w;
        b4.x += v.x; b4.y += v.y; b4.z += v.z; b4.w += v.w;
    }
    if (NIN > 3) {
        float4 u = *(const float4*)(in3 + e0), v = *(const float4*)(in3 + e1);
        a4.x += u.x; a4.y += u.y; a4.z += u.z; a4.w += u.w;
        b4.x += v.x; b4.y += v.y; b4.z += v.z; b4.w += v.w;
    }

    float v = ((a4.x + a4.y) + (a4.z + a4.w)) + ((b4.x + b4.y) + (b4.z + b4.w));
    #pragma unroll
    for (int off = 16; off > 0; off >>= 1) v += __shfl_xor_sync(0xffffffffu, v, off);
    const float mean = v * (1.0f / D_);

    float4 da, db;
    da.x = a4.x - mean; da.y = a4.y - mean; da.z = a4.z - mean; da.w = a4.w - mean;
    db.x = b4.x - mean; db.y = b4.y - mean; db.z = b4.z - mean; db.w = b4.w - mean;
    v = ((da.x * da.x + da.y * da.y) + (da.z * da.z + da.w * da.w))
      + ((db.x * db.x + db.y * db.y) + (db.z * db.z + db.w * db.w));
    #pragma unroll
    for (int off = 16; off > 0; off >>= 1) v += __shfl_xor_sync(0xffffffffu, v, off);
    const float rs = rsqrtf(v * (1.0f / D_) + 1e-5f);

    float4 g0 = *(const float4*)(g + lane * 4);
    float4 g1 = *(const float4*)(g + lane * 4 + 128);
    float4 t0 = *(const float4*)(bt + lane * 4);
    float4 t1 = *(const float4*)(bt + lane * 4 + 128);
    float4 y0, y1;
    y0.x = da.x * rs * g0.x + t0.x; y0.y = da.y * rs * g0.y + t0.y;
    y0.z = da.z * rs * g0.z + t0.z; y0.w = da.w * rs * g0.w + t0.w;
    y1.x = db.x * rs * g1.x + t1.x; y1.y = db.y * rs * g1.y + t1.y;
    y1.z = db.z * rs * g1.z + t1.z; y1.w = db.w * rs * g1.w + t1.w;
    if (RESID) {
        float4 r0 = *(const float4*)(resid + e0), r1 = *(const float4*)(resid + e1);
        y0.x += r0.x; y0.y += r0.y; y0.z += r0.z; y0.w += r0.w;
        y1.x += r1.x; y1.y += r1.y; y1.z += r1.z; y1.w += r1.w;
    }
    *(float4*)(out + e0) = y0;
    *(float4*)(out + e1) = y1;
}

// ---------------- launch ----------------
extern "C" void kernel_launch(void* const* d_in, const int* in_sizes, int n_in,
                              void* d_out, int out_size) {
    const float* x   = (const float*)d_in[0];
    const float* src = (const float*)d_in[1];
    const float* af  = (const float*)d_in[2];
    const float* Wq  = (const float*)d_in[3];
    const float* Wk  = (const float*)d_in[4];
    const float* Wv  = (const float*)d_in[5];
    const float* Wm  = (const float*)d_in[6];
    const float* W1  = (const float*)d_in[7];
    const float* W2  = (const float*)d_in[8];
    const float* g1  = (const float*)d_in[9];
    const float* b1  = (const float*)d_in[10];
    const float* g2  = (const float*)d_in[11];
    const float* b2  = (const float*)d_in[12];
    float* out = (float*)d_out;

    float *Q, *K, *V, *OP, *SS, *O, *M, *HB, *T;
    cudaGetSymbolAddress((void**)&Q,  g_Q);
    cudaGetSymbolAddress((void**)&K,  g_K);
    cudaGetSymbolAddress((void**)&V,  g_V);
    cudaGetSymbolAddress((void**)&OP, g_OP);
    cudaGetSymbolAddress((void**)&SS, g_SS);
    cudaGetSymbolAddress((void**)&O,  g_O);
    cudaGetSymbolAddress((void**)&M,  g_M);
    cudaGetSymbolAddress((void**)&HB, g_HB);
    cudaGetSymbolAddress((void**)&T,  g_T);

    cudaFuncSetAttribute(attn7, cudaFuncAttributeMaxDynamicSharedMemorySize, ATTN_SMEM);

    const int ML = B_ * L_;  // 4096
    float* OP1 = OP + (size_t)B_ * L_ * D_;

    // projections (one launch, grid.z selects Q/K/V; K,V tf32-rounded)
    gemm_qkv<<<dim3(4, ML / 64, 3), 256>>>(x, src, Wq, Wk, Wv, Q, K, V);

    // attention (tf32 mma, 32 rows/block, shared V frags) -> partials + sums
    attn7<<<dim3(L_ / 32, SPLITS, B_), 256, ATTN_SMEM>>>(Q, K, V, af, OP, SS);

    // Wm with fused combine, split-K=2 (partials M,T) + LN1 (sums) -> O
    gemm_wm_combine<<<dim3(4, ML / 64, 2), 256>>>(OP, OP1, SS, Wm, M, T);
    ln_kernel<false, 2><<<ML / 8, 256>>>(M, T, nullptr, nullptr, g1, b1, nullptr, O);

    // MLP: h = relu([x, LN1] @ W1^T)
    gemm_w1<<<dim3(8, ML / 64), 256>>>(x, O, W1, HB);
    // W2 split-K=4 (partials M,T,Q,K — Q/K free after attention)
    gemm_w2_splitk<<<dim3(4, ML / 64, 4), 256>>>(HB, W2, M, T, Q, K);

    // LN2 (sums 4 partials) + residual -> out
    ln_kernel<true, 4><<<ML / 8, 256>>>(M, T, Q, K, g2, b2, x, out);
}